// round 12
// baseline (speedup 1.0000x reference)
#include <cuda_runtime.h>
#include <cuda_bf16.h>
#include <cuda_fp16.h>
#include <cstdint>
#include <cstddef>

// Problem constants (fixed by the reference)
#define NN 50000
#define EE 600000
#define GG 512
#define FF 128
#define DD 128
#define EDIM 384
#define GFS_LD 768
// stacked layout: branch-f rows [0,50000), branch-s rows [50048,100048)
#define SPLIT 50048               // = 391*128, tile-aligned
#define MST   100048              // last valid row + 1
#define ROWS_T 100096             // padded to 782*128

// ---------------------------------------------------------------------------
// Scratch (device globals -- no allocation allowed in kernel_launch)
// ---------------------------------------------------------------------------
__device__ __align__(16) float g_hst [ROWS_T * DD];       // stacked raw h
__device__ __align__(16) float g_nfs [ROWS_T * EDIM];     // stacked node emb (PRE-relu)
__device__ __align__(16) __half g_hidh[ROWS_T * EDIM];
__device__ __align__(16) __half g_hidl[ROWS_T * EDIM];
__device__ float g_lms [ROWS_T];                          // stacked logmap scales
__device__ int   g_degi[NN];
__device__ float g_dinv[NN];
__device__ float g_dinv2[NN];
__device__ int   g_off [NN];
__device__ int   g_cur [NN];
__device__ int   g_csrc[EE];
__device__ float g_cw  [EE];
__device__ __align__(16) float g_gfs [GG * GFS_LD];       // [gf | gs]
__device__ __align__(16) float g_ghid[3 * GG * EDIM];
// transposed + split weights (bf16 hi/lo), [N,K] row-major (GCN)
__device__ __align__(16) __nv_bfloat16 g_wth[393216];
__device__ __align__(16) __nv_bfloat16 g_wtl[393216];
// fp16 head weights, transposed [N,K]: P1 split hi/lo, P2 hi only
__device__ __align__(16) __half g_p1h[147456];
__device__ __align__(16) __half g_p1l[147456];
__device__ __align__(16) __half g_p2h[147456];

// ---------------------------------------------------------------------------
// Static-init stream/event resources
// ---------------------------------------------------------------------------
struct HxStreams {
    cudaStream_t s1 = nullptr;
    cudaEvent_t eFork = nullptr, e2 = nullptr, ePool = nullptr, eEnd = nullptr;
    bool ok = false;
    HxStreams() {
        ok = (cudaStreamCreateWithFlags(&s1, cudaStreamNonBlocking) == cudaSuccess)
          && (cudaEventCreateWithFlags(&eFork, cudaEventDisableTiming) == cudaSuccess)
          && (cudaEventCreateWithFlags(&e2,    cudaEventDisableTiming) == cudaSuccess)
          && (cudaEventCreateWithFlags(&ePool, cudaEventDisableTiming) == cudaSuccess)
          && (cudaEventCreateWithFlags(&eEnd,  cudaEventDisableTiming) == cudaSuccess);
    }
};
static HxStreams g_hx;

// ---------------------------------------------------------------------------
// Helpers
// ---------------------------------------------------------------------------
__device__ __forceinline__ void ldmx4(uint32_t* r, uint32_t addr) {
    asm volatile("ldmatrix.sync.aligned.m8n8.x4.shared.b16 {%0,%1,%2,%3}, [%4];"
                 : "=r"(r[0]), "=r"(r[1]), "=r"(r[2]), "=r"(r[3]) : "r"(addr));
}
__device__ __forceinline__ void ldmx2(uint32_t* r, uint32_t addr) {
    asm volatile("ldmatrix.sync.aligned.m8n8.x2.shared.b16 {%0,%1}, [%2];"
                 : "=r"(r[0]), "=r"(r[1]) : "r"(addr));
}
__device__ __forceinline__ void mma16816(float* d, const uint32_t* a, const uint32_t* b) {
    asm volatile("mma.sync.aligned.m16n8k16.row.col.f32.bf16.bf16.f32 "
                 "{%0,%1,%2,%3}, {%4,%5,%6,%7}, {%8,%9}, {%0,%1,%2,%3};"
                 : "+f"(d[0]), "+f"(d[1]), "+f"(d[2]), "+f"(d[3])
                 : "r"(a[0]), "r"(a[1]), "r"(a[2]), "r"(a[3]), "r"(b[0]), "r"(b[1]));
}
__device__ __forceinline__ void mmaf16(float* d, const uint32_t* a, const uint32_t* b) {
    asm volatile("mma.sync.aligned.m16n8k16.row.col.f32.f16.f16.f32 "
                 "{%0,%1,%2,%3}, {%4,%5,%6,%7}, {%8,%9}, {%0,%1,%2,%3};"
                 : "+f"(d[0]), "+f"(d[1]), "+f"(d[2]), "+f"(d[3])
                 : "r"(a[0]), "r"(a[1]), "r"(a[2]), "r"(a[3]), "r"(b[0]), "r"(b[1]));
}
__device__ __forceinline__ uint32_t smem_u32(const void* p) {
    uint32_t a;
    asm("{ .reg .u64 t; cvta.to.shared.u64 t, %1; cvt.u32.u64 %0, t; }" : "=r"(a) : "l"(p));
    return a;
}
__device__ __forceinline__ void cpa16(uint32_t saddr, const void* gaddr) {
    asm volatile("cp.async.cg.shared.global [%0], [%1], 16;" :: "r"(saddr), "l"(gaddr));
}

// ---------------------------------------------------------------------------
// prep kernel: weight transpose+split (blocks 0..1535), logmap scales after.
// lms2 pointer = lms + SPLIT (stacked).
// ---------------------------------------------------------------------------
__global__ void prep_kernel(const float* __restrict__ W0, const float* __restrict__ W1,
                            const float* __restrict__ W2, const float* __restrict__ W3,
                            const float* __restrict__ W4, const float* __restrict__ W5,
                            const float* __restrict__ P1, const float* __restrict__ P2,
                            __nv_bfloat16* __restrict__ Th, __nv_bfloat16* __restrict__ Tl,
                            __half* __restrict__ p1h, __half* __restrict__ p1l,
                            __half* __restrict__ p2h,
                            const float* __restrict__ x, const float* __restrict__ xs,
                            float* __restrict__ lms, float* __restrict__ lms2)
{
    int b = blockIdx.x;
    if (b < 1536) {
        int idx = b * 256 + threadIdx.x;
        const float* W; int K, N, li, base; int which = 0;
        if (idx < 98304) {
            int m = idx >> 14; li = idx & 16383;
            const float* ws[6] = {W0, W1, W2, W3, W4, W5};
            W = ws[m]; K = 128; N = 128; base = m << 14;
        } else if (idx < 245760) { W = P1; li = idx - 98304; K = 384; N = 384; base = 98304; which = 1; }
        else                     { W = P2; li = idx - 245760; K = 384; N = 384; base = 245760; which = 2; }
        int k = li / N, n = li % N;
        float v = W[li];
        __nv_bfloat16 h = __float2bfloat16_rn(v);
        Th[base + n * K + k] = h;
        Tl[base + n * K + k] = __float2bfloat16_rn(v - __bfloat162float(h));
        if (which == 1) {
            __half fh = __float2half_rn(v);
            p1h[n * 384 + k] = fh;
            p1l[n * 384 + k] = __float2half_rn(v - __half2float(fh));
        } else if (which == 2) {
            p2h[n * 384 + k] = __float2half_rn(v);
        }
    } else {
        int rb = b - 1536;
        const float* xin = x; float* sout = lms;
        if (rb >= 6250) { rb -= 6250; xin = xs; sout = lms2; }
        int w = rb * 8 + (threadIdx.x >> 5);
        if (w >= NN) return;
        int lane = threadIdx.x & 31;
        const float4 v = *reinterpret_cast<const float4*>(xin + (size_t)w * FF + lane * 4);
        float ss = v.x * v.x + v.y * v.y + v.z * v.z + v.w * v.w;
#pragma unroll
        for (int o = 16; o; o >>= 1) ss += __shfl_xor_sync(0xffffffffu, ss, o);
        if (lane == 0) {
            float nrm = sqrtf(ss);
            float n1  = fmaxf(nrm, 1e-15f);
            float arg = fminf(n1, 1.0f - 1e-15f);
            sout[w] = atanhf(arg) / n1;
        }
    }
}

// ---------------------------------------------------------------------------
// Stacked bf16 split-3 GEMM (GCN layers). Two A bases + two weight sets.
// Row mapping: gr < 50000 -> A1; 50048 <= gr < 100048 -> A2 (gr-SPLIT); else 0.
// Tile bm < SPLIT -> B1, else B2 (tile-aligned split).
// flags: 8=RELU on A, 16=scale A rows by ascale[] (stacked).
// ---------------------------------------------------------------------------
#define ROWB 80
#define ASZ (128 * ROWB)
#define GEMM_SMEM (6 * ASZ)

__global__ void __launch_bounds__(256, 2)
mma_gemm2_kernel(const float* __restrict__ A1, const float* __restrict__ A2, int lda,
                 const __nv_bfloat16* __restrict__ B1h, const __nv_bfloat16* __restrict__ B1l,
                 const __nv_bfloat16* __restrict__ B2h, const __nv_bfloat16* __restrict__ B2l,
                 int ldb,
                 float* __restrict__ C, int ldc,
                 int K, int flags,
                 const float* __restrict__ ascale)
{
    extern __shared__ __align__(16) char sm[];
    const int tid  = threadIdx.x;
    const int wid  = tid >> 5;
    const int lane = tid & 31;
    const int wm = wid & 1;
    const int wn = wid >> 1;
    const int bm = blockIdx.x * 128;
    const int bn = blockIdx.y * 128;
    const uint32_t sbase = smem_u32(sm);

    const __nv_bfloat16* Bh = (bm < SPLIT) ? B1h : B2h;
    const __nv_bfloat16* Bl = (bm < SPLIT) ? B1l : B2l;

    int arow[4], akc[4];
    const float* Abase[4];
#pragma unroll
    for (int it = 0; it < 4; ++it) {
        int idx = tid + it * 256;
        arow[it] = idx >> 3;
        akc[it]  = (idx & 7) << 2;
        int gr = bm + arow[it];
        Abase[it] = nullptr;
        if (gr < NN)                       Abase[it] = A1 + (size_t)gr * lda;
        else if (gr >= SPLIT && gr < MST)  Abase[it] = A2 + (size_t)(gr - SPLIT) * lda;
    }
    int brow[2], bc16[2];
#pragma unroll
    for (int it = 0; it < 2; ++it) {
        int idx = tid + it * 256;
        brow[it] = idx >> 2;
        bc16[it] = (idx & 3) << 4;
    }

    float acc[4][4][4];
#pragma unroll
    for (int i = 0; i < 4; i++)
#pragma unroll
        for (int j = 0; j < 4; j++)
#pragma unroll
            for (int l = 0; l < 4; l++) acc[i][j][l] = 0.0f;

    const int nch = K >> 5;
    float4 fr[4];
    float  asc[4];

#pragma unroll
    for (int it = 0; it < 4; ++it) {
        fr[it] = make_float4(0.f, 0.f, 0.f, 0.f);
        asc[it] = 1.0f;
        if (Abase[it]) {
            fr[it] = *reinterpret_cast<const float4*>(Abase[it] + akc[it]);
            if (flags & 16) asc[it] = ascale[bm + arow[it]];
        }
    }
#pragma unroll
    for (int it = 0; it < 2; ++it) {
        uint32_t so = sbase + 2 * ASZ + brow[it] * ROWB + bc16[it];
        size_t gb = ((size_t)(bn + brow[it]) * ldb) * 2 + bc16[it];
        cpa16(so,       (const char*)Bh + gb);
        cpa16(so + ASZ, (const char*)Bl + gb);
    }
    asm volatile("cp.async.commit_group;" ::: "memory");

    for (int ch = 0; ch < nch; ++ch) {
#pragma unroll
        for (int it = 0; it < 4; ++it) {
            float4 v = fr[it];
            float s = asc[it];
            v.x *= s; v.y *= s; v.z *= s; v.w *= s;
            if (flags & 8) {
                v.x = fmaxf(v.x, 0.f); v.y = fmaxf(v.y, 0.f);
                v.z = fmaxf(v.z, 0.f); v.w = fmaxf(v.w, 0.f);
            }
            __nv_bfloat162 h01 = __floats2bfloat162_rn(v.x, v.y);
            __nv_bfloat162 h23 = __floats2bfloat162_rn(v.z, v.w);
            float2 f01 = __bfloat1622float2(h01);
            float2 f23 = __bfloat1622float2(h23);
            __nv_bfloat162 l01 = __floats2bfloat162_rn(v.x - f01.x, v.y - f01.y);
            __nv_bfloat162 l23 = __floats2bfloat162_rn(v.z - f23.x, v.w - f23.y);
            int off = arow[it] * ROWB + akc[it] * 2;
            uint2 uh, ul;
            uh.x = *reinterpret_cast<uint32_t*>(&h01);
            uh.y = *reinterpret_cast<uint32_t*>(&h23);
            ul.x = *reinterpret_cast<uint32_t*>(&l01);
            ul.y = *reinterpret_cast<uint32_t*>(&l23);
            *reinterpret_cast<uint2*>(sm + off)       = uh;
            *reinterpret_cast<uint2*>(sm + ASZ + off) = ul;
        }
        asm volatile("cp.async.wait_group 0;" ::: "memory");
        __syncthreads();

        if (ch + 1 < nch) {
            int k0 = (ch + 1) << 5;
#pragma unroll
            for (int it = 0; it < 4; ++it) {
                fr[it] = make_float4(0.f, 0.f, 0.f, 0.f);
                if (Abase[it])
                    fr[it] = *reinterpret_cast<const float4*>(Abase[it] + k0 + akc[it]);
            }
            uint32_t bufo = 2 * ASZ + ((ch + 1) & 1) * (2 * ASZ);
#pragma unroll
            for (int it = 0; it < 2; ++it) {
                uint32_t so = sbase + bufo + brow[it] * ROWB + bc16[it];
                size_t gb = ((size_t)(bn + brow[it]) * ldb + k0) * 2 + bc16[it];
                cpa16(so,       (const char*)Bh + gb);
                cpa16(so + ASZ, (const char*)Bl + gb);
            }
            asm volatile("cp.async.commit_group;" ::: "memory");
        }

        const uint32_t sB = sbase + 2 * ASZ + (ch & 1) * (2 * ASZ);
#pragma unroll
        for (int ks = 0; ks < 2; ++ks) {
            uint32_t bfh[4][2], bfl[4][2];
#pragma unroll
            for (int nt = 0; nt < 4; ++nt) {
                uint32_t off = (uint32_t)((wn * 32 + nt * 8 + (lane & 7)) * ROWB
                                          + (ks * 16 + ((lane >> 3) & 1) * 8) * 2);
                ldmx2(bfh[nt], sB + off);
                ldmx2(bfl[nt], sB + ASZ + off);
            }
#pragma unroll
            for (int mt = 0; mt < 4; ++mt) {
                uint32_t off = (uint32_t)((wm * 64 + mt * 16 + (lane & 15)) * ROWB
                                          + (ks * 16 + ((lane >> 4) & 1) * 8) * 2);
                uint32_t ah[4], al[4];
                ldmx4(ah, sbase + off);
                ldmx4(al, sbase + ASZ + off);
#pragma unroll
                for (int nt = 0; nt < 4; ++nt) {
                    mma16816(acc[mt][nt], ah, bfh[nt]);
                    mma16816(acc[mt][nt], al, bfh[nt]);
                    mma16816(acc[mt][nt], ah, bfl[nt]);
                }
            }
        }
        __syncthreads();
    }

    const int groupID = lane >> 2;
    const int tid4 = lane & 3;
#pragma unroll
    for (int mt = 0; mt < 4; ++mt) {
#pragma unroll
        for (int half = 0; half < 2; ++half) {
            int gr = bm + wm * 64 + mt * 16 + groupID + half * 8;
#pragma unroll
            for (int nt = 0; nt < 4; ++nt) {
                int gc = bn + wn * 32 + nt * 8 + tid4 * 2;
                float2 r = make_float2(acc[mt][nt][half * 2], acc[mt][nt][half * 2 + 1]);
                *reinterpret_cast<float2*>(C + (size_t)gr * ldc + gc) = r;
            }
        }
    }
}

// ---------------------------------------------------------------------------
// fp16 2-MMA head GEMM, stacked.
// MODE 0: A fp32 stacked (relu) -> fp16; B split: C = A·Bh + A·Bl;
//         relu + store fp16-split (stacked Cbh/Cbl).
// MODE 1: A fp16-split stacked; B single: C = Ah·Bh + Al·Bh;
//         fp32 store to Cf (rows < 50000) / Cs (rows >= SPLIT).
// ---------------------------------------------------------------------------
template<int MODE>
__global__ void __launch_bounds__(256, 2)
hgemm_kernel(const float* __restrict__ A,
             const __half* __restrict__ Ah, const __half* __restrict__ Al,
             int lda,
             const __half* __restrict__ Bh, const __half* __restrict__ Bl,
             int ldb,
             float* __restrict__ Cf, float* __restrict__ Cs,
             __half* __restrict__ Cbh, __half* __restrict__ Cbl,
             int ldc, int K)
{
    extern __shared__ __align__(16) char sm[];
    const int tid  = threadIdx.x;
    const int wid  = tid >> 5;
    const int lane = tid & 31;
    const int wm = wid & 1;
    const int wn = wid >> 1;
    const int bm = blockIdx.x * 128;
    const int bn = blockIdx.y * 128;
    const uint32_t sbase = smem_u32(sm);

    int arow[4], akc[4];
#pragma unroll
    for (int it = 0; it < 4; ++it) {
        int idx = tid + it * 256;
        arow[it] = idx >> 3;
        akc[it]  = (idx & 7) << 2;
    }
    int brow[2], bc16[2];
#pragma unroll
    for (int it = 0; it < 2; ++it) {
        int idx = tid + it * 256;
        brow[it] = idx >> 2;
        bc16[it] = (idx & 3) << 4;
    }

    float acc[4][4][4];
#pragma unroll
    for (int i = 0; i < 4; i++)
#pragma unroll
        for (int j = 0; j < 4; j++)
#pragma unroll
            for (int l = 0; l < 4; l++) acc[i][j][l] = 0.0f;

    const int nch = K >> 5;
    float4 fr[4];
    uint2  urh[4], url[4];

    const uint32_t sB0 = sbase + ((MODE == 0) ? ASZ : 2 * ASZ);
    const uint32_t bstride = (MODE == 0) ? 2 * ASZ : ASZ;

#pragma unroll
    for (int it = 0; it < 4; ++it) {
        int gr = bm + arow[it];     // always < ROWS_T (buffers padded)
        if (MODE == 0) {
            fr[it] = *reinterpret_cast<const float4*>(A + (size_t)gr * lda + akc[it]);
        } else {
            urh[it] = *reinterpret_cast<const uint2*>(Ah + (size_t)gr * lda + akc[it]);
            url[it] = *reinterpret_cast<const uint2*>(Al + (size_t)gr * lda + akc[it]);
        }
    }
#pragma unroll
    for (int it = 0; it < 2; ++it) {
        uint32_t so = sB0 + brow[it] * ROWB + bc16[it];
        size_t gb = ((size_t)(bn + brow[it]) * ldb) * 2 + bc16[it];
        cpa16(so, (const char*)Bh + gb);
        if (MODE == 0) cpa16(so + ASZ, (const char*)Bl + gb);
    }
    asm volatile("cp.async.commit_group;" ::: "memory");

    for (int ch = 0; ch < nch; ++ch) {
#pragma unroll
        for (int it = 0; it < 4; ++it) {
            int off = arow[it] * ROWB + akc[it] * 2;
            if (MODE == 0) {
                float4 v = fr[it];
                v.x = fmaxf(v.x, 0.f); v.y = fmaxf(v.y, 0.f);
                v.z = fmaxf(v.z, 0.f); v.w = fmaxf(v.w, 0.f);
                __half2 h01 = __float22half2_rn(make_float2(v.x, v.y));
                __half2 h23 = __float22half2_rn(make_float2(v.z, v.w));
                uint2 u;
                u.x = *reinterpret_cast<uint32_t*>(&h01);
                u.y = *reinterpret_cast<uint32_t*>(&h23);
                *reinterpret_cast<uint2*>(sm + off) = u;
            } else {
                *reinterpret_cast<uint2*>(sm + off)       = urh[it];
                *reinterpret_cast<uint2*>(sm + ASZ + off) = url[it];
            }
        }
        asm volatile("cp.async.wait_group 0;" ::: "memory");
        __syncthreads();

        if (ch + 1 < nch) {
            int k0 = (ch + 1) << 5;
#pragma unroll
            for (int it = 0; it < 4; ++it) {
                int gr = bm + arow[it];
                if (MODE == 0) {
                    fr[it] = *reinterpret_cast<const float4*>(A + (size_t)gr * lda + k0 + akc[it]);
                } else {
                    urh[it] = *reinterpret_cast<const uint2*>(Ah + (size_t)gr * lda + k0 + akc[it]);
                    url[it] = *reinterpret_cast<const uint2*>(Al + (size_t)gr * lda + k0 + akc[it]);
                }
            }
            uint32_t so0 = sB0 + ((ch + 1) & 1) * bstride;
#pragma unroll
            for (int it = 0; it < 2; ++it) {
                uint32_t so = so0 + brow[it] * ROWB + bc16[it];
                size_t gb = ((size_t)(bn + brow[it]) * ldb + k0) * 2 + bc16[it];
                cpa16(so, (const char*)Bh + gb);
                if (MODE == 0) cpa16(so + ASZ, (const char*)Bl + gb);
            }
            asm volatile("cp.async.commit_group;" ::: "memory");
        }

        const uint32_t sB = sB0 + (ch & 1) * bstride;
#pragma unroll
        for (int ks = 0; ks < 2; ++ks) {
            uint32_t bfh[4][2], bfl[4][2];
#pragma unroll
            for (int nt = 0; nt < 4; ++nt) {
                uint32_t off = (uint32_t)((wn * 32 + nt * 8 + (lane & 7)) * ROWB
                                          + (ks * 16 + ((lane >> 3) & 1) * 8) * 2);
                ldmx2(bfh[nt], sB + off);
                if (MODE == 0) ldmx2(bfl[nt], sB + ASZ + off);
            }
#pragma unroll
            for (int mt = 0; mt < 4; ++mt) {
                uint32_t off = (uint32_t)((wm * 64 + mt * 16 + (lane & 15)) * ROWB
                                          + (ks * 16 + ((lane >> 4) & 1) * 8) * 2);
                uint32_t a0[4], a1[4];
                ldmx4(a0, sbase + off);
                if (MODE == 1) ldmx4(a1, sbase + ASZ + off);
#pragma unroll
                for (int nt = 0; nt < 4; ++nt) {
                    if (MODE == 0) {
                        mmaf16(acc[mt][nt], a0, bfh[nt]);
                        mmaf16(acc[mt][nt], a0, bfl[nt]);
                    } else {
                        mmaf16(acc[mt][nt], a0, bfh[nt]);
                        mmaf16(acc[mt][nt], a1, bfh[nt]);
                    }
                }
            }
        }
        __syncthreads();
    }

    const int groupID = lane >> 2;
    const int tid4 = lane & 3;
#pragma unroll
    for (int mt = 0; mt < 4; ++mt) {
#pragma unroll
        for (int half = 0; half < 2; ++half) {
            int gr = bm + wm * 64 + mt * 16 + groupID + half * 8;
#pragma unroll
            for (int nt = 0; nt < 4; ++nt) {
                int gc = bn + wn * 32 + nt * 8 + tid4 * 2;
                float2 r = make_float2(acc[mt][nt][half * 2], acc[mt][nt][half * 2 + 1]);
                if (MODE == 0) {
                    r.x = fmaxf(r.x, 0.f); r.y = fmaxf(r.y, 0.f);
                    __half2 hh = __float22half2_rn(r);
                    float2 fh = __half22float2(hh);
                    __half2 hl = __float22half2_rn(make_float2(r.x - fh.x, r.y - fh.y));
                    *reinterpret_cast<__half2*>(Cbh + (size_t)gr * ldc + gc) = hh;
                    *reinterpret_cast<__half2*>(Cbl + (size_t)gr * ldc + gc) = hl;
                } else {
                    float* Cp = nullptr;
                    if (gr < NN)                      Cp = Cf + (size_t)gr * ldc;
                    else if (gr >= SPLIT && gr < MST) Cp = Cs + (size_t)(gr - SPLIT) * ldc;
                    if (Cp) *reinterpret_cast<float2*>(Cp + gc) = r;
                }
            }
        }
    }
}

// ---------------------------------------------------------------------------
// CSR build + graph kernels
// ---------------------------------------------------------------------------
__global__ void zero_degi_kernel(int* __restrict__ degi, int n)
{
    int t = blockIdx.x * blockDim.x + threadIdx.x;
    if (t < n) degi[t] = 0;
}

__global__ void degi_kernel(const int* __restrict__ dst, int* __restrict__ degi, int e)
{
    int t = blockIdx.x * blockDim.x + threadIdx.x;
    if (t < e) atomicAdd(&degi[dst[t]], 1);
}

__global__ void __launch_bounds__(1024)
scandinv_kernel(const int* __restrict__ degi, int* __restrict__ off,
                int* __restrict__ cur, float* __restrict__ dinv,
                float* __restrict__ dinv2, int n)
{
    __shared__ int warpsum[32];
    __shared__ int carry;
    const int tid = threadIdx.x;
    const int lane = tid & 31;
    const int wrp = tid >> 5;
    if (tid == 0) carry = 0;
    __syncthreads();
    for (int base = 0; base < n; base += 1024) {
        int i = base + tid;
        int v = (i < n) ? degi[i] : 0;
        if (i < n) {
            float d  = (float)v + 1.0f;
            float di = 1.0f / sqrtf(d);
            dinv[i]  = di;
            dinv2[i] = di * di;
        }
        int x = v;
#pragma unroll
        for (int o = 1; o < 32; o <<= 1) {
            int y = __shfl_up_sync(0xffffffffu, x, o);
            if (lane >= o) x += y;
        }
        if (lane == 31) warpsum[wrp] = x;
        __syncthreads();
        if (tid < 32) {
            int s = warpsum[tid];
#pragma unroll
            for (int o = 1; o < 32; o <<= 1) {
                int y = __shfl_up_sync(0xffffffffu, s, o);
                if (tid >= o) s += y;
            }
            warpsum[tid] = s;
        }
        __syncthreads();
        int incl = x + (wrp ? warpsum[wrp - 1] : 0);
        int excl = incl - v + carry;
        if (i < n) { off[i] = excl; cur[i] = excl; }
        __syncthreads();
        if (tid == 1023) carry += incl;
        __syncthreads();
    }
}

__global__ void place_kernel(const int* __restrict__ src, const int* __restrict__ dst,
                             const float* __restrict__ dinv,
                             int* __restrict__ cur,
                             int* __restrict__ csrc, float* __restrict__ cw, int e)
{
    int t = blockIdx.x * blockDim.x + threadIdx.x;
    if (t >= e) return;
    int s = src[t], d = dst[t];
    int pos = atomicAdd(&cur[d], 1);
    csrc[pos] = s;
    cw[pos]   = dinv[s] * dinv[d];
}

// stacked gather: warps over [0, ROWS_T); both branches in one launch
__global__ void gather2_kernel(const float* __restrict__ h,
                               const int* __restrict__ off, const int* __restrict__ degi,
                               const int* __restrict__ csrc, const float* __restrict__ cw,
                               const float* __restrict__ dinv2,
                               const float* __restrict__ biasF, const float* __restrict__ biasS,
                               float* __restrict__ slice)
{
    int t = blockIdx.x * blockDim.x + threadIdx.x;
    int w = t >> 5;
    int n, hb;
    const float* bias;
    if (w < NN)                       { n = w;         hb = 0;     bias = biasF; }
    else if (w >= SPLIT && w < MST)   { n = w - SPLIT; hb = SPLIT; bias = biasS; }
    else return;
    int lane = t & 31;
    int c = lane << 2;
    const float4 hv = *reinterpret_cast<const float4*>(h + (size_t)w * DD + c);
    const float4 bb = *reinterpret_cast<const float4*>(bias + c);
    float d2 = dinv2[n];
    float4 acc = make_float4(hv.x * d2 + bb.x, hv.y * d2 + bb.y,
                             hv.z * d2 + bb.z, hv.w * d2 + bb.w);
    int j   = off[n];
    int end = j + degi[n];
    for (; j + 4 <= end; j += 4) {
        int   i0 = __ldg(csrc + j)     + hb, i1 = __ldg(csrc + j + 1) + hb;
        int   i2 = __ldg(csrc + j + 2) + hb, i3 = __ldg(csrc + j + 3) + hb;
        float w0 = __ldg(cw + j),       w1 = __ldg(cw + j + 1);
        float w2 = __ldg(cw + j + 2),   w3 = __ldg(cw + j + 3);
        float4 v0 = *reinterpret_cast<const float4*>(h + (size_t)i0 * DD + c);
        float4 v1 = *reinterpret_cast<const float4*>(h + (size_t)i1 * DD + c);
        float4 v2 = *reinterpret_cast<const float4*>(h + (size_t)i2 * DD + c);
        float4 v3 = *reinterpret_cast<const float4*>(h + (size_t)i3 * DD + c);
        acc.x += w0 * v0.x + w1 * v1.x + w2 * v2.x + w3 * v3.x;
        acc.y += w0 * v0.y + w1 * v1.y + w2 * v2.y + w3 * v3.y;
        acc.z += w0 * v0.z + w1 * v1.z + w2 * v2.z + w3 * v3.z;
        acc.w += w0 * v0.w + w1 * v1.w + w2 * v2.w + w3 * v3.w;
    }
    for (; j < end; ++j) {
        int s    = __ldg(csrc + j) + hb;
        float wt = __ldg(cw + j);
        float4 v = *reinterpret_cast<const float4*>(h + (size_t)s * DD + c);
        acc.x += wt * v.x; acc.y += wt * v.y;
        acc.z += wt * v.z; acc.w += wt * v.w;
    }
    *reinterpret_cast<float4*>(slice + (size_t)w * EDIM + c) = acc;
}

// stacked expmap+proj over 2*NN logical rows (out2/out4)
__global__ void expmap2_kernel(float* __restrict__ pF, float* __restrict__ pS)
{
    int t = blockIdx.x * blockDim.x + threadIdx.x;
    int w = t >> 5;
    if (w >= 2 * NN) return;
    int lane = t & 31;
    float* r = (w < NN) ? pF + (size_t)w * EDIM : pS + (size_t)(w - NN) * EDIM;
    float4 v0 = *reinterpret_cast<const float4*>(r + lane * 4);
    float4 v1 = *reinterpret_cast<const float4*>(r + lane * 4 + 128);
    float4 v2 = *reinterpret_cast<const float4*>(r + lane * 4 + 256);
    float ss = v0.x*v0.x + v0.y*v0.y + v0.z*v0.z + v0.w*v0.w
             + v1.x*v1.x + v1.y*v1.y + v1.z*v1.z + v1.w*v1.w
             + v2.x*v2.x + v2.y*v2.y + v2.z*v2.z + v2.w*v2.w;
#pragma unroll
    for (int o = 16; o; o >>= 1) ss += __shfl_xor_sync(0xffffffffu, ss, o);
    float nrm = sqrtf(ss);
    float n1  = fmaxf(nrm, 1e-15f);
    float s   = tanhf(n1) / n1;
    float yn  = s * nrm;
    const float maxn = 1.0f - 4e-3f;
    if (yn > maxn) s = s * maxn / yn;
    v0.x*=s; v0.y*=s; v0.z*=s; v0.w*=s;
    v1.x*=s; v1.y*=s; v1.z*=s; v1.w*=s;
    v2.x*=s; v2.y*=s; v2.z*=s; v2.w*=s;
    *reinterpret_cast<float4*>(r + lane * 4      ) = v0;
    *reinterpret_cast<float4*>(r + lane * 4 + 128) = v1;
    *reinterpret_cast<float4*>(r + lane * 4 + 256) = v2;
}

__global__ void expmap_proj_kernel(float* __restrict__ p, int rows)
{
    int t = blockIdx.x * blockDim.x + threadIdx.x;
    int w = t >> 5;
    if (w >= rows) return;
    int lane = t & 31;
    float* r = p + (size_t)w * EDIM;
    float4 v0 = *reinterpret_cast<const float4*>(r + lane * 4);
    float4 v1 = *reinterpret_cast<const float4*>(r + lane * 4 + 128);
    float4 v2 = *reinterpret_cast<const float4*>(r + lane * 4 + 256);
    float ss = v0.x*v0.x + v0.y*v0.y + v0.z*v0.z + v0.w*v0.w
             + v1.x*v1.x + v1.y*v1.y + v1.z*v1.z + v1.w*v1.w
             + v2.x*v2.x + v2.y*v2.y + v2.z*v2.z + v2.w*v2.w;
#pragma unroll
    for (int o = 16; o; o >>= 1) ss += __shfl_xor_sync(0xffffffffu, ss, o);
    float nrm = sqrtf(ss);
    float n1  = fmaxf(nrm, 1e-15f);
    float s   = tanhf(n1) / n1;
    float yn  = s * nrm;
    const float maxn = 1.0f - 4e-3f;
    if (yn > maxn) s = s * maxn / yn;
    v0.x*=s; v0.y*=s; v0.z*=s; v0.w*=s;
    v1.x*=s; v1.y*=s; v1.z*=s; v1.w*=s;
    v2.x*=s; v2.y*=s; v2.z*=s; v2.w*=s;
    *reinterpret_cast<float4*>(r + lane * 4      ) = v0;
    *reinterpret_cast<float4*>(r + lane * 4 + 128) = v1;
    *reinterpret_cast<float4*>(r + lane * 4 + 256) = v2;
}

// pool of relu(nfs): 1024 blocks; block g: graph g&511, branch g>>9
__global__ void pool2_kernel(const float* __restrict__ nfs, const int* __restrict__ batch,
                             float* __restrict__ gfs, int n)
{
    int g  = blockIdx.x & 511;
    int br = blockIdx.x >> 9;
    int t  = threadIdx.x;
    int lo = 0, hi = n;
    while (lo < hi) { int m = (lo + hi) >> 1; if (batch[m] < g) lo = m + 1; else hi = m; }
    int s0 = lo;
    hi = n;
    while (lo < hi) { int m = (lo + hi) >> 1; if (batch[m] < g + 1) lo = m + 1; else hi = m; }
    int s1 = lo;
    size_t rbase = (size_t)br * SPLIT;
    float acc = 0.0f;
    for (int i = s0; i < s1; i++)
        acc += fmaxf(nfs[(rbase + i) * EDIM + t], 0.0f);
    gfs[(size_t)g * GFS_LD + br * EDIM + t] = acc;
}

// ---------------------------------------------------------------------------
// fp32 SGEMM (tiny graph-level GEMMs, M=512). flags: 1=RELU, 2=ACCUM
// ---------------------------------------------------------------------------
__global__ void __launch_bounds__(256)
sgemm_kernel(const float* __restrict__ A, int lda,
             const float* __restrict__ B,
             float* __restrict__ C, int ldc,
             int M, int Nc, int K, int flags)
{
    __shared__ float As[16][132];
    __shared__ float Bs[16][128];
    const int tid = threadIdx.x;
    const int bm = blockIdx.x * 128;
    const int bn = blockIdx.y * 128;
    const int tx = tid & 15;
    const int ty = tid >> 4;

    float acc[8][8];
#pragma unroll
    for (int i = 0; i < 8; i++)
#pragma unroll
        for (int j = 0; j < 8; j++) acc[i][j] = 0.0f;

    for (int k0 = 0; k0 < K; k0 += 16) {
#pragma unroll
        for (int it = 0; it < 2; ++it) {
            int idx = tid + it * 256;
            int row = idx >> 2;
            int kc  = (idx & 3) << 2;
            int gr  = bm + row;
            float4 v = make_float4(0.f, 0.f, 0.f, 0.f);
            if (gr < M) v = *reinterpret_cast<const float4*>(A + (size_t)gr * lda + k0 + kc);
            As[kc + 0][row] = v.x; As[kc + 1][row] = v.y;
            As[kc + 2][row] = v.z; As[kc + 3][row] = v.w;
        }
#pragma unroll
        for (int it = 0; it < 2; ++it) {
            int idx = tid + it * 256;
            int kr  = idx >> 5;
            int nc  = (idx & 31) << 2;
            float4 v = *reinterpret_cast<const float4*>(B + (size_t)(k0 + kr) * Nc + bn + nc);
            *reinterpret_cast<float4*>(&Bs[kr][nc]) = v;
        }
        __syncthreads();
#pragma unroll
        for (int k = 0; k < 16; ++k) {
            float a[8], b[8];
#pragma unroll
            for (int i = 0; i < 8; i++) a[i] = As[k][ty * 8 + i];
#pragma unroll
            for (int j = 0; j < 8; j++) b[j] = Bs[k][tx * 8 + j];
#pragma unroll
            for (int i = 0; i < 8; i++)
#pragma unroll
                for (int j = 0; j < 8; j++) acc[i][j] = fmaf(a[i], b[j], acc[i][j]);
        }
        __syncthreads();
    }

#pragma unroll
    for (int i = 0; i < 8; i++) {
        int gr = bm + ty * 8 + i;
        if (gr >= M) break;
#pragma unroll
        for (int j = 0; j < 8; j += 4) {
            int gc = bn + tx * 8 + j;
            float4 r = make_float4(acc[i][j], acc[i][j+1], acc[i][j+2], acc[i][j+3]);
            if (flags & 2) {
                float4 o = *reinterpret_cast<const float4*>(C + (size_t)gr * ldc + gc);
                r.x += o.x; r.y += o.y; r.z += o.z; r.w += o.w;
            }
            if (flags & 1) {
                r.x = fmaxf(r.x, 0.f); r.y = fmaxf(r.y, 0.f);
                r.z = fmaxf(r.z, 0.f); r.w = fmaxf(r.w, 0.f);
            }
            *reinterpret_cast<float4*>(C + (size_t)gr * ldc + gc) = r;
        }
    }
}

// ---------------------------------------------------------------------------
// Host driver
// ---------------------------------------------------------------------------
static inline int ceil_div(int a, int b) { return (a + b - 1) / b; }

extern "C" void kernel_launch(void* const* d_in, const int* in_sizes, int n_in,
                              void* d_out, int out_size)
{
    (void)out_size;
    const float *x = nullptr, *xs = nullptr;
    const int *src = nullptr, *dst = nullptr, *batch = nullptr;
    const float *W[6] = {}; const float *bv[6] = {};
    const float *p147[3] = {}; const float *G1 = nullptr;
    int xi = 0, ei = 0, wi = 0, bi = 0, pi = 0;
    for (int i = 0; i < n_in; i++) {
        int s = in_sizes[i];
        const void* p = d_in[i];
        if (s == NN * FF)          { if (xi == 0) x = (const float*)p; else xs = (const float*)p; xi++; }
        else if (s == EE)          { if (ei == 0) src = (const int*)p; else dst = (const int*)p; ei++; }
        else if (s == NN)          { batch = (const int*)p; }
        else if (s == FF * DD)     { if (wi < 6) W[wi] = (const float*)p; wi++; }
        else if (s == DD)          { if (bi < 6) bv[bi] = (const float*)p; bi++; }
        else if (s == EDIM * EDIM) { if (pi < 3) p147[pi] = (const float*)p; pi++; }
        else if (s == 2 * EDIM * EDIM) { G1 = (const float*)p; }
    }
    const float* P1 = p147[0];
    const float* P2 = p147[1];
    const float* G2 = p147[2];

    float *hst, *nfs, *lms, *dinv, *dinv2, *gfs, *ghid, *cw;
    int *degi, *off, *cur, *csrc;
    __nv_bfloat16 *wth, *wtl;
    __half *hidh, *hidl, *p1h, *p1l, *p2h;
    cudaGetSymbolAddress((void**)&hst,  g_hst);
    cudaGetSymbolAddress((void**)&nfs,  g_nfs);
    cudaGetSymbolAddress((void**)&hidh, g_hidh);
    cudaGetSymbolAddress((void**)&hidl, g_hidl);
    cudaGetSymbolAddress((void**)&lms,  g_lms);
    cudaGetSymbolAddress((void**)&degi, g_degi);
    cudaGetSymbolAddress((void**)&dinv, g_dinv);
    cudaGetSymbolAddress((void**)&dinv2,g_dinv2);
    cudaGetSymbolAddress((void**)&off,  g_off);
    cudaGetSymbolAddress((void**)&cur,  g_cur);
    cudaGetSymbolAddress((void**)&csrc, g_csrc);
    cudaGetSymbolAddress((void**)&cw,   g_cw);
    cudaGetSymbolAddress((void**)&gfs,  g_gfs);
    cudaGetSymbolAddress((void**)&ghid, g_ghid);
    cudaGetSymbolAddress((void**)&wth,  g_wth);
    cudaGetSymbolAddress((void**)&wtl,  g_wtl);
    cudaGetSymbolAddress((void**)&p1h,  g_p1h);
    cudaGetSymbolAddress((void**)&p1l,  g_p1l);
    cudaGetSymbolAddress((void**)&p2h,  g_p2h);

    cudaFuncSetAttribute(mma_gemm2_kernel, cudaFuncAttributeMaxDynamicSharedMemorySize, GEMM_SMEM);
    cudaFuncSetAttribute(hgemm_kernel<0>, cudaFuncAttributeMaxDynamicSharedMemorySize, 5 * ASZ);
    cudaFuncSetAttribute(hgemm_kernel<1>, cudaFuncAttributeMaxDynamicSharedMemorySize, 4 * ASZ);

    float* out = (float*)d_out;
    const int E = EE, N = NN;
    const size_t OFF_P1 = 98304, OFF_P2 = 245760;

    const bool fork = g_hx.ok;
    cudaStream_t s0 = 0;
    cudaStream_t s1 = fork ? g_hx.s1 : (cudaStream_t)0;

    const int gemm_mx = ROWS_T / 128;        // 782 stacked tiles
    const int gwarps_st = ROWS_T * 32;       // stacked warp kernels

    // ---------------- prelude --------------------------------------------
    if (fork) {
        cudaEventRecord(g_hx.eFork, s0);
        cudaStreamWaitEvent(s1, g_hx.eFork, 0);
        zero_degi_kernel<<<ceil_div(N, 256), 256, 0, s1>>>(degi, N);
        degi_kernel<<<ceil_div(E, 256), 256, 0, s1>>>(dst, degi, E);
        scandinv_kernel<<<1, 1024, 0, s1>>>(degi, off, cur, dinv, dinv2, N);
        place_kernel<<<ceil_div(E, 256), 256, 0, s1>>>(src, dst, dinv, cur, csrc, cw, E);
        cudaEventRecord(g_hx.e2, s1);
        prep_kernel<<<14036, 256, 0, s0>>>(W[0], W[1], W[2], W[3], W[4], W[5], P1, P2,
                                           wth, wtl, p1h, p1l, p2h, x, xs,
                                           lms, lms + SPLIT);
        // stacked layer-0 GEMM (weights + lms only)
        mma_gemm2_kernel<<<dim3(gemm_mx, 1), 256, GEMM_SMEM, s0>>>(
            x, xs, FF,
            wth, wtl, wth + 3 * 16384, wtl + 3 * 16384, DD,
            hst, DD, DD, 16, lms);
        cudaStreamWaitEvent(s0, g_hx.e2, 0);   // gathers need CSR
    } else {
        zero_degi_kernel<<<ceil_div(N, 256), 256, 0, s0>>>(degi, N);
        degi_kernel<<<ceil_div(E, 256), 256, 0, s0>>>(dst, degi, E);
        scandinv_kernel<<<1, 1024, 0, s0>>>(degi, off, cur, dinv, dinv2, N);
        place_kernel<<<ceil_div(E, 256), 256, 0, s0>>>(src, dst, dinv, cur, csrc, cw, E);
        prep_kernel<<<14036, 256, 0, s0>>>(W[0], W[1], W[2], W[3], W[4], W[5], P1, P2,
                                           wth, wtl, p1h, p1l, p2h, x, xs,
                                           lms, lms + SPLIT);
        mma_gemm2_kernel<<<dim3(gemm_mx, 1), 256, GEMM_SMEM, s0>>>(
            x, xs, FF,
            wth, wtl, wth + 3 * 16384, wtl + 3 * 16384, DD,
            hst, DD, DD, 16, lms);
    }

    // ---------------- stacked encoder (s0) ---------------------------------
    for (int l = 0; l < 3; l++) {
        float* slice = nfs + l * DD;
        gather2_kernel<<<ceil_div(gwarps_st, 256), 256, 0, s0>>>(
            hst, off, degi, csrc, cw, dinv2, bv[l], bv[3 + l], slice);
        if (l < 2) {
            size_t wf = (size_t)(l + 1) * 16384;
            size_t ws = (size_t)(l + 4) * 16384;
            mma_gemm2_kernel<<<dim3(gemm_mx, 1), 256, GEMM_SMEM, s0>>>(
                slice, slice + (size_t)SPLIT * EDIM, EDIM,
                wth + wf, wtl + wf, wth + ws, wtl + ws, DD,
                hst, DD, DD, 8, nullptr);
        }
    }
    pool2_kernel<<<1024, EDIM, 0, s0>>>(nfs, batch, gfs, N);
    if (fork) cudaEventRecord(g_hx.ePool, s0);

    const size_t off0 = 0;
    const size_t off1 = (size_t)GG * EDIM;
    const size_t off2 = 2 * (size_t)GG * EDIM;
    const size_t off3 = off2 + (size_t)N * EDIM;
    const size_t off4 = off3 + (size_t)GG * EDIM;

    const int ggrid = ceil_div(GG, 128);
    const int gwarp_threads = GG * 32;
    float* ghid0 = ghid;
    float* ghid1 = ghid + (size_t)GG * EDIM;
    float* ghid3 = ghid + 2 * (size_t)GG * EDIM;
    float* gf = gfs;
    float* gs = gfs + EDIM;

    // ---------------- s1 tail: out3 + out1 (small) -------------------------
    if (fork) {
        cudaStreamWaitEvent(s1, g_hx.ePool, 0);
        sgemm_kernel<<<dim3(ggrid, 3), 256, 0, s1>>>(gs, GFS_LD, P1, ghid3, EDIM,
                                                     GG, EDIM, EDIM, 1);
        sgemm_kernel<<<dim3(ggrid, 3), 256, 0, s1>>>(ghid3, EDIM, P2, out + off3, EDIM,
                                                     GG, EDIM, EDIM, 0);
        expmap_proj_kernel<<<ceil_div(gwarp_threads, 256), 256, 0, s1>>>(out + off3, GG);
        sgemm_kernel<<<dim3(ggrid, 3), 256, 0, s1>>>(gf, GFS_LD, P1, ghid1, EDIM,
                                                     GG, EDIM, EDIM, 1);
        sgemm_kernel<<<dim3(ggrid, 3), 256, 0, s1>>>(ghid1, EDIM, P2, out + off1, EDIM,
                                                     GG, EDIM, EDIM, 0);
        expmap_proj_kernel<<<ceil_div(gwarp_threads, 256), 256, 0, s1>>>(out + off1, GG);
        cudaEventRecord(g_hx.eEnd, s1);
    }

    // ---------------- s0: stacked heads (out2 + out4) ----------------------
    hgemm_kernel<0><<<dim3(gemm_mx, 3), 256, 5 * ASZ, s0>>>(
        nfs, nullptr, nullptr, EDIM, p1h, p1l, EDIM,
        nullptr, nullptr, hidh, hidl, EDIM, EDIM);
    hgemm_kernel<1><<<dim3(gemm_mx, 3), 256, 4 * ASZ, s0>>>(
        nullptr, hidh, hidl, EDIM, p2h, nullptr, EDIM,
        out + off2, out + off4, nullptr, nullptr, EDIM, EDIM);
    expmap2_kernel<<<ceil_div(2 * N * 32, 256), 256, 0, s0>>>(out + off2, out + off4);

    // ---------------- out0 (needs gfs; same stream as pool) ----------------
    sgemm_kernel<<<dim3(ggrid, 3), 256, 0, s0>>>(gfs, GFS_LD, G1, ghid0, EDIM,
                                                 GG, EDIM, 2 * EDIM, 1);
    sgemm_kernel<<<dim3(ggrid, 3), 256, 0, s0>>>(ghid0, EDIM, G2, out + off0, EDIM,
                                                 GG, EDIM, EDIM, 0);
    expmap_proj_kernel<<<ceil_div(gwarp_threads, 256), 256, 0, s0>>>(out + off0, GG);

    if (!fork) {
        // serial tail: out3 + out1 on s0
        sgemm_kernel<<<dim3(ggrid, 3), 256, 0, s0>>>(gs, GFS_LD, P1, ghid3, EDIM,
                                                     GG, EDIM, EDIM, 1);
        sgemm_kernel<<<dim3(ggrid, 3), 256, 0, s0>>>(ghid3, EDIM, P2, out + off3, EDIM,
                                                     GG, EDIM, EDIM, 0);
        expmap_proj_kernel<<<ceil_div(gwarp_threads, 256), 256, 0, s0>>>(out + off3, GG);
        sgemm_kernel<<<dim3(ggrid, 3), 256, 0, s0>>>(gf, GFS_LD, P1, ghid1, EDIM,
                                                     GG, EDIM, EDIM, 1);
        sgemm_kernel<<<dim3(ggrid, 3), 256, 0, s0>>>(ghid1, EDIM, P2, out + off1, EDIM,
                                                     GG, EDIM, EDIM, 0);
        expmap_proj_kernel<<<ceil_div(gwarp_threads, 256), 256, 0, s0>>>(out + off1, GG);
    } else {
        cudaStreamWaitEvent(s0, g_hx.eEnd, 0);
    }
}

// round 13
// speedup vs baseline: 1.0244x; 1.0244x over previous
#include <cuda_runtime.h>
#include <cuda_bf16.h>
#include <cuda_fp16.h>
#include <cstdint>
#include <cstddef>

// Problem constants (fixed by the reference)
#define NN 50000
#define EE 600000
#define GG 512
#define FF 128
#define DD 128
#define EDIM 384
#define GFS_LD 768

// ---------------------------------------------------------------------------
// Scratch (device globals -- no allocation allowed in kernel_launch)
// ---------------------------------------------------------------------------
__device__ __align__(16) float g_h   [NN * DD];
__device__ __align__(16) float g_h2  [NN * DD];
__device__ __align__(16) float g_nf  [NN * EDIM];
__device__ __align__(16) float g_ns  [NN * EDIM];
__device__ __align__(16) __half g_hidh [NN * EDIM];
__device__ __align__(16) __half g_hidl [NN * EDIM];
__device__ __align__(16) __half g_hid2h[NN * EDIM];
__device__ __align__(16) __half g_hid2l[NN * EDIM];
__device__ float g_lms [NN];
__device__ float g_lms2[NN];
__device__ int   g_degi[NN];
__device__ float g_dinv[NN];
__device__ float g_dinv2[NN];
__device__ int   g_off [NN];
__device__ int   g_cur [NN];
__device__ int   g_csrc[EE];
__device__ float g_cw  [EE];
__device__ __align__(16) float g_gfs [GG * GFS_LD];   // [gf | gs] concat rows
__device__ __align__(16) float g_ghid[3 * GG * EDIM];
// transposed + split weights (bf16 hi/lo), [N,K] row-major (GCN)
__device__ __align__(16) __nv_bfloat16 g_wth[393216];
__device__ __align__(16) __nv_bfloat16 g_wtl[393216];
// fp16 head weights, transposed [N,K]: P1 split hi/lo, P2 hi only
__device__ __align__(16) __half g_p1h[147456];
__device__ __align__(16) __half g_p1l[147456];
__device__ __align__(16) __half g_p2h[147456];

// ---------------------------------------------------------------------------
// Static-init stream/event resources
// ---------------------------------------------------------------------------
struct HxStreams {
    cudaStream_t s1 = nullptr;
    cudaEvent_t eFork = nullptr, e1 = nullptr, e2 = nullptr;
    cudaEvent_t eGS = nullptr, eGF = nullptr, eEnd = nullptr;
    bool ok = false;
    HxStreams() {
        ok = (cudaStreamCreateWithFlags(&s1, cudaStreamNonBlocking) == cudaSuccess)
          && (cudaEventCreateWithFlags(&eFork, cudaEventDisableTiming) == cudaSuccess)
          && (cudaEventCreateWithFlags(&e1,   cudaEventDisableTiming) == cudaSuccess)
          && (cudaEventCreateWithFlags(&e2,   cudaEventDisableTiming) == cudaSuccess)
          && (cudaEventCreateWithFlags(&eGS,  cudaEventDisableTiming) == cudaSuccess)
          && (cudaEventCreateWithFlags(&eGF,  cudaEventDisableTiming) == cudaSuccess)
          && (cudaEventCreateWithFlags(&eEnd, cudaEventDisableTiming) == cudaSuccess);
    }
};
static HxStreams g_hx;

// ---------------------------------------------------------------------------
// Helpers
// ---------------------------------------------------------------------------
__device__ __forceinline__ void ldmx4(uint32_t* r, uint32_t addr) {
    asm volatile("ldmatrix.sync.aligned.m8n8.x4.shared.b16 {%0,%1,%2,%3}, [%4];"
                 : "=r"(r[0]), "=r"(r[1]), "=r"(r[2]), "=r"(r[3]) : "r"(addr));
}
__device__ __forceinline__ void ldmx2(uint32_t* r, uint32_t addr) {
    asm volatile("ldmatrix.sync.aligned.m8n8.x2.shared.b16 {%0,%1}, [%2];"
                 : "=r"(r[0]), "=r"(r[1]) : "r"(addr));
}
__device__ __forceinline__ void mma16816(float* d, const uint32_t* a, const uint32_t* b) {
    asm volatile("mma.sync.aligned.m16n8k16.row.col.f32.bf16.bf16.f32 "
                 "{%0,%1,%2,%3}, {%4,%5,%6,%7}, {%8,%9}, {%0,%1,%2,%3};"
                 : "+f"(d[0]), "+f"(d[1]), "+f"(d[2]), "+f"(d[3])
                 : "r"(a[0]), "r"(a[1]), "r"(a[2]), "r"(a[3]), "r"(b[0]), "r"(b[1]));
}
__device__ __forceinline__ void mmaf16(float* d, const uint32_t* a, const uint32_t* b) {
    asm volatile("mma.sync.aligned.m16n8k16.row.col.f32.f16.f16.f32 "
                 "{%0,%1,%2,%3}, {%4,%5,%6,%7}, {%8,%9}, {%0,%1,%2,%3};"
                 : "+f"(d[0]), "+f"(d[1]), "+f"(d[2]), "+f"(d[3])
                 : "r"(a[0]), "r"(a[1]), "r"(a[2]), "r"(a[3]), "r"(b[0]), "r"(b[1]));
}
__device__ __forceinline__ uint32_t smem_u32(const void* p) {
    uint32_t a;
    asm("{ .reg .u64 t; cvta.to.shared.u64 t, %1; cvt.u32.u64 %0, t; }" : "=r"(a) : "l"(p));
    return a;
}
__device__ __forceinline__ void cpa16(uint32_t saddr, const void* gaddr) {
    asm volatile("cp.async.cg.shared.global [%0], [%1], 16;" :: "r"(saddr), "l"(gaddr));
}

// ---------------------------------------------------------------------------
// prep kernel: weight transpose+split (blocks 0..1535), logmap scales after.
// ---------------------------------------------------------------------------
__global__ void prep_kernel(const float* __restrict__ W0, const float* __restrict__ W1,
                            const float* __restrict__ W2, const float* __restrict__ W3,
                            const float* __restrict__ W4, const float* __restrict__ W5,
                            const float* __restrict__ P1, const float* __restrict__ P2,
                            __nv_bfloat16* __restrict__ Th, __nv_bfloat16* __restrict__ Tl,
                            __half* __restrict__ p1h, __half* __restrict__ p1l,
                            __half* __restrict__ p2h,
                            const float* __restrict__ x, const float* __restrict__ xs,
                            float* __restrict__ lms, float* __restrict__ lms2)
{
    int b = blockIdx.x;
    if (b < 1536) {
        int idx = b * 256 + threadIdx.x;
        const float* W; int K, N, li, base; int which = 0;
        if (idx < 98304) {
            int m = idx >> 14; li = idx & 16383;
            const float* ws[6] = {W0, W1, W2, W3, W4, W5};
            W = ws[m]; K = 128; N = 128; base = m << 14;
        } else if (idx < 245760) { W = P1; li = idx - 98304; K = 384; N = 384; base = 98304; which = 1; }
        else                     { W = P2; li = idx - 245760; K = 384; N = 384; base = 245760; which = 2; }
        int k = li / N, n = li % N;
        float v = W[li];
        __nv_bfloat16 h = __float2bfloat16_rn(v);
        Th[base + n * K + k] = h;
        Tl[base + n * K + k] = __float2bfloat16_rn(v - __bfloat162float(h));
        if (which == 1) {
            __half fh = __float2half_rn(v);
            p1h[n * 384 + k] = fh;
            p1l[n * 384 + k] = __float2half_rn(v - __half2float(fh));
        } else if (which == 2) {
            p2h[n * 384 + k] = __float2half_rn(v);
        }
    } else {
        int rb = b - 1536;
        const float* xin = x; float* sout = lms;
        if (rb >= 6250) { rb -= 6250; xin = xs; sout = lms2; }
        int w = rb * 8 + (threadIdx.x >> 5);
        if (w >= NN) return;
        int lane = threadIdx.x & 31;
        const float4 v = *reinterpret_cast<const float4*>(xin + (size_t)w * FF + lane * 4);
        float ss = v.x * v.x + v.y * v.y + v.z * v.z + v.w * v.w;
#pragma unroll
        for (int o = 16; o; o >>= 1) ss += __shfl_xor_sync(0xffffffffu, ss, o);
        if (lane == 0) {
            float nrm = sqrtf(ss);
            float n1  = fmaxf(nrm, 1e-15f);
            float arg = fminf(n1, 1.0f - 1e-15f);
            sout[w] = atanhf(arg) / n1;
        }
    }
}

// ---------------------------------------------------------------------------
// bf16 split-3 GEMM (GCN layers). A fp32 on the fly.
// flags: 8=RELU on A, 16=scale A rows by ascale[].
// ---------------------------------------------------------------------------
#define ROWB 80
#define ASZ (128 * ROWB)
#define GEMM_SMEM (6 * ASZ)

__global__ void __launch_bounds__(256, 2)
mma_gemm_kernel(const float* __restrict__ A, int lda,
                const __nv_bfloat16* __restrict__ Bh, const __nv_bfloat16* __restrict__ Bl,
                int ldb,
                float* __restrict__ C, int ldc,
                int M, int K, int flags,
                const float* __restrict__ ascale)
{
    extern __shared__ __align__(16) char sm[];
    const int tid  = threadIdx.x;
    const int wid  = tid >> 5;
    const int lane = tid & 31;
    const int wm = wid & 1;
    const int wn = wid >> 1;
    const int bm = blockIdx.x * 128;
    const int bn = blockIdx.y * 128;
    const uint32_t sbase = smem_u32(sm);

    int arow[4], akc[4];
#pragma unroll
    for (int it = 0; it < 4; ++it) {
        int idx = tid + it * 256;
        arow[it] = idx >> 3;
        akc[it]  = (idx & 7) << 2;
    }
    int brow[2], bc16[2];
#pragma unroll
    for (int it = 0; it < 2; ++it) {
        int idx = tid + it * 256;
        brow[it] = idx >> 2;
        bc16[it] = (idx & 3) << 4;
    }

    float acc[4][4][4];
#pragma unroll
    for (int i = 0; i < 4; i++)
#pragma unroll
        for (int j = 0; j < 4; j++)
#pragma unroll
            for (int l = 0; l < 4; l++) acc[i][j][l] = 0.0f;

    const int nch = K >> 5;
    float4 fr[4];
    float  asc[4];

#pragma unroll
    for (int it = 0; it < 4; ++it) {
        int gr = bm + arow[it];
        fr[it] = make_float4(0.f, 0.f, 0.f, 0.f);
        asc[it] = 1.0f;
        if (gr < M) {
            fr[it] = *reinterpret_cast<const float4*>(A + (size_t)gr * lda + akc[it]);
            if (flags & 16) asc[it] = ascale[gr];
        }
    }
#pragma unroll
    for (int it = 0; it < 2; ++it) {
        uint32_t so = sbase + 2 * ASZ + brow[it] * ROWB + bc16[it];
        size_t gb = ((size_t)(bn + brow[it]) * ldb) * 2 + bc16[it];
        cpa16(so,       (const char*)Bh + gb);
        cpa16(so + ASZ, (const char*)Bl + gb);
    }
    asm volatile("cp.async.commit_group;" ::: "memory");

    for (int ch = 0; ch < nch; ++ch) {
#pragma unroll
        for (int it = 0; it < 4; ++it) {
            float4 v = fr[it];
            float s = asc[it];
            v.x *= s; v.y *= s; v.z *= s; v.w *= s;
            if (flags & 8) {
                v.x = fmaxf(v.x, 0.f); v.y = fmaxf(v.y, 0.f);
                v.z = fmaxf(v.z, 0.f); v.w = fmaxf(v.w, 0.f);
            }
            __nv_bfloat162 h01 = __floats2bfloat162_rn(v.x, v.y);
            __nv_bfloat162 h23 = __floats2bfloat162_rn(v.z, v.w);
            float2 f01 = __bfloat1622float2(h01);
            float2 f23 = __bfloat1622float2(h23);
            __nv_bfloat162 l01 = __floats2bfloat162_rn(v.x - f01.x, v.y - f01.y);
            __nv_bfloat162 l23 = __floats2bfloat162_rn(v.z - f23.x, v.w - f23.y);
            int off = arow[it] * ROWB + akc[it] * 2;
            uint2 uh, ul;
            uh.x = *reinterpret_cast<uint32_t*>(&h01);
            uh.y = *reinterpret_cast<uint32_t*>(&h23);
            ul.x = *reinterpret_cast<uint32_t*>(&l01);
            ul.y = *reinterpret_cast<uint32_t*>(&l23);
            *reinterpret_cast<uint2*>(sm + off)       = uh;
            *reinterpret_cast<uint2*>(sm + ASZ + off) = ul;
        }
        asm volatile("cp.async.wait_group 0;" ::: "memory");
        __syncthreads();

        if (ch + 1 < nch) {
            int k0 = (ch + 1) << 5;
#pragma unroll
            for (int it = 0; it < 4; ++it) {
                int gr = bm + arow[it];
                fr[it] = make_float4(0.f, 0.f, 0.f, 0.f);
                if (gr < M)
                    fr[it] = *reinterpret_cast<const float4*>(A + (size_t)gr * lda + k0 + akc[it]);
            }
            uint32_t bufo = 2 * ASZ + ((ch + 1) & 1) * (2 * ASZ);
#pragma unroll
            for (int it = 0; it < 2; ++it) {
                uint32_t so = sbase + bufo + brow[it] * ROWB + bc16[it];
                size_t gb = ((size_t)(bn + brow[it]) * ldb + k0) * 2 + bc16[it];
                cpa16(so,       (const char*)Bh + gb);
                cpa16(so + ASZ, (const char*)Bl + gb);
            }
            asm volatile("cp.async.commit_group;" ::: "memory");
        }

        const uint32_t sB = sbase + 2 * ASZ + (ch & 1) * (2 * ASZ);
#pragma unroll
        for (int ks = 0; ks < 2; ++ks) {
            uint32_t bfh[4][2], bfl[4][2];
#pragma unroll
            for (int nt = 0; nt < 4; ++nt) {
                uint32_t off = (uint32_t)((wn * 32 + nt * 8 + (lane & 7)) * ROWB
                                          + (ks * 16 + ((lane >> 3) & 1) * 8) * 2);
                ldmx2(bfh[nt], sB + off);
                ldmx2(bfl[nt], sB + ASZ + off);
            }
#pragma unroll
            for (int mt = 0; mt < 4; ++mt) {
                uint32_t off = (uint32_t)((wm * 64 + mt * 16 + (lane & 15)) * ROWB
                                          + (ks * 16 + ((lane >> 4) & 1) * 8) * 2);
                uint32_t ah[4], al[4];
                ldmx4(ah, sbase + off);
                ldmx4(al, sbase + ASZ + off);
#pragma unroll
                for (int nt = 0; nt < 4; ++nt) {
                    mma16816(acc[mt][nt], ah, bfh[nt]);
                    mma16816(acc[mt][nt], al, bfh[nt]);
                    mma16816(acc[mt][nt], ah, bfl[nt]);
                }
            }
        }
        __syncthreads();
    }

    const int groupID = lane >> 2;
    const int tid4 = lane & 3;
#pragma unroll
    for (int mt = 0; mt < 4; ++mt) {
#pragma unroll
        for (int half = 0; half < 2; ++half) {
            int gr = bm + wm * 64 + mt * 16 + groupID + half * 8;
            if (gr >= M) continue;
#pragma unroll
            for (int nt = 0; nt < 4; ++nt) {
                int gc = bn + wn * 32 + nt * 8 + tid4 * 2;
                float2 r = make_float2(acc[mt][nt][half * 2], acc[mt][nt][half * 2 + 1]);
                *reinterpret_cast<float2*>(C + (size_t)gr * ldc + gc) = r;
            }
        }
    }
}

// ---------------------------------------------------------------------------
// fp16 2-MMA head GEMM (MODE 0: fp32 A + split B -> fp16-split C;
//                       MODE 1: split A + single B -> fp32 C)
// ---------------------------------------------------------------------------
template<int MODE>
__global__ void __launch_bounds__(256, 2)
hgemm_kernel(const float* __restrict__ A,
             const __half* __restrict__ Ah, const __half* __restrict__ Al,
             int lda,
             const __half* __restrict__ Bh, const __half* __restrict__ Bl,
             int ldb,
             float* __restrict__ C,
             __half* __restrict__ Cbh, __half* __restrict__ Cbl,
             int ldc, int M, int K)
{
    extern __shared__ __align__(16) char sm[];
    const int tid  = threadIdx.x;
    const int wid  = tid >> 5;
    const int lane = tid & 31;
    const int wm = wid & 1;
    const int wn = wid >> 1;
    const int bm = blockIdx.x * 128;
    const int bn = blockIdx.y * 128;
    const uint32_t sbase = smem_u32(sm);

    int arow[4], akc[4];
#pragma unroll
    for (int it = 0; it < 4; ++it) {
        int idx = tid + it * 256;
        arow[it] = idx >> 3;
        akc[it]  = (idx & 7) << 2;
    }
    int brow[2], bc16[2];
#pragma unroll
    for (int it = 0; it < 2; ++it) {
        int idx = tid + it * 256;
        brow[it] = idx >> 2;
        bc16[it] = (idx & 3) << 4;
    }

    float acc[4][4][4];
#pragma unroll
    for (int i = 0; i < 4; i++)
#pragma unroll
        for (int j = 0; j < 4; j++)
#pragma unroll
            for (int l = 0; l < 4; l++) acc[i][j][l] = 0.0f;

    const int nch = K >> 5;
    float4 fr[4];
    uint2  urh[4], url[4];

    const uint32_t sB0 = sbase + ((MODE == 0) ? ASZ : 2 * ASZ);
    const uint32_t bstride = (MODE == 0) ? 2 * ASZ : ASZ;

#pragma unroll
    for (int it = 0; it < 4; ++it) {
        int gr = bm + arow[it];
        if (MODE == 0) {
            fr[it] = make_float4(0.f, 0.f, 0.f, 0.f);
            if (gr < M) fr[it] = *reinterpret_cast<const float4*>(A + (size_t)gr * lda + akc[it]);
        } else {
            urh[it] = make_uint2(0, 0); url[it] = make_uint2(0, 0);
            if (gr < M) {
                urh[it] = *reinterpret_cast<const uint2*>(Ah + (size_t)gr * lda + akc[it]);
                url[it] = *reinterpret_cast<const uint2*>(Al + (size_t)gr * lda + akc[it]);
            }
        }
    }
#pragma unroll
    for (int it = 0; it < 2; ++it) {
        uint32_t so = sB0 + brow[it] * ROWB + bc16[it];
        size_t gb = ((size_t)(bn + brow[it]) * ldb) * 2 + bc16[it];
        cpa16(so, (const char*)Bh + gb);
        if (MODE == 0) cpa16(so + ASZ, (const char*)Bl + gb);
    }
    asm volatile("cp.async.commit_group;" ::: "memory");

    for (int ch = 0; ch < nch; ++ch) {
#pragma unroll
        for (int it = 0; it < 4; ++it) {
            int off = arow[it] * ROWB + akc[it] * 2;
            if (MODE == 0) {
                float4 v = fr[it];
                v.x = fmaxf(v.x, 0.f); v.y = fmaxf(v.y, 0.f);
                v.z = fmaxf(v.z, 0.f); v.w = fmaxf(v.w, 0.f);
                __half2 h01 = __float22half2_rn(make_float2(v.x, v.y));
                __half2 h23 = __float22half2_rn(make_float2(v.z, v.w));
                uint2 u;
                u.x = *reinterpret_cast<uint32_t*>(&h01);
                u.y = *reinterpret_cast<uint32_t*>(&h23);
                *reinterpret_cast<uint2*>(sm + off) = u;
            } else {
                *reinterpret_cast<uint2*>(sm + off)       = urh[it];
                *reinterpret_cast<uint2*>(sm + ASZ + off) = url[it];
            }
        }
        asm volatile("cp.async.wait_group 0;" ::: "memory");
        __syncthreads();

        if (ch + 1 < nch) {
            int k0 = (ch + 1) << 5;
#pragma unroll
            for (int it = 0; it < 4; ++it) {
                int gr = bm + arow[it];
                if (MODE == 0) {
                    fr[it] = make_float4(0.f, 0.f, 0.f, 0.f);
                    if (gr < M)
                        fr[it] = *reinterpret_cast<const float4*>(A + (size_t)gr * lda + k0 + akc[it]);
                } else {
                    urh[it] = make_uint2(0, 0); url[it] = make_uint2(0, 0);
                    if (gr < M) {
                        urh[it] = *reinterpret_cast<const uint2*>(Ah + (size_t)gr * lda + k0 + akc[it]);
                        url[it] = *reinterpret_cast<const uint2*>(Al + (size_t)gr * lda + k0 + akc[it]);
                    }
                }
            }
            uint32_t so0 = sB0 + ((ch + 1) & 1) * bstride;
#pragma unroll
            for (int it = 0; it < 2; ++it) {
                uint32_t so = so0 + brow[it] * ROWB + bc16[it];
                size_t gb = ((size_t)(bn + brow[it]) * ldb + k0) * 2 + bc16[it];
                cpa16(so, (const char*)Bh + gb);
                if (MODE == 0) cpa16(so + ASZ, (const char*)Bl + gb);
            }
            asm volatile("cp.async.commit_group;" ::: "memory");
        }

        const uint32_t sB = sB0 + (ch & 1) * bstride;
#pragma unroll
        for (int ks = 0; ks < 2; ++ks) {
            uint32_t bfh[4][2], bfl[4][2];
#pragma unroll
            for (int nt = 0; nt < 4; ++nt) {
                uint32_t off = (uint32_t)((wn * 32 + nt * 8 + (lane & 7)) * ROWB
                                          + (ks * 16 + ((lane >> 3) & 1) * 8) * 2);
                ldmx2(bfh[nt], sB + off);
                if (MODE == 0) ldmx2(bfl[nt], sB + ASZ + off);
            }
#pragma unroll
            for (int mt = 0; mt < 4; ++mt) {
                uint32_t off = (uint32_t)((wm * 64 + mt * 16 + (lane & 15)) * ROWB
                                          + (ks * 16 + ((lane >> 4) & 1) * 8) * 2);
                uint32_t a0[4], a1[4];
                ldmx4(a0, sbase + off);
                if (MODE == 1) ldmx4(a1, sbase + ASZ + off);
#pragma unroll
                for (int nt = 0; nt < 4; ++nt) {
                    if (MODE == 0) {
                        mmaf16(acc[mt][nt], a0, bfh[nt]);
                        mmaf16(acc[mt][nt], a0, bfl[nt]);
                    } else {
                        mmaf16(acc[mt][nt], a0, bfh[nt]);
                        mmaf16(acc[mt][nt], a1, bfh[nt]);
                    }
                }
            }
        }
        __syncthreads();
    }

    const int groupID = lane >> 2;
    const int tid4 = lane & 3;
#pragma unroll
    for (int mt = 0; mt < 4; ++mt) {
#pragma unroll
        for (int half = 0; half < 2; ++half) {
            int gr = bm + wm * 64 + mt * 16 + groupID + half * 8;
            if (gr >= M) continue;
#pragma unroll
            for (int nt = 0; nt < 4; ++nt) {
                int gc = bn + wn * 32 + nt * 8 + tid4 * 2;
                float2 r = make_float2(acc[mt][nt][half * 2], acc[mt][nt][half * 2 + 1]);
                if (MODE == 0) {
                    r.x = fmaxf(r.x, 0.f); r.y = fmaxf(r.y, 0.f);
                    __half2 hh = __float22half2_rn(r);
                    float2 fh = __half22float2(hh);
                    __half2 hl = __float22half2_rn(make_float2(r.x - fh.x, r.y - fh.y));
                    *reinterpret_cast<__half2*>(Cbh + (size_t)gr * ldc + gc) = hh;
                    *reinterpret_cast<__half2*>(Cbl + (size_t)gr * ldc + gc) = hl;
                } else {
                    *reinterpret_cast<float2*>(C + (size_t)gr * ldc + gc) = r;
                }
            }
        }
    }
}

// ---------------------------------------------------------------------------
// CSR build + graph kernels
// ---------------------------------------------------------------------------
__global__ void zero_degi_kernel(int* __restrict__ degi, int n)
{
    int t = blockIdx.x * blockDim.x + threadIdx.x;
    if (t < n) degi[t] = 0;
}

__global__ void degi_kernel(const int* __restrict__ dst, int* __restrict__ degi, int e)
{
    int t = blockIdx.x * blockDim.x + threadIdx.x;
    if (t < e) atomicAdd(&degi[dst[t]], 1);
}

__global__ void __launch_bounds__(1024)
scandinv_kernel(const int* __restrict__ degi, int* __restrict__ off,
                int* __restrict__ cur, float* __restrict__ dinv,
                float* __restrict__ dinv2, int n)
{
    __shared__ int warpsum[32];
    __shared__ int carry;
    const int tid = threadIdx.x;
    const int lane = tid & 31;
    const int wrp = tid >> 5;
    if (tid == 0) carry = 0;
    __syncthreads();
    for (int base = 0; base < n; base += 1024) {
        int i = base + tid;
        int v = (i < n) ? degi[i] : 0;
        if (i < n) {
            float d  = (float)v + 1.0f;
            float di = 1.0f / sqrtf(d);
            dinv[i]  = di;
            dinv2[i] = di * di;
        }
        int x = v;
#pragma unroll
        for (int o = 1; o < 32; o <<= 1) {
            int y = __shfl_up_sync(0xffffffffu, x, o);
            if (lane >= o) x += y;
        }
        if (lane == 31) warpsum[wrp] = x;
        __syncthreads();
        if (tid < 32) {
            int s = warpsum[tid];
#pragma unroll
            for (int o = 1; o < 32; o <<= 1) {
                int y = __shfl_up_sync(0xffffffffu, s, o);
                if (tid >= o) s += y;
            }
            warpsum[tid] = s;
        }
        __syncthreads();
        int incl = x + (wrp ? warpsum[wrp - 1] : 0);
        int excl = incl - v + carry;
        if (i < n) { off[i] = excl; cur[i] = excl; }
        __syncthreads();
        if (tid == 1023) carry += incl;
        __syncthreads();
    }
}

__global__ void place_kernel(const int* __restrict__ src, const int* __restrict__ dst,
                             const float* __restrict__ dinv,
                             int* __restrict__ cur,
                             int* __restrict__ csrc, float* __restrict__ cw, int e)
{
    int t = blockIdx.x * blockDim.x + threadIdx.x;
    if (t >= e) return;
    int s = src[t], d = dst[t];
    int pos = atomicAdd(&cur[d], 1);
    csrc[pos] = s;
    cw[pos]   = dinv[s] * dinv[d];
}

// gather aggregation: one warp per node, 4-way unrolled edge loop (MLP=4)
__global__ void gather_kernel(const float* __restrict__ h,
                              const int* __restrict__ off, const int* __restrict__ degi,
                              const int* __restrict__ csrc, const float* __restrict__ cw,
                              const float* __restrict__ dinv2, const float* __restrict__ bias,
                              float* __restrict__ slice, int n)
{
    int t = blockIdx.x * blockDim.x + threadIdx.x;
    int w = t >> 5;
    if (w >= n) return;
    int lane = t & 31;
    int c = lane << 2;
    const float4 hv = *reinterpret_cast<const float4*>(h + (size_t)w * DD + c);
    const float4 bb = *reinterpret_cast<const float4*>(bias + c);
    float d2 = dinv2[w];
    float4 acc = make_float4(hv.x * d2 + bb.x, hv.y * d2 + bb.y,
                             hv.z * d2 + bb.z, hv.w * d2 + bb.w);
    int j   = off[w];
    int end = j + degi[w];
    for (; j + 4 <= end; j += 4) {
        int   i0 = __ldg(csrc + j),     i1 = __ldg(csrc + j + 1);
        int   i2 = __ldg(csrc + j + 2), i3 = __ldg(csrc + j + 3);
        float w0 = __ldg(cw + j),       w1 = __ldg(cw + j + 1);
        float w2 = __ldg(cw + j + 2),   w3 = __ldg(cw + j + 3);
        float4 v0 = *reinterpret_cast<const float4*>(h + (size_t)i0 * DD + c);
        float4 v1 = *reinterpret_cast<const float4*>(h + (size_t)i1 * DD + c);
        float4 v2 = *reinterpret_cast<const float4*>(h + (size_t)i2 * DD + c);
        float4 v3 = *reinterpret_cast<const float4*>(h + (size_t)i3 * DD + c);
        acc.x += w0 * v0.x + w1 * v1.x + w2 * v2.x + w3 * v3.x;
        acc.y += w0 * v0.y + w1 * v1.y + w2 * v2.y + w3 * v3.y;
        acc.z += w0 * v0.z + w1 * v1.z + w2 * v2.z + w3 * v3.z;
        acc.w += w0 * v0.w + w1 * v1.w + w2 * v2.w + w3 * v3.w;
    }
    for (; j < end; ++j) {
        int s    = __ldg(csrc + j);
        float wt = __ldg(cw + j);
        float4 v = *reinterpret_cast<const float4*>(h + (size_t)s * DD + c);
        acc.x += wt * v.x; acc.y += wt * v.y;
        acc.z += wt * v.z; acc.w += wt * v.w;
    }
    *reinterpret_cast<float4*>(slice + (size_t)w * EDIM + c) = acc;
}

__global__ void expmap_proj_kernel(float* __restrict__ p, int rows)
{
    int t = blockIdx.x * blockDim.x + threadIdx.x;
    int w = t >> 5;
    if (w >= rows) return;
    int lane = t & 31;
    float* r = p + (size_t)w * EDIM;
    float4 v0 = *reinterpret_cast<const float4*>(r + lane * 4);
    float4 v1 = *reinterpret_cast<const float4*>(r + lane * 4 + 128);
    float4 v2 = *reinterpret_cast<const float4*>(r + lane * 4 + 256);
    float ss = v0.x*v0.x + v0.y*v0.y + v0.z*v0.z + v0.w*v0.w
             + v1.x*v1.x + v1.y*v1.y + v1.z*v1.z + v1.w*v1.w
             + v2.x*v2.x + v2.y*v2.y + v2.z*v2.z + v2.w*v2.w;
#pragma unroll
    for (int o = 16; o; o >>= 1) ss += __shfl_xor_sync(0xffffffffu, ss, o);
    float nrm = sqrtf(ss);
    float n1  = fmaxf(nrm, 1e-15f);
    float s   = tanhf(n1) / n1;
    float yn  = s * nrm;
    const float maxn = 1.0f - 4e-3f;
    if (yn > maxn) s = s * maxn / yn;
    v0.x*=s; v0.y*=s; v0.z*=s; v0.w*=s;
    v1.x*=s; v1.y*=s; v1.z*=s; v1.w*=s;
    v2.x*=s; v2.y*=s; v2.z*=s; v2.w*=s;
    *reinterpret_cast<float4*>(r + lane * 4      ) = v0;
    *reinterpret_cast<float4*>(r + lane * 4 + 128) = v1;
    *reinterpret_cast<float4*>(r + lane * 4 + 256) = v2;
}

// pool of relu(nf): writes 384 cols at out[g*ldo + t]
__global__ void pool_kernel(const float* __restrict__ nf, const int* __restrict__ batch,
                            float* __restrict__ out, int ldo, int n)
{
    int g = blockIdx.x;
    int t = threadIdx.x;
    int lo = 0, hi = n;
    while (lo < hi) { int m = (lo + hi) >> 1; if (batch[m] < g) lo = m + 1; else hi = m; }
    int s0 = lo;
    hi = n;
    while (lo < hi) { int m = (lo + hi) >> 1; if (batch[m] < g + 1) lo = m + 1; else hi = m; }
    int s1 = lo;
    float acc = 0.0f;
    for (int i = s0; i < s1; i++) acc += fmaxf(nf[(size_t)i * EDIM + t], 0.0f);
    out[(size_t)g * ldo + t] = acc;
}

// ---------------------------------------------------------------------------
// fp32 SGEMM (tiny graph-level GEMMs, M=512). flags: 1=RELU, 2=ACCUM
// ---------------------------------------------------------------------------
__global__ void __launch_bounds__(256)
sgemm_kernel(const float* __restrict__ A, int lda,
             const float* __restrict__ B,
             float* __restrict__ C, int ldc,
             int M, int Nc, int K, int flags)
{
    __shared__ float As[16][132];
    __shared__ float Bs[16][128];
    const int tid = threadIdx.x;
    const int bm = blockIdx.x * 128;
    const int bn = blockIdx.y * 128;
    const int tx = tid & 15;
    const int ty = tid >> 4;

    float acc[8][8];
#pragma unroll
    for (int i = 0; i < 8; i++)
#pragma unroll
        for (int j = 0; j < 8; j++) acc[i][j] = 0.0f;

    for (int k0 = 0; k0 < K; k0 += 16) {
#pragma unroll
        for (int it = 0; it < 2; ++it) {
            int idx = tid + it * 256;
            int row = idx >> 2;
            int kc  = (idx & 3) << 2;
            int gr  = bm + row;
            float4 v = make_float4(0.f, 0.f, 0.f, 0.f);
            if (gr < M) v = *reinterpret_cast<const float4*>(A + (size_t)gr * lda + k0 + kc);
            As[kc + 0][row] = v.x; As[kc + 1][row] = v.y;
            As[kc + 2][row] = v.z; As[kc + 3][row] = v.w;
        }
#pragma unroll
        for (int it = 0; it < 2; ++it) {
            int idx = tid + it * 256;
            int kr  = idx >> 5;
            int nc  = (idx & 31) << 2;
            float4 v = *reinterpret_cast<const float4*>(B + (size_t)(k0 + kr) * Nc + bn + nc);
            *reinterpret_cast<float4*>(&Bs[kr][nc]) = v;
        }
        __syncthreads();
#pragma unroll
        for (int k = 0; k < 16; ++k) {
            float a[8], b[8];
#pragma unroll
            for (int i = 0; i < 8; i++) a[i] = As[k][ty * 8 + i];
#pragma unroll
            for (int j = 0; j < 8; j++) b[j] = Bs[k][tx * 8 + j];
#pragma unroll
            for (int i = 0; i < 8; i++)
#pragma unroll
                for (int j = 0; j < 8; j++) acc[i][j] = fmaf(a[i], b[j], acc[i][j]);
        }
        __syncthreads();
    }

#pragma unroll
    for (int i = 0; i < 8; i++) {
        int gr = bm + ty * 8 + i;
        if (gr >= M) break;
#pragma unroll
        for (int j = 0; j < 8; j += 4) {
            int gc = bn + tx * 8 + j;
            float4 r = make_float4(acc[i][j], acc[i][j+1], acc[i][j+2], acc[i][j+3]);
            if (flags & 2) {
                float4 o = *reinterpret_cast<const float4*>(C + (size_t)gr * ldc + gc);
                r.x += o.x; r.y += o.y; r.z += o.z; r.w += o.w;
            }
            if (flags & 1) {
                r.x = fmaxf(r.x, 0.f); r.y = fmaxf(r.y, 0.f);
                r.z = fmaxf(r.z, 0.f); r.w = fmaxf(r.w, 0.f);
            }
            *reinterpret_cast<float4*>(C + (size_t)gr * ldc + gc) = r;
        }
    }
}

// ---------------------------------------------------------------------------
// Host driver
// ---------------------------------------------------------------------------
static inline int ceil_div(int a, int b) { return (a + b - 1) / b; }

extern "C" void kernel_launch(void* const* d_in, const int* in_sizes, int n_in,
                              void* d_out, int out_size)
{
    (void)out_size;
    const float *x = nullptr, *xs = nullptr;
    const int *src = nullptr, *dst = nullptr, *batch = nullptr;
    const float *W[6] = {}; const float *bv[6] = {};
    const float *p147[3] = {}; const float *G1 = nullptr;
    int xi = 0, ei = 0, wi = 0, bi = 0, pi = 0;
    for (int i = 0; i < n_in; i++) {
        int s = in_sizes[i];
        const void* p = d_in[i];
        if (s == NN * FF)          { if (xi == 0) x = (const float*)p; else xs = (const float*)p; xi++; }
        else if (s == EE)          { if (ei == 0) src = (const int*)p; else dst = (const int*)p; ei++; }
        else if (s == NN)          { batch = (const int*)p; }
        else if (s == FF * DD)     { if (wi < 6) W[wi] = (const float*)p; wi++; }
        else if (s == DD)          { if (bi < 6) bv[bi] = (const float*)p; bi++; }
        else if (s == EDIM * EDIM) { if (pi < 3) p147[pi] = (const float*)p; pi++; }
        else if (s == 2 * EDIM * EDIM) { G1 = (const float*)p; }
    }
    const float* P1 = p147[0];
    const float* P2 = p147[1];
    const float* G2 = p147[2];

    float *h, *h2, *nf, *ns, *lms, *lms2, *dinv, *dinv2, *gfs, *ghid, *cw;
    int *degi, *off, *cur, *csrc;
    __nv_bfloat16 *wth, *wtl;
    __half *hidh, *hidl, *hid2h, *hid2l, *p1h, *p1l, *p2h;
    cudaGetSymbolAddress((void**)&h,    g_h);
    cudaGetSymbolAddress((void**)&h2,   g_h2);
    cudaGetSymbolAddress((void**)&nf,   g_nf);
    cudaGetSymbolAddress((void**)&ns,   g_ns);
    cudaGetSymbolAddress((void**)&hidh, g_hidh);
    cudaGetSymbolAddress((void**)&hidl, g_hidl);
    cudaGetSymbolAddress((void**)&hid2h,g_hid2h);
    cudaGetSymbolAddress((void**)&hid2l,g_hid2l);
    cudaGetSymbolAddress((void**)&lms,  g_lms);
    cudaGetSymbolAddress((void**)&lms2, g_lms2);
    cudaGetSymbolAddress((void**)&degi, g_degi);
    cudaGetSymbolAddress((void**)&dinv, g_dinv);
    cudaGetSymbolAddress((void**)&dinv2,g_dinv2);
    cudaGetSymbolAddress((void**)&off,  g_off);
    cudaGetSymbolAddress((void**)&cur,  g_cur);
    cudaGetSymbolAddress((void**)&csrc, g_csrc);
    cudaGetSymbolAddress((void**)&cw,   g_cw);
    cudaGetSymbolAddress((void**)&gfs,  g_gfs);
    cudaGetSymbolAddress((void**)&ghid, g_ghid);
    cudaGetSymbolAddress((void**)&wth,  g_wth);
    cudaGetSymbolAddress((void**)&wtl,  g_wtl);
    cudaGetSymbolAddress((void**)&p1h,  g_p1h);
    cudaGetSymbolAddress((void**)&p1l,  g_p1l);
    cudaGetSymbolAddress((void**)&p2h,  g_p2h);

    cudaFuncSetAttribute(mma_gemm_kernel, cudaFuncAttributeMaxDynamicSharedMemorySize, GEMM_SMEM);
    cudaFuncSetAttribute(hgemm_kernel<0>, cudaFuncAttributeMaxDynamicSharedMemorySize, 5 * ASZ);
    cudaFuncSetAttribute(hgemm_kernel<1>, cudaFuncAttributeMaxDynamicSharedMemorySize, 4 * ASZ);

    float* out = (float*)d_out;
    const int E = EE, N = NN;
    const size_t OFF_P1 = 98304, OFF_P2 = 245760;

    const bool fork = g_hx.ok;
    cudaStream_t s0 = 0;
    cudaStream_t s1 = fork ? g_hx.s1 : (cudaStream_t)0;

    const int gemm_mx = ceil_div(N, 128);
    const int nwarp_threads = N * 32;

    // ---------------- prelude --------------------------------------------
    if (fork) {
        cudaEventRecord(g_hx.eFork, s0);
        cudaStreamWaitEvent(s1, g_hx.eFork, 0);
        zero_degi_kernel<<<ceil_div(N, 256), 256, 0, s1>>>(degi, N);
        degi_kernel<<<ceil_div(E, 256), 256, 0, s1>>>(dst, degi, E);
        scandinv_kernel<<<1, 1024, 0, s1>>>(degi, off, cur, dinv, dinv2, N);
        place_kernel<<<ceil_div(E, 256), 256, 0, s1>>>(src, dst, dinv, cur, csrc, cw, E);
        cudaEventRecord(g_hx.e2, s1);
        prep_kernel<<<14036, 256, 0, s0>>>(W[0], W[1], W[2], W[3], W[4], W[5], P1, P2,
                                           wth, wtl, p1h, p1l, p2h, x, xs, lms, lms2);
        cudaEventRecord(g_hx.e1, s0);
        mma_gemm_kernel<<<dim3(gemm_mx, 1), 256, GEMM_SMEM, s0>>>(
            x, FF, wth, wtl, DD, h, DD, N, DD, 16, lms);
        cudaStreamWaitEvent(s1, g_hx.e1, 0);
        cudaStreamWaitEvent(s0, g_hx.e2, 0);
    } else {
        zero_degi_kernel<<<ceil_div(N, 256), 256, 0, s0>>>(degi, N);
        degi_kernel<<<ceil_div(E, 256), 256, 0, s0>>>(dst, degi, E);
        scandinv_kernel<<<1, 1024, 0, s0>>>(degi, off, cur, dinv, dinv2, N);
        place_kernel<<<ceil_div(E, 256), 256, 0, s0>>>(src, dst, dinv, cur, csrc, cw, E);
        prep_kernel<<<14036, 256, 0, s0>>>(W[0], W[1], W[2], W[3], W[4], W[5], P1, P2,
                                           wth, wtl, p1h, p1l, p2h, x, xs, lms, lms2);
        mma_gemm_kernel<<<dim3(gemm_mx, 1), 256, GEMM_SMEM, s0>>>(
            x, FF, wth, wtl, DD, h, DD, N, DD, 16, lms);
    }

    auto run_branch = [&](cudaStream_t st, const float* xin, const float* lmsb, float* hb,
                          int wbase, const float* const* bb, float* nbuf, float* gpool,
                          bool skipFirstGemm) {
        const float* in = xin;
        int lda = FF;
        for (int l = 0; l < 3; l++) {
            float* slice = nbuf + l * DD;
            size_t woff = (size_t)(wbase + l) * 16384;
            if (!(l == 0 && skipFirstGemm)) {
                int fl = (l == 0) ? 16 : 8;
                mma_gemm_kernel<<<dim3(gemm_mx, 1), 256, GEMM_SMEM, st>>>(
                    in, lda, wth + woff, wtl + woff, DD,
                    hb, DD, N, DD, fl, lmsb);
            }
            gather_kernel<<<ceil_div(nwarp_threads, 256), 256, 0, st>>>(
                hb, off, degi, csrc, cw, dinv2, bb[l], slice, N);
            in = slice;
            lda = EDIM;
        }
        pool_kernel<<<GG, EDIM, 0, st>>>(nbuf, batch, gpool, GFS_LD, N);
    };

    const float* bf[3]  = {bv[0], bv[1], bv[2]};
    const float* bs_[3] = {bv[3], bv[4], bv[5]};

    const size_t off0 = 0;
    const size_t off1 = (size_t)GG * EDIM;
    const size_t off2 = 2 * (size_t)GG * EDIM;
    const size_t off3 = off2 + (size_t)N * EDIM;
    const size_t off4 = off3 + (size_t)GG * EDIM;

    const int ggrid = ceil_div(GG, 128);
    const int gwarp_threads = GG * 32;
    float* ghid0 = ghid;
    float* ghid1 = ghid + (size_t)GG * EDIM;
    float* ghid3 = ghid + 2 * (size_t)GG * EDIM;
    float* gf = gfs;           // cols [0,384) of gfs
    float* gs = gfs + EDIM;    // cols [384,768)

    // ---------------- stream s1: structure branch + out4 + out3 ------------
    run_branch(s1, xs, lms2, h2, 3, bs_, ns, gs, false);
    if (fork) cudaEventRecord(g_hx.eGS, s1);

    // out4: P1 (fp16 MODE0), P2 (fp16 MODE1), expmap
    hgemm_kernel<0><<<dim3(gemm_mx, 3), 256, 5 * ASZ, s1>>>(
        ns, nullptr, nullptr, EDIM, p1h, p1l, EDIM,
        nullptr, hid2h, hid2l, EDIM, N, EDIM);
    hgemm_kernel<1><<<dim3(gemm_mx, 3), 256, 4 * ASZ, s1>>>(
        nullptr, hid2h, hid2l, EDIM, p2h, nullptr, EDIM,
        out + off4, nullptr, nullptr, EDIM, N, EDIM);
    expmap_proj_kernel<<<ceil_div(nwarp_threads, 256), 256, 0, s1>>>(out + off4, N);

    // out3: mlp(gs, P1, P2)   (gs slice of gfs, lda=768)
    sgemm_kernel<<<dim3(ggrid, 3), 256, 0, s1>>>(gs, GFS_LD, P1, ghid3, EDIM, GG, EDIM, EDIM, 1);
    sgemm_kernel<<<dim3(ggrid, 3), 256, 0, s1>>>(ghid3, EDIM, P2, out + off3, EDIM,
                                                 GG, EDIM, EDIM, 0);
    expmap_proj_kernel<<<ceil_div(gwarp_threads, 256), 256, 0, s1>>>(out + off3, GG);

    // ---------------- stream 0: feature branch --------------------------
    run_branch(s0, x, lms, h, 0, bf, nf, gf, /*skipFirstGemm=*/true);
    if (fork) cudaEventRecord(g_hx.eGF, s0);   // gf pool ready

    // ---------------- s1: out1 (after eGF; record follows in host order) ---
    if (fork) {
        cudaStreamWaitEvent(s1, g_hx.eGF, 0);
        sgemm_kernel<<<dim3(ggrid, 3), 256, 0, s1>>>(gf, GFS_LD, P1, ghid1, EDIM,
                                                     GG, EDIM, EDIM, 1);
        sgemm_kernel<<<dim3(ggrid, 3), 256, 0, s1>>>(ghid1, EDIM, P2, out + off1, EDIM,
                                                     GG, EDIM, EDIM, 0);
        expmap_proj_kernel<<<ceil_div(gwarp_threads, 256), 256, 0, s1>>>(out + off1, GG);
        cudaEventRecord(g_hx.eEnd, s1);
    }

    // ---------------- s0: out2 head + out0 --------------------------------
    hgemm_kernel<0><<<dim3(gemm_mx, 3), 256, 5 * ASZ, s0>>>(
        nf, nullptr, nullptr, EDIM, p1h, p1l, EDIM,
        nullptr, hidh, hidl, EDIM, N, EDIM);
    hgemm_kernel<1><<<dim3(gemm_mx, 3), 256, 4 * ASZ, s0>>>(
        nullptr, hidh, hidl, EDIM, p2h, nullptr, EDIM,
        out + off2, nullptr, nullptr, EDIM, N, EDIM);
    expmap_proj_kernel<<<ceil_div(nwarp_threads, 256), 256, 0, s0>>>(out + off2, N);

    // out0: e( relu(gfs @ G1 [K=768]) @ G2 )  -- needs gs pool from s1
    if (fork) cudaStreamWaitEvent(s0, g_hx.eGS, 0);
    sgemm_kernel<<<dim3(ggrid, 3), 256, 0, s0>>>(gfs, GFS_LD, G1, ghid0, EDIM,
                                                 GG, EDIM, 2 * EDIM, 1);
    sgemm_kernel<<<dim3(ggrid, 3), 256, 0, s0>>>(ghid0, EDIM, G2, out + off0, EDIM,
                                                 GG, EDIM, EDIM, 0);
    expmap_proj_kernel<<<ceil_div(gwarp_threads, 256), 256, 0, s0>>>(out + off0, GG);

    if (!fork) {
        // serial out1 on s0
        sgemm_kernel<<<dim3(ggrid, 3), 256, 0, s0>>>(gf, GFS_LD, P1, ghid1, EDIM,
                                                     GG, EDIM, EDIM, 1);
        sgemm_kernel<<<dim3(ggrid, 3), 256, 0, s0>>>(ghid1, EDIM, P2, out + off1, EDIM,
                                                     GG, EDIM, EDIM, 0);
        expmap_proj_kernel<<<ceil_div(gwarp_threads, 256), 256, 0, s0>>>(out + off1, GG);
    } else {
        cudaStreamWaitEvent(s0, g_hx.eEnd, 0);
    }
}

// round 14
// speedup vs baseline: 1.0466x; 1.0216x over previous
#include <cuda_runtime.h>
#include <cuda_bf16.h>
#include <cuda_fp16.h>
#include <cstdint>
#include <cstddef>

// Problem constants (fixed by the reference)
#define NN 50000
#define EE 600000
#define GG 512
#define FF 128
#define DD 128
#define EDIM 384
#define GFS_LD 768

// ---------------------------------------------------------------------------
// Scratch (device globals -- no allocation allowed in kernel_launch)
// ---------------------------------------------------------------------------
__device__ __align__(16) float g_h   [NN * DD];
__device__ __align__(16) float g_h2  [NN * DD];
__device__ __align__(16) float g_nf  [NN * EDIM];
__device__ __align__(16) float g_ns  [NN * EDIM];
__device__ __align__(16) __half g_hidh [NN * EDIM];
__device__ __align__(16) __half g_hidl [NN * EDIM];
__device__ __align__(16) __half g_hid2h[NN * EDIM];
__device__ __align__(16) __half g_hid2l[NN * EDIM];
__device__ float g_lms [NN];
__device__ float g_lms2[NN];
__device__ int   g_degi[NN];
__device__ float g_dinv[NN];
__device__ float g_dinv2[NN];
__device__ int   g_off [NN];
__device__ int   g_cur [NN];
__device__ int   g_csrc[EE];
__device__ float g_cw  [EE];
__device__ __align__(16) float g_gfs [GG * GFS_LD];    // [gf | gs] concat rows
__device__ __align__(16) float g_ghid[5 * GG * EDIM];  // ghid0 + ghid13 (1024) + out13c (1024)
// transposed + split weights (bf16 hi/lo), [N,K] row-major (GCN)
__device__ __align__(16) __nv_bfloat16 g_wth[393216];
__device__ __align__(16) __nv_bfloat16 g_wtl[393216];
// fp16 head weights, transposed [N,K]: P1 split hi/lo, P2 hi only
__device__ __align__(16) __half g_p1h[147456];
__device__ __align__(16) __half g_p1l[147456];
__device__ __align__(16) __half g_p2h[147456];

// ---------------------------------------------------------------------------
// Static-init stream/event resources
// ---------------------------------------------------------------------------
struct HxStreams {
    cudaStream_t s1 = nullptr;
    cudaEvent_t eFork = nullptr, e1 = nullptr, e2 = nullptr;
    cudaEvent_t eGS = nullptr, eEnd = nullptr;
    bool ok = false;
    HxStreams() {
        ok = (cudaStreamCreateWithFlags(&s1, cudaStreamNonBlocking) == cudaSuccess)
          && (cudaEventCreateWithFlags(&eFork, cudaEventDisableTiming) == cudaSuccess)
          && (cudaEventCreateWithFlags(&e1,   cudaEventDisableTiming) == cudaSuccess)
          && (cudaEventCreateWithFlags(&e2,   cudaEventDisableTiming) == cudaSuccess)
          && (cudaEventCreateWithFlags(&eGS,  cudaEventDisableTiming) == cudaSuccess)
          && (cudaEventCreateWithFlags(&eEnd, cudaEventDisableTiming) == cudaSuccess);
    }
};
static HxStreams g_hx;

// ---------------------------------------------------------------------------
// Helpers
// ---------------------------------------------------------------------------
__device__ __forceinline__ void ldmx4(uint32_t* r, uint32_t addr) {
    asm volatile("ldmatrix.sync.aligned.m8n8.x4.shared.b16 {%0,%1,%2,%3}, [%4];"
                 : "=r"(r[0]), "=r"(r[1]), "=r"(r[2]), "=r"(r[3]) : "r"(addr));
}
__device__ __forceinline__ void ldmx2(uint32_t* r, uint32_t addr) {
    asm volatile("ldmatrix.sync.aligned.m8n8.x2.shared.b16 {%0,%1}, [%2];"
                 : "=r"(r[0]), "=r"(r[1]) : "r"(addr));
}
__device__ __forceinline__ void mma16816(float* d, const uint32_t* a, const uint32_t* b) {
    asm volatile("mma.sync.aligned.m16n8k16.row.col.f32.bf16.bf16.f32 "
                 "{%0,%1,%2,%3}, {%4,%5,%6,%7}, {%8,%9}, {%0,%1,%2,%3};"
                 : "+f"(d[0]), "+f"(d[1]), "+f"(d[2]), "+f"(d[3])
                 : "r"(a[0]), "r"(a[1]), "r"(a[2]), "r"(a[3]), "r"(b[0]), "r"(b[1]));
}
__device__ __forceinline__ void mmaf16(float* d, const uint32_t* a, const uint32_t* b) {
    asm volatile("mma.sync.aligned.m16n8k16.row.col.f32.f16.f16.f32 "
                 "{%0,%1,%2,%3}, {%4,%5,%6,%7}, {%8,%9}, {%0,%1,%2,%3};"
                 : "+f"(d[0]), "+f"(d[1]), "+f"(d[2]), "+f"(d[3])
                 : "r"(a[0]), "r"(a[1]), "r"(a[2]), "r"(a[3]), "r"(b[0]), "r"(b[1]));
}
__device__ __forceinline__ uint32_t smem_u32(const void* p) {
    uint32_t a;
    asm("{ .reg .u64 t; cvta.to.shared.u64 t, %1; cvt.u32.u64 %0, t; }" : "=r"(a) : "l"(p));
    return a;
}
__device__ __forceinline__ void cpa16(uint32_t saddr, const void* gaddr) {
    asm volatile("cp.async.cg.shared.global [%0], [%1], 16;" :: "r"(saddr), "l"(gaddr));
}

// ---------------------------------------------------------------------------
// prep kernel: weight transpose+split (blocks 0..1535), logmap scales after.
// ---------------------------------------------------------------------------
__global__ void prep_kernel(const float* __restrict__ W0, const float* __restrict__ W1,
                            const float* __restrict__ W2, const float* __restrict__ W3,
                            const float* __restrict__ W4, const float* __restrict__ W5,
                            const float* __restrict__ P1, const float* __restrict__ P2,
                            __nv_bfloat16* __restrict__ Th, __nv_bfloat16* __restrict__ Tl,
                            __half* __restrict__ p1h, __half* __restrict__ p1l,
                            __half* __restrict__ p2h,
                            const float* __restrict__ x, const float* __restrict__ xs,
                            float* __restrict__ lms, float* __restrict__ lms2)
{
    int b = blockIdx.x;
    if (b < 1536) {
        int idx = b * 256 + threadIdx.x;
        const float* W; int K, N, li, base; int which = 0;
        if (idx < 98304) {
            int m = idx >> 14; li = idx & 16383;
            const float* ws[6] = {W0, W1, W2, W3, W4, W5};
            W = ws[m]; K = 128; N = 128; base = m << 14;
        } else if (idx < 245760) { W = P1; li = idx - 98304; K = 384; N = 384; base = 98304; which = 1; }
        else                     { W = P2; li = idx - 245760; K = 384; N = 384; base = 245760; which = 2; }
        int k = li / N, n = li % N;
        float v = W[li];
        __nv_bfloat16 h = __float2bfloat16_rn(v);
        Th[base + n * K + k] = h;
        Tl[base + n * K + k] = __float2bfloat16_rn(v - __bfloat162float(h));
        if (which == 1) {
            __half fh = __float2half_rn(v);
            p1h[n * 384 + k] = fh;
            p1l[n * 384 + k] = __float2half_rn(v - __half2float(fh));
        } else if (which == 2) {
            p2h[n * 384 + k] = __float2half_rn(v);
        }
    } else {
        int rb = b - 1536;
        const float* xin = x; float* sout = lms;
        if (rb >= 6250) { rb -= 6250; xin = xs; sout = lms2; }
        int w = rb * 8 + (threadIdx.x >> 5);
        if (w >= NN) return;
        int lane = threadIdx.x & 31;
        const float4 v = *reinterpret_cast<const float4*>(xin + (size_t)w * FF + lane * 4);
        float ss = v.x * v.x + v.y * v.y + v.z * v.z + v.w * v.w;
#pragma unroll
        for (int o = 16; o; o >>= 1) ss += __shfl_xor_sync(0xffffffffu, ss, o);
        if (lane == 0) {
            float nrm = sqrtf(ss);
            float n1  = fmaxf(nrm, 1e-15f);
            float arg = fminf(n1, 1.0f - 1e-15f);
            sout[w] = atanhf(arg) / n1;
        }
    }
}

// ---------------------------------------------------------------------------
// bf16 split-3 GEMM (GCN layers). A fp32 on the fly.
// flags: 8=RELU on A, 16=scale A rows by ascale[].
// ---------------------------------------------------------------------------
#define ROWB 80
#define ASZ (128 * ROWB)
#define GEMM_SMEM (6 * ASZ)

__global__ void __launch_bounds__(256, 2)
mma_gemm_kernel(const float* __restrict__ A, int lda,
                const __nv_bfloat16* __restrict__ Bh, const __nv_bfloat16* __restrict__ Bl,
                int ldb,
                float* __restrict__ C, int ldc,
                int M, int K, int flags,
                const float* __restrict__ ascale)
{
    extern __shared__ __align__(16) char sm[];
    const int tid  = threadIdx.x;
    const int wid  = tid >> 5;
    const int lane = tid & 31;
    const int wm = wid & 1;
    const int wn = wid >> 1;
    const int bm = blockIdx.x * 128;
    const int bn = blockIdx.y * 128;
    const uint32_t sbase = smem_u32(sm);

    int arow[4], akc[4];
#pragma unroll
    for (int it = 0; it < 4; ++it) {
        int idx = tid + it * 256;
        arow[it] = idx >> 3;
        akc[it]  = (idx & 7) << 2;
    }
    int brow[2], bc16[2];
#pragma unroll
    for (int it = 0; it < 2; ++it) {
        int idx = tid + it * 256;
        brow[it] = idx >> 2;
        bc16[it] = (idx & 3) << 4;
    }

    float acc[4][4][4];
#pragma unroll
    for (int i = 0; i < 4; i++)
#pragma unroll
        for (int j = 0; j < 4; j++)
#pragma unroll
            for (int l = 0; l < 4; l++) acc[i][j][l] = 0.0f;

    const int nch = K >> 5;
    float4 fr[4];
    float  asc[4];

#pragma unroll
    for (int it = 0; it < 4; ++it) {
        int gr = bm + arow[it];
        fr[it] = make_float4(0.f, 0.f, 0.f, 0.f);
        asc[it] = 1.0f;
        if (gr < M) {
            fr[it] = *reinterpret_cast<const float4*>(A + (size_t)gr * lda + akc[it]);
            if (flags & 16) asc[it] = ascale[gr];
        }
    }
#pragma unroll
    for (int it = 0; it < 2; ++it) {
        uint32_t so = sbase + 2 * ASZ + brow[it] * ROWB + bc16[it];
        size_t gb = ((size_t)(bn + brow[it]) * ldb) * 2 + bc16[it];
        cpa16(so,       (const char*)Bh + gb);
        cpa16(so + ASZ, (const char*)Bl + gb);
    }
    asm volatile("cp.async.commit_group;" ::: "memory");

    for (int ch = 0; ch < nch; ++ch) {
#pragma unroll
        for (int it = 0; it < 4; ++it) {
            float4 v = fr[it];
            float s = asc[it];
            v.x *= s; v.y *= s; v.z *= s; v.w *= s;
            if (flags & 8) {
                v.x = fmaxf(v.x, 0.f); v.y = fmaxf(v.y, 0.f);
                v.z = fmaxf(v.z, 0.f); v.w = fmaxf(v.w, 0.f);
            }
            __nv_bfloat162 h01 = __floats2bfloat162_rn(v.x, v.y);
            __nv_bfloat162 h23 = __floats2bfloat162_rn(v.z, v.w);
            float2 f01 = __bfloat1622float2(h01);
            float2 f23 = __bfloat1622float2(h23);
            __nv_bfloat162 l01 = __floats2bfloat162_rn(v.x - f01.x, v.y - f01.y);
            __nv_bfloat162 l23 = __floats2bfloat162_rn(v.z - f23.x, v.w - f23.y);
            int off = arow[it] * ROWB + akc[it] * 2;
            uint2 uh, ul;
            uh.x = *reinterpret_cast<uint32_t*>(&h01);
            uh.y = *reinterpret_cast<uint32_t*>(&h23);
            ul.x = *reinterpret_cast<uint32_t*>(&l01);
            ul.y = *reinterpret_cast<uint32_t*>(&l23);
            *reinterpret_cast<uint2*>(sm + off)       = uh;
            *reinterpret_cast<uint2*>(sm + ASZ + off) = ul;
        }
        asm volatile("cp.async.wait_group 0;" ::: "memory");
        __syncthreads();

        if (ch + 1 < nch) {
            int k0 = (ch + 1) << 5;
#pragma unroll
            for (int it = 0; it < 4; ++it) {
                int gr = bm + arow[it];
                fr[it] = make_float4(0.f, 0.f, 0.f, 0.f);
                if (gr < M)
                    fr[it] = *reinterpret_cast<const float4*>(A + (size_t)gr * lda + k0 + akc[it]);
            }
            uint32_t bufo = 2 * ASZ + ((ch + 1) & 1) * (2 * ASZ);
#pragma unroll
            for (int it = 0; it < 2; ++it) {
                uint32_t so = sbase + bufo + brow[it] * ROWB + bc16[it];
                size_t gb = ((size_t)(bn + brow[it]) * ldb + k0) * 2 + bc16[it];
                cpa16(so,       (const char*)Bh + gb);
                cpa16(so + ASZ, (const char*)Bl + gb);
            }
            asm volatile("cp.async.commit_group;" ::: "memory");
        }

        const uint32_t sB = sbase + 2 * ASZ + (ch & 1) * (2 * ASZ);
#pragma unroll
        for (int ks = 0; ks < 2; ++ks) {
            uint32_t bfh[4][2], bfl[4][2];
#pragma unroll
            for (int nt = 0; nt < 4; ++nt) {
                uint32_t off = (uint32_t)((wn * 32 + nt * 8 + (lane & 7)) * ROWB
                                          + (ks * 16 + ((lane >> 3) & 1) * 8) * 2);
                ldmx2(bfh[nt], sB + off);
                ldmx2(bfl[nt], sB + ASZ + off);
            }
#pragma unroll
            for (int mt = 0; mt < 4; ++mt) {
                uint32_t off = (uint32_t)((wm * 64 + mt * 16 + (lane & 15)) * ROWB
                                          + (ks * 16 + ((lane >> 4) & 1) * 8) * 2);
                uint32_t ah[4], al[4];
                ldmx4(ah, sbase + off);
                ldmx4(al, sbase + ASZ + off);
#pragma unroll
                for (int nt = 0; nt < 4; ++nt) {
                    mma16816(acc[mt][nt], ah, bfh[nt]);
                    mma16816(acc[mt][nt], al, bfh[nt]);
                    mma16816(acc[mt][nt], ah, bfl[nt]);
                }
            }
        }
        __syncthreads();
    }

    const int groupID = lane >> 2;
    const int tid4 = lane & 3;
#pragma unroll
    for (int mt = 0; mt < 4; ++mt) {
#pragma unroll
        for (int half = 0; half < 2; ++half) {
            int gr = bm + wm * 64 + mt * 16 + groupID + half * 8;
            if (gr >= M) continue;
#pragma unroll
            for (int nt = 0; nt < 4; ++nt) {
                int gc = bn + wn * 32 + nt * 8 + tid4 * 2;
                float2 r = make_float2(acc[mt][nt][half * 2], acc[mt][nt][half * 2 + 1]);
                *reinterpret_cast<float2*>(C + (size_t)gr * ldc + gc) = r;
            }
        }
    }
}

// ---------------------------------------------------------------------------
// fp16 2-MMA head GEMM (MODE 0: fp32 A + split B -> fp16-split C;
//                       MODE 1: split A + single B -> fp32 C)
// ---------------------------------------------------------------------------
template<int MODE>
__global__ void __launch_bounds__(256, 2)
hgemm_kernel(const float* __restrict__ A,
             const __half* __restrict__ Ah, const __half* __restrict__ Al,
             int lda,
             const __half* __restrict__ Bh, const __half* __restrict__ Bl,
             int ldb,
             float* __restrict__ C,
             __half* __restrict__ Cbh, __half* __restrict__ Cbl,
             int ldc, int M, int K)
{
    extern __shared__ __align__(16) char sm[];
    const int tid  = threadIdx.x;
    const int wid  = tid >> 5;
    const int lane = tid & 31;
    const int wm = wid & 1;
    const int wn = wid >> 1;
    const int bm = blockIdx.x * 128;
    const int bn = blockIdx.y * 128;
    const uint32_t sbase = smem_u32(sm);

    int arow[4], akc[4];
#pragma unroll
    for (int it = 0; it < 4; ++it) {
        int idx = tid + it * 256;
        arow[it] = idx >> 3;
        akc[it]  = (idx & 7) << 2;
    }
    int brow[2], bc16[2];
#pragma unroll
    for (int it = 0; it < 2; ++it) {
        int idx = tid + it * 256;
        brow[it] = idx >> 2;
        bc16[it] = (idx & 3) << 4;
    }

    float acc[4][4][4];
#pragma unroll
    for (int i = 0; i < 4; i++)
#pragma unroll
        for (int j = 0; j < 4; j++)
#pragma unroll
            for (int l = 0; l < 4; l++) acc[i][j][l] = 0.0f;

    const int nch = K >> 5;
    float4 fr[4];
    uint2  urh[4], url[4];

    const uint32_t sB0 = sbase + ((MODE == 0) ? ASZ : 2 * ASZ);
    const uint32_t bstride = (MODE == 0) ? 2 * ASZ : ASZ;

#pragma unroll
    for (int it = 0; it < 4; ++it) {
        int gr = bm + arow[it];
        if (MODE == 0) {
            fr[it] = make_float4(0.f, 0.f, 0.f, 0.f);
            if (gr < M) fr[it] = *reinterpret_cast<const float4*>(A + (size_t)gr * lda + akc[it]);
        } else {
            urh[it] = make_uint2(0, 0); url[it] = make_uint2(0, 0);
            if (gr < M) {
                urh[it] = *reinterpret_cast<const uint2*>(Ah + (size_t)gr * lda + akc[it]);
                url[it] = *reinterpret_cast<const uint2*>(Al + (size_t)gr * lda + akc[it]);
            }
        }
    }
#pragma unroll
    for (int it = 0; it < 2; ++it) {
        uint32_t so = sB0 + brow[it] * ROWB + bc16[it];
        size_t gb = ((size_t)(bn + brow[it]) * ldb) * 2 + bc16[it];
        cpa16(so, (const char*)Bh + gb);
        if (MODE == 0) cpa16(so + ASZ, (const char*)Bl + gb);
    }
    asm volatile("cp.async.commit_group;" ::: "memory");

    for (int ch = 0; ch < nch; ++ch) {
#pragma unroll
        for (int it = 0; it < 4; ++it) {
            int off = arow[it] * ROWB + akc[it] * 2;
            if (MODE == 0) {
                float4 v = fr[it];
                v.x = fmaxf(v.x, 0.f); v.y = fmaxf(v.y, 0.f);
                v.z = fmaxf(v.z, 0.f); v.w = fmaxf(v.w, 0.f);
                __half2 h01 = __float22half2_rn(make_float2(v.x, v.y));
                __half2 h23 = __float22half2_rn(make_float2(v.z, v.w));
                uint2 u;
                u.x = *reinterpret_cast<uint32_t*>(&h01);
                u.y = *reinterpret_cast<uint32_t*>(&h23);
                *reinterpret_cast<uint2*>(sm + off) = u;
            } else {
                *reinterpret_cast<uint2*>(sm + off)       = urh[it];
                *reinterpret_cast<uint2*>(sm + ASZ + off) = url[it];
            }
        }
        asm volatile("cp.async.wait_group 0;" ::: "memory");
        __syncthreads();

        if (ch + 1 < nch) {
            int k0 = (ch + 1) << 5;
#pragma unroll
            for (int it = 0; it < 4; ++it) {
                int gr = bm + arow[it];
                if (MODE == 0) {
                    fr[it] = make_float4(0.f, 0.f, 0.f, 0.f);
                    if (gr < M)
                        fr[it] = *reinterpret_cast<const float4*>(A + (size_t)gr * lda + k0 + akc[it]);
                } else {
                    urh[it] = make_uint2(0, 0); url[it] = make_uint2(0, 0);
                    if (gr < M) {
                        urh[it] = *reinterpret_cast<const uint2*>(Ah + (size_t)gr * lda + k0 + akc[it]);
                        url[it] = *reinterpret_cast<const uint2*>(Al + (size_t)gr * lda + k0 + akc[it]);
                    }
                }
            }
            uint32_t so0 = sB0 + ((ch + 1) & 1) * bstride;
#pragma unroll
            for (int it = 0; it < 2; ++it) {
                uint32_t so = so0 + brow[it] * ROWB + bc16[it];
                size_t gb = ((size_t)(bn + brow[it]) * ldb + k0) * 2 + bc16[it];
                cpa16(so, (const char*)Bh + gb);
                if (MODE == 0) cpa16(so + ASZ, (const char*)Bl + gb);
            }
            asm volatile("cp.async.commit_group;" ::: "memory");
        }

        const uint32_t sB = sB0 + (ch & 1) * bstride;
#pragma unroll
        for (int ks = 0; ks < 2; ++ks) {
            uint32_t bfh[4][2], bfl[4][2];
#pragma unroll
            for (int nt = 0; nt < 4; ++nt) {
                uint32_t off = (uint32_t)((wn * 32 + nt * 8 + (lane & 7)) * ROWB
                                          + (ks * 16 + ((lane >> 3) & 1) * 8) * 2);
                ldmx2(bfh[nt], sB + off);
                if (MODE == 0) ldmx2(bfl[nt], sB + ASZ + off);
            }
#pragma unroll
            for (int mt = 0; mt < 4; ++mt) {
                uint32_t off = (uint32_t)((wm * 64 + mt * 16 + (lane & 15)) * ROWB
                                          + (ks * 16 + ((lane >> 4) & 1) * 8) * 2);
                uint32_t a0[4], a1[4];
                ldmx4(a0, sbase + off);
                if (MODE == 1) ldmx4(a1, sbase + ASZ + off);
#pragma unroll
                for (int nt = 0; nt < 4; ++nt) {
                    if (MODE == 0) {
                        mmaf16(acc[mt][nt], a0, bfh[nt]);
                        mmaf16(acc[mt][nt], a0, bfl[nt]);
                    } else {
                        mmaf16(acc[mt][nt], a0, bfh[nt]);
                        mmaf16(acc[mt][nt], a1, bfh[nt]);
                    }
                }
            }
        }
        __syncthreads();
    }

    const int groupID = lane >> 2;
    const int tid4 = lane & 3;
#pragma unroll
    for (int mt = 0; mt < 4; ++mt) {
#pragma unroll
        for (int half = 0; half < 2; ++half) {
            int gr = bm + wm * 64 + mt * 16 + groupID + half * 8;
            if (gr >= M) continue;
#pragma unroll
            for (int nt = 0; nt < 4; ++nt) {
                int gc = bn + wn * 32 + nt * 8 + tid4 * 2;
                float2 r = make_float2(acc[mt][nt][half * 2], acc[mt][nt][half * 2 + 1]);
                if (MODE == 0) {
                    r.x = fmaxf(r.x, 0.f); r.y = fmaxf(r.y, 0.f);
                    __half2 hh = __float22half2_rn(r);
                    float2 fh = __half22float2(hh);
                    __half2 hl = __float22half2_rn(make_float2(r.x - fh.x, r.y - fh.y));
                    *reinterpret_cast<__half2*>(Cbh + (size_t)gr * ldc + gc) = hh;
                    *reinterpret_cast<__half2*>(Cbl + (size_t)gr * ldc + gc) = hl;
                } else {
                    *reinterpret_cast<float2*>(C + (size_t)gr * ldc + gc) = r;
                }
            }
        }
    }
}

// ---------------------------------------------------------------------------
// CSR build + graph kernels
// ---------------------------------------------------------------------------
__global__ void zero_degi_kernel(int* __restrict__ degi, int n)
{
    int t = blockIdx.x * blockDim.x + threadIdx.x;
    if (t < n) degi[t] = 0;
}

__global__ void degi_kernel(const int* __restrict__ dst, int* __restrict__ degi, int e)
{
    int t = blockIdx.x * blockDim.x + threadIdx.x;
    if (t < e) atomicAdd(&degi[dst[t]], 1);
}

__global__ void __launch_bounds__(1024)
scandinv_kernel(const int* __restrict__ degi, int* __restrict__ off,
                int* __restrict__ cur, float* __restrict__ dinv,
                float* __restrict__ dinv2, int n)
{
    __shared__ int warpsum[32];
    __shared__ int carry;
    const int tid = threadIdx.x;
    const int lane = tid & 31;
    const int wrp = tid >> 5;
    if (tid == 0) carry = 0;
    __syncthreads();
    for (int base = 0; base < n; base += 1024) {
        int i = base + tid;
        int v = (i < n) ? degi[i] : 0;
        if (i < n) {
            float d  = (float)v + 1.0f;
            float di = 1.0f / sqrtf(d);
            dinv[i]  = di;
            dinv2[i] = di * di;
        }
        int x = v;
#pragma unroll
        for (int o = 1; o < 32; o <<= 1) {
            int y = __shfl_up_sync(0xffffffffu, x, o);
            if (lane >= o) x += y;
        }
        if (lane == 31) warpsum[wrp] = x;
        __syncthreads();
        if (tid < 32) {
            int s = warpsum[tid];
#pragma unroll
            for (int o = 1; o < 32; o <<= 1) {
                int y = __shfl_up_sync(0xffffffffu, s, o);
                if (tid >= o) s += y;
            }
            warpsum[tid] = s;
        }
        __syncthreads();
        int incl = x + (wrp ? warpsum[wrp - 1] : 0);
        int excl = incl - v + carry;
        if (i < n) { off[i] = excl; cur[i] = excl; }
        __syncthreads();
        if (tid == 1023) carry += incl;
        __syncthreads();
    }
}

__global__ void place_kernel(const int* __restrict__ src, const int* __restrict__ dst,
                             const float* __restrict__ dinv,
                             int* __restrict__ cur,
                             int* __restrict__ csrc, float* __restrict__ cw, int e)
{
    int t = blockIdx.x * blockDim.x + threadIdx.x;
    if (t >= e) return;
    int s = src[t], d = dst[t];
    int pos = atomicAdd(&cur[d], 1);
    csrc[pos] = s;
    cw[pos]   = dinv[s] * dinv[d];
}

// gather aggregation: one warp per node, 4-way unrolled edge loop (MLP=4)
__global__ void gather_kernel(const float* __restrict__ h,
                              const int* __restrict__ off, const int* __restrict__ degi,
                              const int* __restrict__ csrc, const float* __restrict__ cw,
                              const float* __restrict__ dinv2, const float* __restrict__ bias,
                              float* __restrict__ slice, int n)
{
    int t = blockIdx.x * blockDim.x + threadIdx.x;
    int w = t >> 5;
    if (w >= n) return;
    int lane = t & 31;
    int c = lane << 2;
    const float4 hv = *reinterpret_cast<const float4*>(h + (size_t)w * DD + c);
    const float4 bb = *reinterpret_cast<const float4*>(bias + c);
    float d2 = dinv2[w];
    float4 acc = make_float4(hv.x * d2 + bb.x, hv.y * d2 + bb.y,
                             hv.z * d2 + bb.z, hv.w * d2 + bb.w);
    int j   = off[w];
    int end = j + degi[w];
    for (; j + 4 <= end; j += 4) {
        int   i0 = __ldg(csrc + j),     i1 = __ldg(csrc + j + 1);
        int   i2 = __ldg(csrc + j + 2), i3 = __ldg(csrc + j + 3);
        float w0 = __ldg(cw + j),       w1 = __ldg(cw + j + 1);
        float w2 = __ldg(cw + j + 2),   w3 = __ldg(cw + j + 3);
        float4 v0 = *reinterpret_cast<const float4*>(h + (size_t)i0 * DD + c);
        float4 v1 = *reinterpret_cast<const float4*>(h + (size_t)i1 * DD + c);
        float4 v2 = *reinterpret_cast<const float4*>(h + (size_t)i2 * DD + c);
        float4 v3 = *reinterpret_cast<const float4*>(h + (size_t)i3 * DD + c);
        acc.x += w0 * v0.x + w1 * v1.x + w2 * v2.x + w3 * v3.x;
        acc.y += w0 * v0.y + w1 * v1.y + w2 * v2.y + w3 * v3.y;
        acc.z += w0 * v0.z + w1 * v1.z + w2 * v2.z + w3 * v3.z;
        acc.w += w0 * v0.w + w1 * v1.w + w2 * v2.w + w3 * v3.w;
    }
    for (; j < end; ++j) {
        int s    = __ldg(csrc + j);
        float wt = __ldg(cw + j);
        float4 v = *reinterpret_cast<const float4*>(h + (size_t)s * DD + c);
        acc.x += wt * v.x; acc.y += wt * v.y;
        acc.z += wt * v.z; acc.w += wt * v.w;
    }
    *reinterpret_cast<float4*>(slice + (size_t)w * EDIM + c) = acc;
}

__global__ void expmap_proj_kernel(float* __restrict__ p, int rows)
{
    int t = blockIdx.x * blockDim.x + threadIdx.x;
    int w = t >> 5;
    if (w >= rows) return;
    int lane = t & 31;
    float* r = p + (size_t)w * EDIM;
    float4 v0 = *reinterpret_cast<const float4*>(r + lane * 4);
    float4 v1 = *reinterpret_cast<const float4*>(r + lane * 4 + 128);
    float4 v2 = *reinterpret_cast<const float4*>(r + lane * 4 + 256);
    float ss = v0.x*v0.x + v0.y*v0.y + v0.z*v0.z + v0.w*v0.w
             + v1.x*v1.x + v1.y*v1.y + v1.z*v1.z + v1.w*v1.w
             + v2.x*v2.x + v2.y*v2.y + v2.z*v2.z + v2.w*v2.w;
#pragma unroll
    for (int o = 16; o; o >>= 1) ss += __shfl_xor_sync(0xffffffffu, ss, o);
    float nrm = sqrtf(ss);
    float n1  = fmaxf(nrm, 1e-15f);
    float s   = tanhf(n1) / n1;
    float yn  = s * nrm;
    const float maxn = 1.0f - 4e-3f;
    if (yn > maxn) s = s * maxn / yn;
    v0.x*=s; v0.y*=s; v0.z*=s; v0.w*=s;
    v1.x*=s; v1.y*=s; v1.z*=s; v1.w*=s;
    v2.x*=s; v2.y*=s; v2.z*=s; v2.w*=s;
    *reinterpret_cast<float4*>(r + lane * 4      ) = v0;
    *reinterpret_cast<float4*>(r + lane * 4 + 128) = v1;
    *reinterpret_cast<float4*>(r + lane * 4 + 256) = v2;
}

// parity-demux expmap for the combined out1/out3 buffer (1024 rows):
// even row 2g -> out1[g], odd row 2g+1 -> out3[g]
__global__ void expmap13_kernel(const float* __restrict__ pc,
                                float* __restrict__ out1p, float* __restrict__ out3p)
{
    int t = blockIdx.x * blockDim.x + threadIdx.x;
    int w = t >> 5;
    if (w >= 2 * GG) return;
    int lane = t & 31;
    const float* r = pc + (size_t)w * EDIM;
    float4 v0 = *reinterpret_cast<const float4*>(r + lane * 4);
    float4 v1 = *reinterpret_cast<const float4*>(r + lane * 4 + 128);
    float4 v2 = *reinterpret_cast<const float4*>(r + lane * 4 + 256);
    float ss = v0.x*v0.x + v0.y*v0.y + v0.z*v0.z + v0.w*v0.w
             + v1.x*v1.x + v1.y*v1.y + v1.z*v1.z + v1.w*v1.w
             + v2.x*v2.x + v2.y*v2.y + v2.z*v2.z + v2.w*v2.w;
#pragma unroll
    for (int o = 16; o; o >>= 1) ss += __shfl_xor_sync(0xffffffffu, ss, o);
    float nrm = sqrtf(ss);
    float n1  = fmaxf(nrm, 1e-15f);
    float s   = tanhf(n1) / n1;
    float yn  = s * nrm;
    const float maxn = 1.0f - 4e-3f;
    if (yn > maxn) s = s * maxn / yn;
    v0.x*=s; v0.y*=s; v0.z*=s; v0.w*=s;
    v1.x*=s; v1.y*=s; v1.z*=s; v1.w*=s;
    v2.x*=s; v2.y*=s; v2.z*=s; v2.w*=s;
    float* o = (w & 1) ? out3p + (size_t)(w >> 1) * EDIM
                       : out1p + (size_t)(w >> 1) * EDIM;
    *reinterpret_cast<float4*>(o + lane * 4      ) = v0;
    *reinterpret_cast<float4*>(o + lane * 4 + 128) = v1;
    *reinterpret_cast<float4*>(o + lane * 4 + 256) = v2;
}

// pool of relu(nf): writes 384 cols at out[g*ldo + t]
__global__ void pool_kernel(const float* __restrict__ nf, const int* __restrict__ batch,
                            float* __restrict__ out, int ldo, int n)
{
    int g = blockIdx.x;
    int t = threadIdx.x;
    int lo = 0, hi = n;
    while (lo < hi) { int m = (lo + hi) >> 1; if (batch[m] < g) lo = m + 1; else hi = m; }
    int s0 = lo;
    hi = n;
    while (lo < hi) { int m = (lo + hi) >> 1; if (batch[m] < g + 1) lo = m + 1; else hi = m; }
    int s1 = lo;
    float acc = 0.0f;
    for (int i = s0; i < s1; i++) acc += fmaxf(nf[(size_t)i * EDIM + t], 0.0f);
    out[(size_t)g * ldo + t] = acc;
}

// ---------------------------------------------------------------------------
// fp32 SGEMM (tiny graph-level GEMMs). flags: 1=RELU, 2=ACCUM
// ---------------------------------------------------------------------------
__global__ void __launch_bounds__(256)
sgemm_kernel(const float* __restrict__ A, int lda,
             const float* __restrict__ B,
             float* __restrict__ C, int ldc,
             int M, int Nc, int K, int flags)
{
    __shared__ float As[16][132];
    __shared__ float Bs[16][128];
    const int tid = threadIdx.x;
    const int bm = blockIdx.x * 128;
    const int bn = blockIdx.y * 128;
    const int tx = tid & 15;
    const int ty = tid >> 4;

    float acc[8][8];
#pragma unroll
    for (int i = 0; i < 8; i++)
#pragma unroll
        for (int j = 0; j < 8; j++) acc[i][j] = 0.0f;

    for (int k0 = 0; k0 < K; k0 += 16) {
#pragma unroll
        for (int it = 0; it < 2; ++it) {
            int idx = tid + it * 256;
            int row = idx >> 2;
            int kc  = (idx & 3) << 2;
            int gr  = bm + row;
            float4 v = make_float4(0.f, 0.f, 0.f, 0.f);
            if (gr < M) v = *reinterpret_cast<const float4*>(A + (size_t)gr * lda + k0 + kc);
            As[kc + 0][row] = v.x; As[kc + 1][row] = v.y;
            As[kc + 2][row] = v.z; As[kc + 3][row] = v.w;
        }
#pragma unroll
        for (int it = 0; it < 2; ++it) {
            int idx = tid + it * 256;
            int kr  = idx >> 5;
            int nc  = (idx & 31) << 2;
            float4 v = *reinterpret_cast<const float4*>(B + (size_t)(k0 + kr) * Nc + bn + nc);
            *reinterpret_cast<float4*>(&Bs[kr][nc]) = v;
        }
        __syncthreads();
#pragma unroll
        for (int k = 0; k < 16; ++k) {
            float a[8], b[8];
#pragma unroll
            for (int i = 0; i < 8; i++) a[i] = As[k][ty * 8 + i];
#pragma unroll
            for (int j = 0; j < 8; j++) b[j] = Bs[k][tx * 8 + j];
#pragma unroll
            for (int i = 0; i < 8; i++)
#pragma unroll
                for (int j = 0; j < 8; j++) acc[i][j] = fmaf(a[i], b[j], acc[i][j]);
        }
        __syncthreads();
    }

#pragma unroll
    for (int i = 0; i < 8; i++) {
        int gr = bm + ty * 8 + i;
        if (gr >= M) break;
#pragma unroll
        for (int j = 0; j < 8; j += 4) {
            int gc = bn + tx * 8 + j;
            float4 r = make_float4(acc[i][j], acc[i][j+1], acc[i][j+2], acc[i][j+3]);
            if (flags & 2) {
                float4 o = *reinterpret_cast<const float4*>(C + (size_t)gr * ldc + gc);
                r.x += o.x; r.y += o.y; r.z += o.z; r.w += o.w;
            }
            if (flags & 1) {
                r.x = fmaxf(r.x, 0.f); r.y = fmaxf(r.y, 0.f);
                r.z = fmaxf(r.z, 0.f); r.w = fmaxf(r.w, 0.f);
            }
            *reinterpret_cast<float4*>(C + (size_t)gr * ldc + gc) = r;
        }
    }
}

// ---------------------------------------------------------------------------
// Host driver
// ---------------------------------------------------------------------------
static inline int ceil_div(int a, int b) { return (a + b - 1) / b; }

extern "C" void kernel_launch(void* const* d_in, const int* in_sizes, int n_in,
                              void* d_out, int out_size)
{
    (void)out_size;
    const float *x = nullptr, *xs = nullptr;
    const int *src = nullptr, *dst = nullptr, *batch = nullptr;
    const float *W[6] = {}; const float *bv[6] = {};
    const float *p147[3] = {}; const float *G1 = nullptr;
    int xi = 0, ei = 0, wi = 0, bi = 0, pi = 0;
    for (int i = 0; i < n_in; i++) {
        int s = in_sizes[i];
        const void* p = d_in[i];
        if (s == NN * FF)          { if (xi == 0) x = (const float*)p; else xs = (const float*)p; xi++; }
        else if (s == EE)          { if (ei == 0) src = (const int*)p; else dst = (const int*)p; ei++; }
        else if (s == NN)          { batch = (const int*)p; }
        else if (s == FF * DD)     { if (wi < 6) W[wi] = (const float*)p; wi++; }
        else if (s == DD)          { if (bi < 6) bv[bi] = (const float*)p; bi++; }
        else if (s == EDIM * EDIM) { if (pi < 3) p147[pi] = (const float*)p; pi++; }
        else if (s == 2 * EDIM * EDIM) { G1 = (const float*)p; }
    }
    const float* P1 = p147[0];
    const float* P2 = p147[1];
    const float* G2 = p147[2];

    float *h, *h2, *nf, *ns, *lms, *lms2, *dinv, *dinv2, *gfs, *ghid, *cw;
    int *degi, *off, *cur, *csrc;
    __nv_bfloat16 *wth, *wtl;
    __half *hidh, *hidl, *hid2h, *hid2l, *p1h, *p1l, *p2h;
    cudaGetSymbolAddress((void**)&h,    g_h);
    cudaGetSymbolAddress((void**)&h2,   g_h2);
    cudaGetSymbolAddress((void**)&nf,   g_nf);
    cudaGetSymbolAddress((void**)&ns,   g_ns);
    cudaGetSymbolAddress((void**)&hidh, g_hidh);
    cudaGetSymbolAddress((void**)&hidl, g_hidl);
    cudaGetSymbolAddress((void**)&hid2h,g_hid2h);
    cudaGetSymbolAddress((void**)&hid2l,g_hid2l);
    cudaGetSymbolAddress((void**)&lms,  g_lms);
    cudaGetSymbolAddress((void**)&lms2, g_lms2);
    cudaGetSymbolAddress((void**)&degi, g_degi);
    cudaGetSymbolAddress((void**)&dinv, g_dinv);
    cudaGetSymbolAddress((void**)&dinv2,g_dinv2);
    cudaGetSymbolAddress((void**)&off,  g_off);
    cudaGetSymbolAddress((void**)&cur,  g_cur);
    cudaGetSymbolAddress((void**)&csrc, g_csrc);
    cudaGetSymbolAddress((void**)&cw,   g_cw);
    cudaGetSymbolAddress((void**)&gfs,  g_gfs);
    cudaGetSymbolAddress((void**)&ghid, g_ghid);
    cudaGetSymbolAddress((void**)&wth,  g_wth);
    cudaGetSymbolAddress((void**)&wtl,  g_wtl);
    cudaGetSymbolAddress((void**)&p1h,  g_p1h);
    cudaGetSymbolAddress((void**)&p1l,  g_p1l);
    cudaGetSymbolAddress((void**)&p2h,  g_p2h);

    cudaFuncSetAttribute(mma_gemm_kernel, cudaFuncAttributeMaxDynamicSharedMemorySize, GEMM_SMEM);
    cudaFuncSetAttribute(hgemm_kernel<0>, cudaFuncAttributeMaxDynamicSharedMemorySize, 5 * ASZ);
    cudaFuncSetAttribute(hgemm_kernel<1>, cudaFuncAttributeMaxDynamicSharedMemorySize, 4 * ASZ);

    float* out = (float*)d_out;
    const int E = EE, N = NN;

    const bool fork = g_hx.ok;
    cudaStream_t s0 = 0;
    cudaStream_t s1 = fork ? g_hx.s1 : (cudaStream_t)0;

    const int gemm_mx = ceil_div(N, 128);
    const int nwarp_threads = N * 32;

    // ---------------- prelude --------------------------------------------
    if (fork) {
        cudaEventRecord(g_hx.eFork, s0);
        cudaStreamWaitEvent(s1, g_hx.eFork, 0);
        zero_degi_kernel<<<ceil_div(N, 256), 256, 0, s1>>>(degi, N);
        degi_kernel<<<ceil_div(E, 256), 256, 0, s1>>>(dst, degi, E);
        scandinv_kernel<<<1, 1024, 0, s1>>>(degi, off, cur, dinv, dinv2, N);
        place_kernel<<<ceil_div(E, 256), 256, 0, s1>>>(src, dst, dinv, cur, csrc, cw, E);
        cudaEventRecord(g_hx.e2, s1);
        prep_kernel<<<14036, 256, 0, s0>>>(W[0], W[1], W[2], W[3], W[4], W[5], P1, P2,
                                           wth, wtl, p1h, p1l, p2h, x, xs, lms, lms2);
        cudaEventRecord(g_hx.e1, s0);
        mma_gemm_kernel<<<dim3(gemm_mx, 1), 256, GEMM_SMEM, s0>>>(
            x, FF, wth, wtl, DD, h, DD, N, DD, 16, lms);
        cudaStreamWaitEvent(s1, g_hx.e1, 0);
        cudaStreamWaitEvent(s0, g_hx.e2, 0);
    } else {
        zero_degi_kernel<<<ceil_div(N, 256), 256, 0, s0>>>(degi, N);
        degi_kernel<<<ceil_div(E, 256), 256, 0, s0>>>(dst, degi, E);
        scandinv_kernel<<<1, 1024, 0, s0>>>(degi, off, cur, dinv, dinv2, N);
        place_kernel<<<ceil_div(E, 256), 256, 0, s0>>>(src, dst, dinv, cur, csrc, cw, E);
        prep_kernel<<<14036, 256, 0, s0>>>(W[0], W[1], W[2], W[3], W[4], W[5], P1, P2,
                                           wth, wtl, p1h, p1l, p2h, x, xs, lms, lms2);
        mma_gemm_kernel<<<dim3(gemm_mx, 1), 256, GEMM_SMEM, s0>>>(
            x, FF, wth, wtl, DD, h, DD, N, DD, 16, lms);
    }

    auto run_branch = [&](cudaStream_t st, const float* xin, const float* lmsb, float* hb,
                          int wbase, const float* const* bb, float* nbuf, float* gpool,
                          bool skipFirstGemm) {
        const float* in = xin;
        int lda = FF;
        for (int l = 0; l < 3; l++) {
            float* slice = nbuf + l * DD;
            size_t woff = (size_t)(wbase + l) * 16384;
            if (!(l == 0 && skipFirstGemm)) {
                int fl = (l == 0) ? 16 : 8;
                mma_gemm_kernel<<<dim3(gemm_mx, 1), 256, GEMM_SMEM, st>>>(
                    in, lda, wth + woff, wtl + woff, DD,
                    hb, DD, N, DD, fl, lmsb);
            }
            gather_kernel<<<ceil_div(nwarp_threads, 256), 256, 0, st>>>(
                hb, off, degi, csrc, cw, dinv2, bb[l], slice, N);
            in = slice;
            lda = EDIM;
        }
        pool_kernel<<<GG, EDIM, 0, st>>>(nbuf, batch, gpool, GFS_LD, N);
    };

    const float* bf[3]  = {bv[0], bv[1], bv[2]};
    const float* bs_[3] = {bv[3], bv[4], bv[5]};

    const size_t off0 = 0;
    const size_t off1 = (size_t)GG * EDIM;
    const size_t off2 = 2 * (size_t)GG * EDIM;
    const size_t off3 = off2 + (size_t)N * EDIM;
    const size_t off4 = off3 + (size_t)GG * EDIM;

    const int ggrid = ceil_div(GG, 128);
    const int gwarp_threads = GG * 32;
    float* ghid0  = ghid;                           // 512 rows  (out0 hidden)
    float* ghid13 = ghid + (size_t)GG * EDIM;       // 1024 rows (combined hidden)
    float* out13c = ghid + 3 * (size_t)GG * EDIM;   // 1024 rows (combined pre-expmap)
    float* gf = gfs;           // cols [0,384) of gfs
    float* gs = gfs + EDIM;    // cols [384,768)

    // ---------------- stream s1: structure branch + out4 (heads only) ------
    run_branch(s1, xs, lms2, h2, 3, bs_, ns, gs, false);
    if (fork) cudaEventRecord(g_hx.eGS, s1);

    // out4: P1 (fp16 MODE0), P2 (fp16 MODE1), expmap
    hgemm_kernel<0><<<dim3(gemm_mx, 3), 256, 5 * ASZ, s1>>>(
        ns, nullptr, nullptr, EDIM, p1h, p1l, EDIM,
        nullptr, hid2h, hid2l, EDIM, N, EDIM);
    hgemm_kernel<1><<<dim3(gemm_mx, 3), 256, 4 * ASZ, s1>>>(
        nullptr, hid2h, hid2l, EDIM, p2h, nullptr, EDIM,
        out + off4, nullptr, nullptr, EDIM, N, EDIM);
    expmap_proj_kernel<<<ceil_div(nwarp_threads, 256), 256, 0, s1>>>(out + off4, N);
    if (fork) cudaEventRecord(g_hx.eEnd, s1);

    // ---------------- stream 0: feature branch + out2 + out13 + out0 -------
    run_branch(s0, x, lms, h, 0, bf, nf, gf, /*skipFirstGemm=*/true);

    // out2 head
    hgemm_kernel<0><<<dim3(gemm_mx, 3), 256, 5 * ASZ, s0>>>(
        nf, nullptr, nullptr, EDIM, p1h, p1l, EDIM,
        nullptr, hidh, hidl, EDIM, N, EDIM);
    hgemm_kernel<1><<<dim3(gemm_mx, 3), 256, 4 * ASZ, s0>>>(
        nullptr, hidh, hidl, EDIM, p2h, nullptr, EDIM,
        out + off2, nullptr, nullptr, EDIM, N, EDIM);
    expmap_proj_kernel<<<ceil_div(nwarp_threads, 256), 256, 0, s0>>>(out + off2, N);

    // combined out1+out3: gfs viewed as [1024 x 384] (lda=384): even=gf, odd=gs
    if (fork) cudaStreamWaitEvent(s0, g_hx.eGS, 0);
    sgemm_kernel<<<dim3(2 * ggrid, 3), 256, 0, s0>>>(gfs, EDIM, P1, ghid13, EDIM,
                                                     2 * GG, EDIM, EDIM, 1);
    sgemm_kernel<<<dim3(2 * ggrid, 3), 256, 0, s0>>>(ghid13, EDIM, P2, out13c, EDIM,
                                                     2 * GG, EDIM, EDIM, 0);
    expmap13_kernel<<<ceil_div(2 * gwarp_threads, 256), 256, 0, s0>>>(
        out13c, out + off1, out + off3);

    // out0: e( relu(gfs @ G1 [K=768]) @ G2 )
    sgemm_kernel<<<dim3(ggrid, 3), 256, 0, s0>>>(gfs, GFS_LD, G1, ghid0, EDIM,
                                                 GG, EDIM, 2 * EDIM, 1);
    sgemm_kernel<<<dim3(ggrid, 3), 256, 0, s0>>>(ghid0, EDIM, G2, out + off0, EDIM,
                                                 GG, EDIM, EDIM, 0);
    expmap_proj_kernel<<<ceil_div(gwarp_threads, 256), 256, 0, s0>>>(out + off0, GG);

    if (fork) cudaStreamWaitEvent(s0, g_hx.eEnd, 0);
}

// round 15
// speedup vs baseline: 1.0600x; 1.0128x over previous
#include <cuda_runtime.h>
#include <cuda_bf16.h>
#include <cuda_fp16.h>
#include <cstdint>
#include <cstddef>

// Problem constants (fixed by the reference)
#define NN 50000
#define EE 600000
#define GG 512
#define FF 128
#define DD 128
#define EDIM 384
#define GFS_LD 768

// ---------------------------------------------------------------------------
// Scratch (device globals -- no allocation allowed in kernel_launch)
// ---------------------------------------------------------------------------
__device__ __align__(16) float g_h   [NN * DD];
__device__ __align__(16) float g_h2  [NN * DD];
__device__ __align__(16) float g_nf  [NN * EDIM];
__device__ __align__(16) float g_ns  [NN * EDIM];
__device__ __align__(16) __half g_hidh [NN * EDIM];
__device__ __align__(16) __half g_hidl [NN * EDIM];
__device__ __align__(16) __half g_hid2h[NN * EDIM];
__device__ __align__(16) __half g_hid2l[NN * EDIM];
__device__ float g_lms [NN];
__device__ float g_lms2[NN];
__device__ int   g_degi[NN];
__device__ float g_dinv[NN];
__device__ float g_dinv2[NN];
__device__ int   g_off [NN];
__device__ int   g_cur [NN];
__device__ int   g_csrc[EE];
__device__ float g_cw  [EE];
__device__ __align__(16) float g_gfs [GG * GFS_LD];   // [gf | gs] concat rows
__device__ __align__(16) float g_ghid[3 * GG * EDIM];
// transposed + split weights (bf16 hi/lo), [N,K] row-major (GCN)
__device__ __align__(16) __nv_bfloat16 g_wth[393216];
__device__ __align__(16) __nv_bfloat16 g_wtl[393216];
// fp16 head weights, transposed [N,K]: P1 split hi/lo, P2 hi only
__device__ __align__(16) __half g_p1h[147456];
__device__ __align__(16) __half g_p1l[147456];
__device__ __align__(16) __half g_p2h[147456];

// ---------------------------------------------------------------------------
// Static-init stream/event resources
// ---------------------------------------------------------------------------
struct HxStreams {
    cudaStream_t s1 = nullptr;
    cudaEvent_t eFork = nullptr, e1 = nullptr, e2 = nullptr;
    cudaEvent_t eGS = nullptr, eGF = nullptr, eEnd = nullptr;
    bool ok = false;
    HxStreams() {
        ok = (cudaStreamCreateWithFlags(&s1, cudaStreamNonBlocking) == cudaSuccess)
          && (cudaEventCreateWithFlags(&eFork, cudaEventDisableTiming) == cudaSuccess)
          && (cudaEventCreateWithFlags(&e1,   cudaEventDisableTiming) == cudaSuccess)
          && (cudaEventCreateWithFlags(&e2,   cudaEventDisableTiming) == cudaSuccess)
          && (cudaEventCreateWithFlags(&eGS,  cudaEventDisableTiming) == cudaSuccess)
          && (cudaEventCreateWithFlags(&eGF,  cudaEventDisableTiming) == cudaSuccess)
          && (cudaEventCreateWithFlags(&eEnd, cudaEventDisableTiming) == cudaSuccess);
    }
};
static HxStreams g_hx;

// ---------------------------------------------------------------------------
// Helpers
// ---------------------------------------------------------------------------
__device__ __forceinline__ void ldmx4(uint32_t* r, uint32_t addr) {
    asm volatile("ldmatrix.sync.aligned.m8n8.x4.shared.b16 {%0,%1,%2,%3}, [%4];"
                 : "=r"(r[0]), "=r"(r[1]), "=r"(r[2]), "=r"(r[3]) : "r"(addr));
}
__device__ __forceinline__ void ldmx2(uint32_t* r, uint32_t addr) {
    asm volatile("ldmatrix.sync.aligned.m8n8.x2.shared.b16 {%0,%1}, [%2];"
                 : "=r"(r[0]), "=r"(r[1]) : "r"(addr));
}
__device__ __forceinline__ void mma16816(float* d, const uint32_t* a, const uint32_t* b) {
    asm volatile("mma.sync.aligned.m16n8k16.row.col.f32.bf16.bf16.f32 "
                 "{%0,%1,%2,%3}, {%4,%5,%6,%7}, {%8,%9}, {%0,%1,%2,%3};"
                 : "+f"(d[0]), "+f"(d[1]), "+f"(d[2]), "+f"(d[3])
                 : "r"(a[0]), "r"(a[1]), "r"(a[2]), "r"(a[3]), "r"(b[0]), "r"(b[1]));
}
__device__ __forceinline__ void mmaf16(float* d, const uint32_t* a, const uint32_t* b) {
    asm volatile("mma.sync.aligned.m16n8k16.row.col.f32.f16.f16.f32 "
                 "{%0,%1,%2,%3}, {%4,%5,%6,%7}, {%8,%9}, {%0,%1,%2,%3};"
                 : "+f"(d[0]), "+f"(d[1]), "+f"(d[2]), "+f"(d[3])
                 : "r"(a[0]), "r"(a[1]), "r"(a[2]), "r"(a[3]), "r"(b[0]), "r"(b[1]));
}
__device__ __forceinline__ uint32_t smem_u32(const void* p) {
    uint32_t a;
    asm("{ .reg .u64 t; cvta.to.shared.u64 t, %1; cvt.u32.u64 %0, t; }" : "=r"(a) : "l"(p));
    return a;
}
__device__ __forceinline__ void cpa16(uint32_t saddr, const void* gaddr) {
    asm volatile("cp.async.cg.shared.global [%0], [%1], 16;" :: "r"(saddr), "l"(gaddr));
}

// ---------------------------------------------------------------------------
// prep kernel: weight transpose+split (blocks 0..1535), logmap scales after.
// ---------------------------------------------------------------------------
__global__ void prep_kernel(const float* __restrict__ W0, const float* __restrict__ W1,
                            const float* __restrict__ W2, const float* __restrict__ W3,
                            const float* __restrict__ W4, const float* __restrict__ W5,
                            const float* __restrict__ P1, const float* __restrict__ P2,
                            __nv_bfloat16* __restrict__ Th, __nv_bfloat16* __restrict__ Tl,
                            __half* __restrict__ p1h, __half* __restrict__ p1l,
                            __half* __restrict__ p2h,
                            const float* __restrict__ x, const float* __restrict__ xs,
                            float* __restrict__ lms, float* __restrict__ lms2)
{
    int b = blockIdx.x;
    if (b < 1536) {
        int idx = b * 256 + threadIdx.x;
        const float* W; int K, N, li, base; int which = 0;
        if (idx < 98304) {
            int m = idx >> 14; li = idx & 16383;
            const float* ws[6] = {W0, W1, W2, W3, W4, W5};
            W = ws[m]; K = 128; N = 128; base = m << 14;
        } else if (idx < 245760) { W = P1; li = idx - 98304; K = 384; N = 384; base = 98304; which = 1; }
        else                     { W = P2; li = idx - 245760; K = 384; N = 384; base = 245760; which = 2; }
        int k = li / N, n = li % N;
        float v = W[li];
        __nv_bfloat16 h = __float2bfloat16_rn(v);
        Th[base + n * K + k] = h;
        Tl[base + n * K + k] = __float2bfloat16_rn(v - __bfloat162float(h));
        if (which == 1) {
            __half fh = __float2half_rn(v);
            p1h[n * 384 + k] = fh;
            p1l[n * 384 + k] = __float2half_rn(v - __half2float(fh));
        } else if (which == 2) {
            p2h[n * 384 + k] = __float2half_rn(v);
        }
    } else {
        int rb = b - 1536;
        const float* xin = x; float* sout = lms;
        if (rb >= 6250) { rb -= 6250; xin = xs; sout = lms2; }
        int w = rb * 8 + (threadIdx.x >> 5);
        if (w >= NN) return;
        int lane = threadIdx.x & 31;
        const float4 v = *reinterpret_cast<const float4*>(xin + (size_t)w * FF + lane * 4);
        float ss = v.x * v.x + v.y * v.y + v.z * v.z + v.w * v.w;
#pragma unroll
        for (int o = 16; o; o >>= 1) ss += __shfl_xor_sync(0xffffffffu, ss, o);
        if (lane == 0) {
            float nrm = sqrtf(ss);
            float n1  = fmaxf(nrm, 1e-15f);
            float arg = fminf(n1, 1.0f - 1e-15f);
            sout[w] = atanhf(arg) / n1;
        }
    }
}

// ---------------------------------------------------------------------------
// bf16 split-3 GEMM (GCN layers). A fp32 on the fly.
// flags: 8=RELU on A, 16=scale A rows by ascale[].
// ---------------------------------------------------------------------------
#define ROWB 80
#define ASZ (128 * ROWB)
#define GEMM_SMEM (6 * ASZ)

__global__ void __launch_bounds__(256, 2)
mma_gemm_kernel(const float* __restrict__ A, int lda,
                const __nv_bfloat16* __restrict__ Bh, const __nv_bfloat16* __restrict__ Bl,
                int ldb,
                float* __restrict__ C, int ldc,
                int M, int K, int flags,
                const float* __restrict__ ascale)
{
    extern __shared__ __align__(16) char sm[];
    const int tid  = threadIdx.x;
    const int wid  = tid >> 5;
    const int lane = tid & 31;
    const int wm = wid & 1;
    const int wn = wid >> 1;
    const int bm = blockIdx.x * 128;
    const int bn = blockIdx.y * 128;
    const uint32_t sbase = smem_u32(sm);

    int arow[4], akc[4];
#pragma unroll
    for (int it = 0; it < 4; ++it) {
        int idx = tid + it * 256;
        arow[it] = idx >> 3;
        akc[it]  = (idx & 7) << 2;
    }
    int brow[2], bc16[2];
#pragma unroll
    for (int it = 0; it < 2; ++it) {
        int idx = tid + it * 256;
        brow[it] = idx >> 2;
        bc16[it] = (idx & 3) << 4;
    }

    float acc[4][4][4];
#pragma unroll
    for (int i = 0; i < 4; i++)
#pragma unroll
        for (int j = 0; j < 4; j++)
#pragma unroll
            for (int l = 0; l < 4; l++) acc[i][j][l] = 0.0f;

    const int nch = K >> 5;
    float4 fr[4];
    float  asc[4];

#pragma unroll
    for (int it = 0; it < 4; ++it) {
        int gr = bm + arow[it];
        fr[it] = make_float4(0.f, 0.f, 0.f, 0.f);
        asc[it] = 1.0f;
        if (gr < M) {
            fr[it] = *reinterpret_cast<const float4*>(A + (size_t)gr * lda + akc[it]);
            if (flags & 16) asc[it] = ascale[gr];
        }
    }
#pragma unroll
    for (int it = 0; it < 2; ++it) {
        uint32_t so = sbase + 2 * ASZ + brow[it] * ROWB + bc16[it];
        size_t gb = ((size_t)(bn + brow[it]) * ldb) * 2 + bc16[it];
        cpa16(so,       (const char*)Bh + gb);
        cpa16(so + ASZ, (const char*)Bl + gb);
    }
    asm volatile("cp.async.commit_group;" ::: "memory");

    for (int ch = 0; ch < nch; ++ch) {
#pragma unroll
        for (int it = 0; it < 4; ++it) {
            float4 v = fr[it];
            float s = asc[it];
            v.x *= s; v.y *= s; v.z *= s; v.w *= s;
            if (flags & 8) {
                v.x = fmaxf(v.x, 0.f); v.y = fmaxf(v.y, 0.f);
                v.z = fmaxf(v.z, 0.f); v.w = fmaxf(v.w, 0.f);
            }
            __nv_bfloat162 h01 = __floats2bfloat162_rn(v.x, v.y);
            __nv_bfloat162 h23 = __floats2bfloat162_rn(v.z, v.w);
            float2 f01 = __bfloat1622float2(h01);
            float2 f23 = __bfloat1622float2(h23);
            __nv_bfloat162 l01 = __floats2bfloat162_rn(v.x - f01.x, v.y - f01.y);
            __nv_bfloat162 l23 = __floats2bfloat162_rn(v.z - f23.x, v.w - f23.y);
            int off = arow[it] * ROWB + akc[it] * 2;
            uint2 uh, ul;
            uh.x = *reinterpret_cast<uint32_t*>(&h01);
            uh.y = *reinterpret_cast<uint32_t*>(&h23);
            ul.x = *reinterpret_cast<uint32_t*>(&l01);
            ul.y = *reinterpret_cast<uint32_t*>(&l23);
            *reinterpret_cast<uint2*>(sm + off)       = uh;
            *reinterpret_cast<uint2*>(sm + ASZ + off) = ul;
        }
        asm volatile("cp.async.wait_group 0;" ::: "memory");
        __syncthreads();

        if (ch + 1 < nch) {
            int k0 = (ch + 1) << 5;
#pragma unroll
            for (int it = 0; it < 4; ++it) {
                int gr = bm + arow[it];
                fr[it] = make_float4(0.f, 0.f, 0.f, 0.f);
                if (gr < M)
                    fr[it] = *reinterpret_cast<const float4*>(A + (size_t)gr * lda + k0 + akc[it]);
            }
            uint32_t bufo = 2 * ASZ + ((ch + 1) & 1) * (2 * ASZ);
#pragma unroll
            for (int it = 0; it < 2; ++it) {
                uint32_t so = sbase + bufo + brow[it] * ROWB + bc16[it];
                size_t gb = ((size_t)(bn + brow[it]) * ldb + k0) * 2 + bc16[it];
                cpa16(so,       (const char*)Bh + gb);
                cpa16(so + ASZ, (const char*)Bl + gb);
            }
            asm volatile("cp.async.commit_group;" ::: "memory");
        }

        const uint32_t sB = sbase + 2 * ASZ + (ch & 1) * (2 * ASZ);
#pragma unroll
        for (int ks = 0; ks < 2; ++ks) {
            uint32_t bfh[4][2], bfl[4][2];
#pragma unroll
            for (int nt = 0; nt < 4; ++nt) {
                uint32_t off = (uint32_t)((wn * 32 + nt * 8 + (lane & 7)) * ROWB
                                          + (ks * 16 + ((lane >> 3) & 1) * 8) * 2);
                ldmx2(bfh[nt], sB + off);
                ldmx2(bfl[nt], sB + ASZ + off);
            }
#pragma unroll
            for (int mt = 0; mt < 4; ++mt) {
                uint32_t off = (uint32_t)((wm * 64 + mt * 16 + (lane & 15)) * ROWB
                                          + (ks * 16 + ((lane >> 4) & 1) * 8) * 2);
                uint32_t ah[4], al[4];
                ldmx4(ah, sbase + off);
                ldmx4(al, sbase + ASZ + off);
#pragma unroll
                for (int nt = 0; nt < 4; ++nt) {
                    mma16816(acc[mt][nt], ah, bfh[nt]);
                    mma16816(acc[mt][nt], al, bfh[nt]);
                    mma16816(acc[mt][nt], ah, bfl[nt]);
                }
            }
        }
        __syncthreads();
    }

    const int groupID = lane >> 2;
    const int tid4 = lane & 3;
#pragma unroll
    for (int mt = 0; mt < 4; ++mt) {
#pragma unroll
        for (int half = 0; half < 2; ++half) {
            int gr = bm + wm * 64 + mt * 16 + groupID + half * 8;
            if (gr >= M) continue;
#pragma unroll
            for (int nt = 0; nt < 4; ++nt) {
                int gc = bn + wn * 32 + nt * 8 + tid4 * 2;
                float2 r = make_float2(acc[mt][nt][half * 2], acc[mt][nt][half * 2 + 1]);
                *reinterpret_cast<float2*>(C + (size_t)gr * ldc + gc) = r;
            }
        }
    }
}

// ---------------------------------------------------------------------------
// fp16 2-MMA head GEMM (MODE 0: fp32 A + split B -> fp16-split C;
//                       MODE 1: split A + single B -> fp32 C)
// ---------------------------------------------------------------------------
template<int MODE>
__global__ void __launch_bounds__(256, 2)
hgemm_kernel(const float* __restrict__ A,
             const __half* __restrict__ Ah, const __half* __restrict__ Al,
             int lda,
             const __half* __restrict__ Bh, const __half* __restrict__ Bl,
             int ldb,
             float* __restrict__ C,
             __half* __restrict__ Cbh, __half* __restrict__ Cbl,
             int ldc, int M, int K)
{
    extern __shared__ __align__(16) char sm[];
    const int tid  = threadIdx.x;
    const int wid  = tid >> 5;
    const int lane = tid & 31;
    const int wm = wid & 1;
    const int wn = wid >> 1;
    const int bm = blockIdx.x * 128;
    const int bn = blockIdx.y * 128;
    const uint32_t sbase = smem_u32(sm);

    int arow[4], akc[4];
#pragma unroll
    for (int it = 0; it < 4; ++it) {
        int idx = tid + it * 256;
        arow[it] = idx >> 3;
        akc[it]  = (idx & 7) << 2;
    }
    int brow[2], bc16[2];
#pragma unroll
    for (int it = 0; it < 2; ++it) {
        int idx = tid + it * 256;
        brow[it] = idx >> 2;
        bc16[it] = (idx & 3) << 4;
    }

    float acc[4][4][4];
#pragma unroll
    for (int i = 0; i < 4; i++)
#pragma unroll
        for (int j = 0; j < 4; j++)
#pragma unroll
            for (int l = 0; l < 4; l++) acc[i][j][l] = 0.0f;

    const int nch = K >> 5;
    float4 fr[4];
    uint2  urh[4], url[4];

    const uint32_t sB0 = sbase + ((MODE == 0) ? ASZ : 2 * ASZ);
    const uint32_t bstride = (MODE == 0) ? 2 * ASZ : ASZ;

#pragma unroll
    for (int it = 0; it < 4; ++it) {
        int gr = bm + arow[it];
        if (MODE == 0) {
            fr[it] = make_float4(0.f, 0.f, 0.f, 0.f);
            if (gr < M) fr[it] = *reinterpret_cast<const float4*>(A + (size_t)gr * lda + akc[it]);
        } else {
            urh[it] = make_uint2(0, 0); url[it] = make_uint2(0, 0);
            if (gr < M) {
                urh[it] = *reinterpret_cast<const uint2*>(Ah + (size_t)gr * lda + akc[it]);
                url[it] = *reinterpret_cast<const uint2*>(Al + (size_t)gr * lda + akc[it]);
            }
        }
    }
#pragma unroll
    for (int it = 0; it < 2; ++it) {
        uint32_t so = sB0 + brow[it] * ROWB + bc16[it];
        size_t gb = ((size_t)(bn + brow[it]) * ldb) * 2 + bc16[it];
        cpa16(so, (const char*)Bh + gb);
        if (MODE == 0) cpa16(so + ASZ, (const char*)Bl + gb);
    }
    asm volatile("cp.async.commit_group;" ::: "memory");

    for (int ch = 0; ch < nch; ++ch) {
#pragma unroll
        for (int it = 0; it < 4; ++it) {
            int off = arow[it] * ROWB + akc[it] * 2;
            if (MODE == 0) {
                float4 v = fr[it];
                v.x = fmaxf(v.x, 0.f); v.y = fmaxf(v.y, 0.f);
                v.z = fmaxf(v.z, 0.f); v.w = fmaxf(v.w, 0.f);
                __half2 h01 = __float22half2_rn(make_float2(v.x, v.y));
                __half2 h23 = __float22half2_rn(make_float2(v.z, v.w));
                uint2 u;
                u.x = *reinterpret_cast<uint32_t*>(&h01);
                u.y = *reinterpret_cast<uint32_t*>(&h23);
                *reinterpret_cast<uint2*>(sm + off) = u;
            } else {
                *reinterpret_cast<uint2*>(sm + off)       = urh[it];
                *reinterpret_cast<uint2*>(sm + ASZ + off) = url[it];
            }
        }
        asm volatile("cp.async.wait_group 0;" ::: "memory");
        __syncthreads();

        if (ch + 1 < nch) {
            int k0 = (ch + 1) << 5;
#pragma unroll
            for (int it = 0; it < 4; ++it) {
                int gr = bm + arow[it];
                if (MODE == 0) {
                    fr[it] = make_float4(0.f, 0.f, 0.f, 0.f);
                    if (gr < M)
                        fr[it] = *reinterpret_cast<const float4*>(A + (size_t)gr * lda + k0 + akc[it]);
                } else {
                    urh[it] = make_uint2(0, 0); url[it] = make_uint2(0, 0);
                    if (gr < M) {
                        urh[it] = *reinterpret_cast<const uint2*>(Ah + (size_t)gr * lda + k0 + akc[it]);
                        url[it] = *reinterpret_cast<const uint2*>(Al + (size_t)gr * lda + k0 + akc[it]);
                    }
                }
            }
            uint32_t so0 = sB0 + ((ch + 1) & 1) * bstride;
#pragma unroll
            for (int it = 0; it < 2; ++it) {
                uint32_t so = so0 + brow[it] * ROWB + bc16[it];
                size_t gb = ((size_t)(bn + brow[it]) * ldb + k0) * 2 + bc16[it];
                cpa16(so, (const char*)Bh + gb);
                if (MODE == 0) cpa16(so + ASZ, (const char*)Bl + gb);
            }
            asm volatile("cp.async.commit_group;" ::: "memory");
        }

        const uint32_t sB = sB0 + (ch & 1) * bstride;
#pragma unroll
        for (int ks = 0; ks < 2; ++ks) {
            uint32_t bfh[4][2], bfl[4][2];
#pragma unroll
            for (int nt = 0; nt < 4; ++nt) {
                uint32_t off = (uint32_t)((wn * 32 + nt * 8 + (lane & 7)) * ROWB
                                          + (ks * 16 + ((lane >> 3) & 1) * 8) * 2);
                ldmx2(bfh[nt], sB + off);
                if (MODE == 0) ldmx2(bfl[nt], sB + ASZ + off);
            }
#pragma unroll
            for (int mt = 0; mt < 4; ++mt) {
                uint32_t off = (uint32_t)((wm * 64 + mt * 16 + (lane & 15)) * ROWB
                                          + (ks * 16 + ((lane >> 4) & 1) * 8) * 2);
                uint32_t a0[4], a1[4];
                ldmx4(a0, sbase + off);
                if (MODE == 1) ldmx4(a1, sbase + ASZ + off);
#pragma unroll
                for (int nt = 0; nt < 4; ++nt) {
                    if (MODE == 0) {
                        mmaf16(acc[mt][nt], a0, bfh[nt]);
                        mmaf16(acc[mt][nt], a0, bfl[nt]);
                    } else {
                        mmaf16(acc[mt][nt], a0, bfh[nt]);
                        mmaf16(acc[mt][nt], a1, bfh[nt]);
                    }
                }
            }
        }
        __syncthreads();
    }

    const int groupID = lane >> 2;
    const int tid4 = lane & 3;
#pragma unroll
    for (int mt = 0; mt < 4; ++mt) {
#pragma unroll
        for (int half = 0; half < 2; ++half) {
            int gr = bm + wm * 64 + mt * 16 + groupID + half * 8;
            if (gr >= M) continue;
#pragma unroll
            for (int nt = 0; nt < 4; ++nt) {
                int gc = bn + wn * 32 + nt * 8 + tid4 * 2;
                float2 r = make_float2(acc[mt][nt][half * 2], acc[mt][nt][half * 2 + 1]);
                if (MODE == 0) {
                    r.x = fmaxf(r.x, 0.f); r.y = fmaxf(r.y, 0.f);
                    __half2 hh = __float22half2_rn(r);
                    float2 fh = __half22float2(hh);
                    __half2 hl = __float22half2_rn(make_float2(r.x - fh.x, r.y - fh.y));
                    *reinterpret_cast<__half2*>(Cbh + (size_t)gr * ldc + gc) = hh;
                    *reinterpret_cast<__half2*>(Cbl + (size_t)gr * ldc + gc) = hl;
                } else {
                    *reinterpret_cast<float2*>(C + (size_t)gr * ldc + gc) = r;
                }
            }
        }
    }
}

// ---------------------------------------------------------------------------
// CSR build + graph kernels
// ---------------------------------------------------------------------------
__global__ void zero_degi_kernel(int* __restrict__ degi, int n)
{
    int t = blockIdx.x * blockDim.x + threadIdx.x;
    if (t < n) degi[t] = 0;
}

__global__ void degi_kernel(const int* __restrict__ dst, int* __restrict__ degi, int e)
{
    int t = blockIdx.x * blockDim.x + threadIdx.x;
    if (t < e) atomicAdd(&degi[dst[t]], 1);
}

__global__ void __launch_bounds__(1024)
scandinv_kernel(const int* __restrict__ degi, int* __restrict__ off,
                int* __restrict__ cur, float* __restrict__ dinv,
                float* __restrict__ dinv2, int n)
{
    __shared__ int warpsum[32];
    __shared__ int carry;
    const int tid = threadIdx.x;
    const int lane = tid & 31;
    const int wrp = tid >> 5;
    if (tid == 0) carry = 0;
    __syncthreads();
    for (int base = 0; base < n; base += 1024) {
        int i = base + tid;
        int v = (i < n) ? degi[i] : 0;
        if (i < n) {
            float d  = (float)v + 1.0f;
            float di = 1.0f / sqrtf(d);
            dinv[i]  = di;
            dinv2[i] = di * di;
        }
        int x = v;
#pragma unroll
        for (int o = 1; o < 32; o <<= 1) {
            int y = __shfl_up_sync(0xffffffffu, x, o);
            if (lane >= o) x += y;
        }
        if (lane == 31) warpsum[wrp] = x;
        __syncthreads();
        if (tid < 32) {
            int s = warpsum[tid];
#pragma unroll
            for (int o = 1; o < 32; o <<= 1) {
                int y = __shfl_up_sync(0xffffffffu, s, o);
                if (tid >= o) s += y;
            }
            warpsum[tid] = s;
        }
        __syncthreads();
        int incl = x + (wrp ? warpsum[wrp - 1] : 0);
        int excl = incl - v + carry;
        if (i < n) { off[i] = excl; cur[i] = excl; }
        __syncthreads();
        if (tid == 1023) carry += incl;
        __syncthreads();
    }
}

__global__ void place_kernel(const int* __restrict__ src, const int* __restrict__ dst,
                             const float* __restrict__ dinv,
                             int* __restrict__ cur,
                             int* __restrict__ csrc, float* __restrict__ cw, int e)
{
    int t = blockIdx.x * blockDim.x + threadIdx.x;
    if (t >= e) return;
    int s = src[t], d = dst[t];
    int pos = atomicAdd(&cur[d], 1);
    csrc[pos] = s;
    cw[pos]   = dinv[s] * dinv[d];
}

// gather aggregation: one warp per node, 8/4/1 unroll ladder (MLP up to 8)
__global__ void gather_kernel(const float* __restrict__ h,
                              const int* __restrict__ off, const int* __restrict__ degi,
                              const int* __restrict__ csrc, const float* __restrict__ cw,
                              const float* __restrict__ dinv2, const float* __restrict__ bias,
                              float* __restrict__ slice, int n)
{
    int t = blockIdx.x * blockDim.x + threadIdx.x;
    int w = t >> 5;
    if (w >= n) return;
    int lane = t & 31;
    int c = lane << 2;
    const float4 hv = *reinterpret_cast<const float4*>(h + (size_t)w * DD + c);
    const float4 bb = *reinterpret_cast<const float4*>(bias + c);
    float d2 = dinv2[w];
    float4 acc = make_float4(hv.x * d2 + bb.x, hv.y * d2 + bb.y,
                             hv.z * d2 + bb.z, hv.w * d2 + bb.w);
    int j   = off[w];
    int end = j + degi[w];
    // 8-wide rung (MLP = 8)
    for (; j + 8 <= end; j += 8) {
        int   ii[8];
        float ww[8];
#pragma unroll
        for (int q = 0; q < 8; ++q) { ii[q] = __ldg(csrc + j + q); ww[q] = __ldg(cw + j + q); }
        float4 vv[8];
#pragma unroll
        for (int q = 0; q < 8; ++q)
            vv[q] = *reinterpret_cast<const float4*>(h + (size_t)ii[q] * DD + c);
#pragma unroll
        for (int q = 0; q < 8; ++q) {
            acc.x += ww[q] * vv[q].x; acc.y += ww[q] * vv[q].y;
            acc.z += ww[q] * vv[q].z; acc.w += ww[q] * vv[q].w;
        }
    }
    // 4-wide rung
    for (; j + 4 <= end; j += 4) {
        int   i0 = __ldg(csrc + j),     i1 = __ldg(csrc + j + 1);
        int   i2 = __ldg(csrc + j + 2), i3 = __ldg(csrc + j + 3);
        float w0 = __ldg(cw + j),       w1 = __ldg(cw + j + 1);
        float w2 = __ldg(cw + j + 2),   w3 = __ldg(cw + j + 3);
        float4 v0 = *reinterpret_cast<const float4*>(h + (size_t)i0 * DD + c);
        float4 v1 = *reinterpret_cast<const float4*>(h + (size_t)i1 * DD + c);
        float4 v2 = *reinterpret_cast<const float4*>(h + (size_t)i2 * DD + c);
        float4 v3 = *reinterpret_cast<const float4*>(h + (size_t)i3 * DD + c);
        acc.x += w0 * v0.x + w1 * v1.x + w2 * v2.x + w3 * v3.x;
        acc.y += w0 * v0.y + w1 * v1.y + w2 * v2.y + w3 * v3.y;
        acc.z += w0 * v0.z + w1 * v1.z + w2 * v2.z + w3 * v3.z;
        acc.w += w0 * v0.w + w1 * v1.w + w2 * v2.w + w3 * v3.w;
    }
    // scalar residue
    for (; j < end; ++j) {
        int s    = __ldg(csrc + j);
        float wt = __ldg(cw + j);
        float4 v = *reinterpret_cast<const float4*>(h + (size_t)s * DD + c);
        acc.x += wt * v.x; acc.y += wt * v.y;
        acc.z += wt * v.z; acc.w += wt * v.w;
    }
    *reinterpret_cast<float4*>(slice + (size_t)w * EDIM + c) = acc;
}

__global__ void expmap_proj_kernel(float* __restrict__ p, int rows)
{
    int t = blockIdx.x * blockDim.x + threadIdx.x;
    int w = t >> 5;
    if (w >= rows) return;
    int lane = t & 31;
    float* r = p + (size_t)w * EDIM;
    float4 v0 = *reinterpret_cast<const float4*>(r + lane * 4);
    float4 v1 = *reinterpret_cast<const float4*>(r + lane * 4 + 128);
    float4 v2 = *reinterpret_cast<const float4*>(r + lane * 4 + 256);
    float ss = v0.x*v0.x + v0.y*v0.y + v0.z*v0.z + v0.w*v0.w
             + v1.x*v1.x + v1.y*v1.y + v1.z*v1.z + v1.w*v1.w
             + v2.x*v2.x + v2.y*v2.y + v2.z*v2.z + v2.w*v2.w;
#pragma unroll
    for (int o = 16; o; o >>= 1) ss += __shfl_xor_sync(0xffffffffu, ss, o);
    float nrm = sqrtf(ss);
    float n1  = fmaxf(nrm, 1e-15f);
    float s   = tanhf(n1) / n1;
    float yn  = s * nrm;
    const float maxn = 1.0f - 4e-3f;
    if (yn > maxn) s = s * maxn / yn;
    v0.x*=s; v0.y*=s; v0.z*=s; v0.w*=s;
    v1.x*=s; v1.y*=s; v1.z*=s; v1.w*=s;
    v2.x*=s; v2.y*=s; v2.z*=s; v2.w*=s;
    *reinterpret_cast<float4*>(r + lane * 4      ) = v0;
    *reinterpret_cast<float4*>(r + lane * 4 + 128) = v1;
    *reinterpret_cast<float4*>(r + lane * 4 + 256) = v2;
}

// pool of relu(nf): writes 384 cols at out[g*ldo + t]
__global__ void pool_kernel(const float* __restrict__ nf, const int* __restrict__ batch,
                            float* __restrict__ out, int ldo, int n)
{
    int g = blockIdx.x;
    int t = threadIdx.x;
    int lo = 0, hi = n;
    while (lo < hi) { int m = (lo + hi) >> 1; if (batch[m] < g) lo = m + 1; else hi = m; }
    int s0 = lo;
    hi = n;
    while (lo < hi) { int m = (lo + hi) >> 1; if (batch[m] < g + 1) lo = m + 1; else hi = m; }
    int s1 = lo;
    float acc = 0.0f;
    for (int i = s0; i < s1; i++) acc += fmaxf(nf[(size_t)i * EDIM + t], 0.0f);
    out[(size_t)g * ldo + t] = acc;
}

// ---------------------------------------------------------------------------
// fp32 SGEMM (tiny graph-level GEMMs, M=512). flags: 1=RELU, 2=ACCUM
// ---------------------------------------------------------------------------
__global__ void __launch_bounds__(256)
sgemm_kernel(const float* __restrict__ A, int lda,
             const float* __restrict__ B,
             float* __restrict__ C, int ldc,
             int M, int Nc, int K, int flags)
{
    __shared__ float As[16][132];
    __shared__ float Bs[16][128];
    const int tid = threadIdx.x;
    const int bm = blockIdx.x * 128;
    const int bn = blockIdx.y * 128;
    const int tx = tid & 15;
    const int ty = tid >> 4;

    float acc[8][8];
#pragma unroll
    for (int i = 0; i < 8; i++)
#pragma unroll
        for (int j = 0; j < 8; j++) acc[i][j] = 0.0f;

    for (int k0 = 0; k0 < K; k0 += 16) {
#pragma unroll
        for (int it = 0; it < 2; ++it) {
            int idx = tid + it * 256;
            int row = idx >> 2;
            int kc  = (idx & 3) << 2;
            int gr  = bm + row;
            float4 v = make_float4(0.f, 0.f, 0.f, 0.f);
            if (gr < M) v = *reinterpret_cast<const float4*>(A + (size_t)gr * lda + k0 + kc);
            As[kc + 0][row] = v.x; As[kc + 1][row] = v.y;
            As[kc + 2][row] = v.z; As[kc + 3][row] = v.w;
        }
#pragma unroll
        for (int it = 0; it < 2; ++it) {
            int idx = tid + it * 256;
            int kr  = idx >> 5;
            int nc  = (idx & 31) << 2;
            float4 v = *reinterpret_cast<const float4*>(B + (size_t)(k0 + kr) * Nc + bn + nc);
            *reinterpret_cast<float4*>(&Bs[kr][nc]) = v;
        }
        __syncthreads();
#pragma unroll
        for (int k = 0; k < 16; ++k) {
            float a[8], b[8];
#pragma unroll
            for (int i = 0; i < 8; i++) a[i] = As[k][ty * 8 + i];
#pragma unroll
            for (int j = 0; j < 8; j++) b[j] = Bs[k][tx * 8 + j];
#pragma unroll
            for (int i = 0; i < 8; i++)
#pragma unroll
                for (int j = 0; j < 8; j++) acc[i][j] = fmaf(a[i], b[j], acc[i][j]);
        }
        __syncthreads();
    }

#pragma unroll
    for (int i = 0; i < 8; i++) {
        int gr = bm + ty * 8 + i;
        if (gr >= M) break;
#pragma unroll
        for (int j = 0; j < 8; j += 4) {
            int gc = bn + tx * 8 + j;
            float4 r = make_float4(acc[i][j], acc[i][j+1], acc[i][j+2], acc[i][j+3]);
            if (flags & 2) {
                float4 o = *reinterpret_cast<const float4*>(C + (size_t)gr * ldc + gc);
                r.x += o.x; r.y += o.y; r.z += o.z; r.w += o.w;
            }
            if (flags & 1) {
                r.x = fmaxf(r.x, 0.f); r.y = fmaxf(r.y, 0.f);
                r.z = fmaxf(r.z, 0.f); r.w = fmaxf(r.w, 0.f);
            }
            *reinterpret_cast<float4*>(C + (size_t)gr * ldc + gc) = r;
        }
    }
}

// ---------------------------------------------------------------------------
// Host driver
// ---------------------------------------------------------------------------
static inline int ceil_div(int a, int b) { return (a + b - 1) / b; }

extern "C" void kernel_launch(void* const* d_in, const int* in_sizes, int n_in,
                              void* d_out, int out_size)
{
    (void)out_size;
    const float *x = nullptr, *xs = nullptr;
    const int *src = nullptr, *dst = nullptr, *batch = nullptr;
    const float *W[6] = {}; const float *bv[6] = {};
    const float *p147[3] = {}; const float *G1 = nullptr;
    int xi = 0, ei = 0, wi = 0, bi = 0, pi = 0;
    for (int i = 0; i < n_in; i++) {
        int s = in_sizes[i];
        const void* p = d_in[i];
        if (s == NN * FF)          { if (xi == 0) x = (const float*)p; else xs = (const float*)p; xi++; }
        else if (s == EE)          { if (ei == 0) src = (const int*)p; else dst = (const int*)p; ei++; }
        else if (s == NN)          { batch = (const int*)p; }
        else if (s == FF * DD)     { if (wi < 6) W[wi] = (const float*)p; wi++; }
        else if (s == DD)          { if (bi < 6) bv[bi] = (const float*)p; bi++; }
        else if (s == EDIM * EDIM) { if (pi < 3) p147[pi] = (const float*)p; pi++; }
        else if (s == 2 * EDIM * EDIM) { G1 = (const float*)p; }
    }
    const float* P1 = p147[0];
    const float* P2 = p147[1];
    const float* G2 = p147[2];

    float *h, *h2, *nf, *ns, *lms, *lms2, *dinv, *dinv2, *gfs, *ghid, *cw;
    int *degi, *off, *cur, *csrc;
    __nv_bfloat16 *wth, *wtl;
    __half *hidh, *hidl, *hid2h, *hid2l, *p1h, *p1l, *p2h;
    cudaGetSymbolAddress((void**)&h,    g_h);
    cudaGetSymbolAddress((void**)&h2,   g_h2);
    cudaGetSymbolAddress((void**)&nf,   g_nf);
    cudaGetSymbolAddress((void**)&ns,   g_ns);
    cudaGetSymbolAddress((void**)&hidh, g_hidh);
    cudaGetSymbolAddress((void**)&hidl, g_hidl);
    cudaGetSymbolAddress((void**)&hid2h,g_hid2h);
    cudaGetSymbolAddress((void**)&hid2l,g_hid2l);
    cudaGetSymbolAddress((void**)&lms,  g_lms);
    cudaGetSymbolAddress((void**)&lms2, g_lms2);
    cudaGetSymbolAddress((void**)&degi, g_degi);
    cudaGetSymbolAddress((void**)&dinv, g_dinv);
    cudaGetSymbolAddress((void**)&dinv2,g_dinv2);
    cudaGetSymbolAddress((void**)&off,  g_off);
    cudaGetSymbolAddress((void**)&cur,  g_cur);
    cudaGetSymbolAddress((void**)&csrc, g_csrc);
    cudaGetSymbolAddress((void**)&cw,   g_cw);
    cudaGetSymbolAddress((void**)&gfs,  g_gfs);
    cudaGetSymbolAddress((void**)&ghid, g_ghid);
    cudaGetSymbolAddress((void**)&wth,  g_wth);
    cudaGetSymbolAddress((void**)&wtl,  g_wtl);
    cudaGetSymbolAddress((void**)&p1h,  g_p1h);
    cudaGetSymbolAddress((void**)&p1l,  g_p1l);
    cudaGetSymbolAddress((void**)&p2h,  g_p2h);

    cudaFuncSetAttribute(mma_gemm_kernel, cudaFuncAttributeMaxDynamicSharedMemorySize, GEMM_SMEM);
    cudaFuncSetAttribute(hgemm_kernel<0>, cudaFuncAttributeMaxDynamicSharedMemorySize, 5 * ASZ);
    cudaFuncSetAttribute(hgemm_kernel<1>, cudaFuncAttributeMaxDynamicSharedMemorySize, 4 * ASZ);

    float* out = (float*)d_out;
    const int E = EE, N = NN;

    const bool fork = g_hx.ok;
    cudaStream_t s0 = 0;
    cudaStream_t s1 = fork ? g_hx.s1 : (cudaStream_t)0;

    const int gemm_mx = ceil_div(N, 128);
    const int nwarp_threads = N * 32;

    // ---------------- prelude --------------------------------------------
    if (fork) {
        cudaEventRecord(g_hx.eFork, s0);
        cudaStreamWaitEvent(s1, g_hx.eFork, 0);
        zero_degi_kernel<<<ceil_div(N, 256), 256, 0, s1>>>(degi, N);
        degi_kernel<<<ceil_div(E, 256), 256, 0, s1>>>(dst, degi, E);
        scandinv_kernel<<<1, 1024, 0, s1>>>(degi, off, cur, dinv, dinv2, N);
        place_kernel<<<ceil_div(E, 256), 256, 0, s1>>>(src, dst, dinv, cur, csrc, cw, E);
        cudaEventRecord(g_hx.e2, s1);
        prep_kernel<<<14036, 256, 0, s0>>>(W[0], W[1], W[2], W[3], W[4], W[5], P1, P2,
                                           wth, wtl, p1h, p1l, p2h, x, xs, lms, lms2);
        cudaEventRecord(g_hx.e1, s0);
        mma_gemm_kernel<<<dim3(gemm_mx, 1), 256, GEMM_SMEM, s0>>>(
            x, FF, wth, wtl, DD, h, DD, N, DD, 16, lms);
        cudaStreamWaitEvent(s1, g_hx.e1, 0);
        cudaStreamWaitEvent(s0, g_hx.e2, 0);
    } else {
        zero_degi_kernel<<<ceil_div(N, 256), 256, 0, s0>>>(degi, N);
        degi_kernel<<<ceil_div(E, 256), 256, 0, s0>>>(dst, degi, E);
        scandinv_kernel<<<1, 1024, 0, s0>>>(degi, off, cur, dinv, dinv2, N);
        place_kernel<<<ceil_div(E, 256), 256, 0, s0>>>(src, dst, dinv, cur, csrc, cw, E);
        prep_kernel<<<14036, 256, 0, s0>>>(W[0], W[1], W[2], W[3], W[4], W[5], P1, P2,
                                           wth, wtl, p1h, p1l, p2h, x, xs, lms, lms2);
        mma_gemm_kernel<<<dim3(gemm_mx, 1), 256, GEMM_SMEM, s0>>>(
            x, FF, wth, wtl, DD, h, DD, N, DD, 16, lms);
    }

    auto run_branch = [&](cudaStream_t st, const float* xin, const float* lmsb, float* hb,
                          int wbase, const float* const* bb, float* nbuf, float* gpool,
                          bool skipFirstGemm) {
        const float* in = xin;
        int lda = FF;
        for (int l = 0; l < 3; l++) {
            float* slice = nbuf + l * DD;
            size_t woff = (size_t)(wbase + l) * 16384;
            if (!(l == 0 && skipFirstGemm)) {
                int fl = (l == 0) ? 16 : 8;
                mma_gemm_kernel<<<dim3(gemm_mx, 1), 256, GEMM_SMEM, st>>>(
                    in, lda, wth + woff, wtl + woff, DD,
                    hb, DD, N, DD, fl, lmsb);
            }
            gather_kernel<<<ceil_div(nwarp_threads, 256), 256, 0, st>>>(
                hb, off, degi, csrc, cw, dinv2, bb[l], slice, N);
            in = slice;
            lda = EDIM;
        }
        pool_kernel<<<GG, EDIM, 0, st>>>(nbuf, batch, gpool, GFS_LD, N);
    };

    const float* bf[3]  = {bv[0], bv[1], bv[2]};
    const float* bs_[3] = {bv[3], bv[4], bv[5]};

    const size_t off0 = 0;
    const size_t off1 = (size_t)GG * EDIM;
    const size_t off2 = 2 * (size_t)GG * EDIM;
    const size_t off3 = off2 + (size_t)N * EDIM;
    const size_t off4 = off3 + (size_t)GG * EDIM;

    const int ggrid = ceil_div(GG, 128);
    const int gwarp_threads = GG * 32;
    float* ghid0 = ghid;
    float* ghid1 = ghid + (size_t)GG * EDIM;
    float* ghid3 = ghid + 2 * (size_t)GG * EDIM;
    float* gf = gfs;           // cols [0,384) of gfs
    float* gs = gfs + EDIM;    // cols [384,768)

    // ---------------- stream s1: structure branch + out4 + out3 ------------
    run_branch(s1, xs, lms2, h2, 3, bs_, ns, gs, false);
    if (fork) cudaEventRecord(g_hx.eGS, s1);

    // out4: P1 (fp16 MODE0), P2 (fp16 MODE1), expmap
    hgemm_kernel<0><<<dim3(gemm_mx, 3), 256, 5 * ASZ, s1>>>(
        ns, nullptr, nullptr, EDIM, p1h, p1l, EDIM,
        nullptr, hid2h, hid2l, EDIM, N, EDIM);
    hgemm_kernel<1><<<dim3(gemm_mx, 3), 256, 4 * ASZ, s1>>>(
        nullptr, hid2h, hid2l, EDIM, p2h, nullptr, EDIM,
        out + off4, nullptr, nullptr, EDIM, N, EDIM);
    expmap_proj_kernel<<<ceil_div(nwarp_threads, 256), 256, 0, s1>>>(out + off4, N);

    // out3: mlp(gs, P1, P2)   (gs slice of gfs, lda=768)
    sgemm_kernel<<<dim3(ggrid, 3), 256, 0, s1>>>(gs, GFS_LD, P1, ghid3, EDIM, GG, EDIM, EDIM, 1);
    sgemm_kernel<<<dim3(ggrid, 3), 256, 0, s1>>>(ghid3, EDIM, P2, out + off3, EDIM,
                                                 GG, EDIM, EDIM, 0);
    expmap_proj_kernel<<<ceil_div(gwarp_threads, 256), 256, 0, s1>>>(out + off3, GG);
    if (fork) cudaEventRecord(g_hx.eEnd, s1);

    // ---------------- stream 0: feature branch + out2 + out1 + out0 --------
    run_branch(s0, x, lms, h, 0, bf, nf, gf, /*skipFirstGemm=*/true);

    // out2 head
    hgemm_kernel<0><<<dim3(gemm_mx, 3), 256, 5 * ASZ, s0>>>(
        nf, nullptr, nullptr, EDIM, p1h, p1l, EDIM,
        nullptr, hidh, hidl, EDIM, N, EDIM);
    hgemm_kernel<1><<<dim3(gemm_mx, 3), 256, 4 * ASZ, s0>>>(
        nullptr, hidh, hidl, EDIM, p2h, nullptr, EDIM,
        out + off2, nullptr, nullptr, EDIM, N, EDIM);
    expmap_proj_kernel<<<ceil_div(nwarp_threads, 256), 256, 0, s0>>>(out + off2, N);

    // out1: mlp(gf, P1, P2)  (gf slice of gfs, lda=768)
    sgemm_kernel<<<dim3(ggrid, 3), 256, 0, s0>>>(gf, GFS_LD, P1, ghid1, EDIM, GG, EDIM, EDIM, 1);
    sgemm_kernel<<<dim3(ggrid, 3), 256, 0, s0>>>(ghid1, EDIM, P2, out + off1, EDIM,
                                                 GG, EDIM, EDIM, 0);
    expmap_proj_kernel<<<ceil_div(gwarp_threads, 256), 256, 0, s0>>>(out + off1, GG);

    // out0: e( relu(gfs @ G1 [K=768]) @ G2 )  -- needs gs pool from s1
    if (fork) cudaStreamWaitEvent(s0, g_hx.eGS, 0);
    sgemm_kernel<<<dim3(ggrid, 3), 256, 0, s0>>>(gfs, GFS_LD, G1, ghid0, EDIM,
                                                 GG, EDIM, 2 * EDIM, 1);
    sgemm_kernel<<<dim3(ggrid, 3), 256, 0, s0>>>(ghid0, EDIM, G2, out + off0, EDIM,
                                                 GG, EDIM, EDIM, 0);
    expmap_proj_kernel<<<ceil_div(gwarp_threads, 256), 256, 0, s0>>>(out + off0, GG);

    if (fork) cudaStreamWaitEvent(s0, g_hx.eEnd, 0);
}

// round 16
// speedup vs baseline: 1.0786x; 1.0175x over previous
#include <cuda_runtime.h>
#include <cuda_bf16.h>
#include <cuda_fp16.h>
#include <cstdint>
#include <cstddef>

// Problem constants (fixed by the reference)
#define NN 50000
#define EE 600000
#define GG 512
#define FF 128
#define DD 128
#define EDIM 384
#define GFS_LD 768

// ---------------------------------------------------------------------------
// Scratch (device globals -- no allocation allowed in kernel_launch)
// ---------------------------------------------------------------------------
__device__ __align__(16) float g_h   [NN * DD];
__device__ __align__(16) float g_h2  [NN * DD];
__device__ __align__(16) float g_nf  [NN * EDIM];
__device__ __align__(16) float g_ns  [NN * EDIM];
__device__ __align__(16) __half g_hidh [NN * EDIM];
__device__ __align__(16) __half g_hidl [NN * EDIM];
__device__ __align__(16) __half g_hid2h[NN * EDIM];
__device__ __align__(16) __half g_hid2l[NN * EDIM];
__device__ float g_lms [NN];
__device__ float g_lms2[NN];
__device__ int   g_degi[NN];
__device__ float g_dinv[NN];
__device__ float g_dinv2[NN];
__device__ int   g_off [NN];
__device__ int   g_cur [NN];
__device__ int   g_csrc[EE];
__device__ float g_cw  [EE];
__device__ __align__(16) float g_gfs [GG * GFS_LD];   // [gf | gs] concat rows
__device__ __align__(16) float g_ghid[3 * GG * EDIM];
// GCN weights: single fp16, transposed [N,K], 6 layers of 16384
__device__ __align__(16) __half g_wgt[98304];
// fp16 head weights, transposed [N,K]: P1 split hi/lo, P2 hi only
__device__ __align__(16) __half g_p1h[147456];
__device__ __align__(16) __half g_p1l[147456];
__device__ __align__(16) __half g_p2h[147456];

// ---------------------------------------------------------------------------
// Static-init stream/event resources
// ---------------------------------------------------------------------------
struct HxStreams {
    cudaStream_t s1 = nullptr;
    cudaEvent_t eFork = nullptr, e1 = nullptr, e2 = nullptr;
    cudaEvent_t eGS = nullptr, eEnd = nullptr;
    bool ok = false;
    HxStreams() {
        ok = (cudaStreamCreateWithFlags(&s1, cudaStreamNonBlocking) == cudaSuccess)
          && (cudaEventCreateWithFlags(&eFork, cudaEventDisableTiming) == cudaSuccess)
          && (cudaEventCreateWithFlags(&e1,   cudaEventDisableTiming) == cudaSuccess)
          && (cudaEventCreateWithFlags(&e2,   cudaEventDisableTiming) == cudaSuccess)
          && (cudaEventCreateWithFlags(&eGS,  cudaEventDisableTiming) == cudaSuccess)
          && (cudaEventCreateWithFlags(&eEnd, cudaEventDisableTiming) == cudaSuccess);
    }
};
static HxStreams g_hx;

// ---------------------------------------------------------------------------
// Helpers
// ---------------------------------------------------------------------------
__device__ __forceinline__ void ldmx4(uint32_t* r, uint32_t addr) {
    asm volatile("ldmatrix.sync.aligned.m8n8.x4.shared.b16 {%0,%1,%2,%3}, [%4];"
                 : "=r"(r[0]), "=r"(r[1]), "=r"(r[2]), "=r"(r[3]) : "r"(addr));
}
__device__ __forceinline__ void ldmx2(uint32_t* r, uint32_t addr) {
    asm volatile("ldmatrix.sync.aligned.m8n8.x2.shared.b16 {%0,%1}, [%2];"
                 : "=r"(r[0]), "=r"(r[1]) : "r"(addr));
}
__device__ __forceinline__ void mmaf16(float* d, const uint32_t* a, const uint32_t* b) {
    asm volatile("mma.sync.aligned.m16n8k16.row.col.f32.f16.f16.f32 "
                 "{%0,%1,%2,%3}, {%4,%5,%6,%7}, {%8,%9}, {%0,%1,%2,%3};"
                 : "+f"(d[0]), "+f"(d[1]), "+f"(d[2]), "+f"(d[3])
                 : "r"(a[0]), "r"(a[1]), "r"(a[2]), "r"(a[3]), "r"(b[0]), "r"(b[1]));
}
__device__ __forceinline__ uint32_t smem_u32(const void* p) {
    uint32_t a;
    asm("{ .reg .u64 t; cvta.to.shared.u64 t, %1; cvt.u32.u64 %0, t; }" : "=r"(a) : "l"(p));
    return a;
}
__device__ __forceinline__ void cpa16(uint32_t saddr, const void* gaddr) {
    asm volatile("cp.async.cg.shared.global [%0], [%1], 16;" :: "r"(saddr), "l"(gaddr));
}

// ---------------------------------------------------------------------------
// prep kernel: weight transpose (blocks 0..1535), logmap scales after.
// GCN weights -> fp16 single; P1 -> fp16 hi/lo; P2 -> fp16 hi.
// ---------------------------------------------------------------------------
__global__ void prep_kernel(const float* __restrict__ W0, const float* __restrict__ W1,
                            const float* __restrict__ W2, const float* __restrict__ W3,
                            const float* __restrict__ W4, const float* __restrict__ W5,
                            const float* __restrict__ P1, const float* __restrict__ P2,
                            __half* __restrict__ wgt,
                            __half* __restrict__ p1h, __half* __restrict__ p1l,
                            __half* __restrict__ p2h,
                            const float* __restrict__ x, const float* __restrict__ xs,
                            float* __restrict__ lms, float* __restrict__ lms2)
{
    int b = blockIdx.x;
    if (b < 1536) {
        int idx = b * 256 + threadIdx.x;
        if (idx < 98304) {
            int m = idx >> 14; int li = idx & 16383;
            const float* ws[6] = {W0, W1, W2, W3, W4, W5};
            int k = li / 128, n = li % 128;
            wgt[(m << 14) + n * 128 + k] = __float2half_rn(ws[m][li]);
        } else if (idx < 245760) {
            int li = idx - 98304;
            int k = li / 384, n = li % 384;
            float v = P1[li];
            __half fh = __float2half_rn(v);
            p1h[n * 384 + k] = fh;
            p1l[n * 384 + k] = __float2half_rn(v - __half2float(fh));
        } else {
            int li = idx - 245760;
            int k = li / 384, n = li % 384;
            p2h[n * 384 + k] = __float2half_rn(P2[li]);
        }
    } else {
        int rb = b - 1536;
        const float* xin = x; float* sout = lms;
        if (rb >= 6250) { rb -= 6250; xin = xs; sout = lms2; }
        int w = rb * 8 + (threadIdx.x >> 5);
        if (w >= NN) return;
        int lane = threadIdx.x & 31;
        const float4 v = *reinterpret_cast<const float4*>(xin + (size_t)w * FF + lane * 4);
        float ss = v.x * v.x + v.y * v.y + v.z * v.z + v.w * v.w;
#pragma unroll
        for (int o = 16; o; o >>= 1) ss += __shfl_xor_sync(0xffffffffu, ss, o);
        if (lane == 0) {
            float nrm = sqrtf(ss);
            float n1  = fmaxf(nrm, 1e-15f);
            float arg = fminf(n1, 1.0f - 1e-15f);
            sout[w] = atanhf(arg) / n1;
        }
    }
}

// ---------------------------------------------------------------------------
// fp16 2-MMA GCN GEMM: A fp32 -> fp16 hi/lo split on the fly (A effectively
// exact); B single fp16; C = Ah*B + Al*B (only B rounding error survives).
// flags: 8=RELU on A, 16=scale A rows by ascale[].
// smem: [Ah][Al][B0][B1] = 4*ASZ (B double-buffered via cp.async)
// ---------------------------------------------------------------------------
#define ROWB 80
#define ASZ (128 * ROWB)
#define GCN_SMEM (4 * ASZ)

__global__ void __launch_bounds__(256, 2)
hgcn_gemm_kernel(const float* __restrict__ A, int lda,
                 const __half* __restrict__ Bw, int ldb,
                 float* __restrict__ C, int ldc,
                 int M, int K, int flags,
                 const float* __restrict__ ascale)
{
    extern __shared__ __align__(16) char sm[];
    const int tid  = threadIdx.x;
    const int wid  = tid >> 5;
    const int lane = tid & 31;
    const int wm = wid & 1;
    const int wn = wid >> 1;
    const int bm = blockIdx.x * 128;
    const int bn = blockIdx.y * 128;
    const uint32_t sbase = smem_u32(sm);
    const uint32_t sB0 = sbase + 2 * ASZ;

    int arow[4], akc[4];
#pragma unroll
    for (int it = 0; it < 4; ++it) {
        int idx = tid + it * 256;
        arow[it] = idx >> 3;
        akc[it]  = (idx & 7) << 2;
    }
    int brow[2], bc16[2];
#pragma unroll
    for (int it = 0; it < 2; ++it) {
        int idx = tid + it * 256;
        brow[it] = idx >> 2;
        bc16[it] = (idx & 3) << 4;
    }

    float acc[4][4][4];
#pragma unroll
    for (int i = 0; i < 4; i++)
#pragma unroll
        for (int j = 0; j < 4; j++)
#pragma unroll
            for (int l = 0; l < 4; l++) acc[i][j][l] = 0.0f;

    const int nch = K >> 5;
    float4 fr[4];
    float  asc[4];

#pragma unroll
    for (int it = 0; it < 4; ++it) {
        int gr = bm + arow[it];
        fr[it] = make_float4(0.f, 0.f, 0.f, 0.f);
        asc[it] = 1.0f;
        if (gr < M) {
            fr[it] = *reinterpret_cast<const float4*>(A + (size_t)gr * lda + akc[it]);
            if (flags & 16) asc[it] = ascale[gr];
        }
    }
#pragma unroll
    for (int it = 0; it < 2; ++it) {
        uint32_t so = sB0 + brow[it] * ROWB + bc16[it];
        size_t gb = ((size_t)(bn + brow[it]) * ldb) * 2 + bc16[it];
        cpa16(so, (const char*)Bw + gb);
    }
    asm volatile("cp.async.commit_group;" ::: "memory");

    for (int ch = 0; ch < nch; ++ch) {
        // ---- convert + store A as fp16 hi/lo ----
#pragma unroll
        for (int it = 0; it < 4; ++it) {
            float4 v = fr[it];
            float s = asc[it];
            v.x *= s; v.y *= s; v.z *= s; v.w *= s;
            if (flags & 8) {
                v.x = fmaxf(v.x, 0.f); v.y = fmaxf(v.y, 0.f);
                v.z = fmaxf(v.z, 0.f); v.w = fmaxf(v.w, 0.f);
            }
            __half2 h01 = __float22half2_rn(make_float2(v.x, v.y));
            __half2 h23 = __float22half2_rn(make_float2(v.z, v.w));
            float2 f01 = __half22float2(h01);
            float2 f23 = __half22float2(h23);
            __half2 l01 = __float22half2_rn(make_float2(v.x - f01.x, v.y - f01.y));
            __half2 l23 = __float22half2_rn(make_float2(v.z - f23.x, v.w - f23.y));
            int off = arow[it] * ROWB + akc[it] * 2;
            uint2 uh, ul;
            uh.x = *reinterpret_cast<uint32_t*>(&h01);
            uh.y = *reinterpret_cast<uint32_t*>(&h23);
            ul.x = *reinterpret_cast<uint32_t*>(&l01);
            ul.y = *reinterpret_cast<uint32_t*>(&l23);
            *reinterpret_cast<uint2*>(sm + off)       = uh;
            *reinterpret_cast<uint2*>(sm + ASZ + off) = ul;
        }
        asm volatile("cp.async.wait_group 0;" ::: "memory");
        __syncthreads();

        // ---- prefetch chunk ch+1 ----
        if (ch + 1 < nch) {
            int k0 = (ch + 1) << 5;
#pragma unroll
            for (int it = 0; it < 4; ++it) {
                int gr = bm + arow[it];
                fr[it] = make_float4(0.f, 0.f, 0.f, 0.f);
                if (gr < M)
                    fr[it] = *reinterpret_cast<const float4*>(A + (size_t)gr * lda + k0 + akc[it]);
            }
            uint32_t so0 = sB0 + ((ch + 1) & 1) * ASZ;
#pragma unroll
            for (int it = 0; it < 2; ++it) {
                uint32_t so = so0 + brow[it] * ROWB + bc16[it];
                size_t gb = ((size_t)(bn + brow[it]) * ldb + k0) * 2 + bc16[it];
                cpa16(so, (const char*)Bw + gb);
            }
            asm volatile("cp.async.commit_group;" ::: "memory");
        }

        // ---- compute chunk ch (2 MMAs per tile pair) ----
        const uint32_t sB = sB0 + (ch & 1) * ASZ;
#pragma unroll
        for (int ks = 0; ks < 2; ++ks) {
            uint32_t bf[4][2];
#pragma unroll
            for (int nt = 0; nt < 4; ++nt) {
                uint32_t off = (uint32_t)((wn * 32 + nt * 8 + (lane & 7)) * ROWB
                                          + (ks * 16 + ((lane >> 3) & 1) * 8) * 2);
                ldmx2(bf[nt], sB + off);
            }
#pragma unroll
            for (int mt = 0; mt < 4; ++mt) {
                uint32_t off = (uint32_t)((wm * 64 + mt * 16 + (lane & 15)) * ROWB
                                          + (ks * 16 + ((lane >> 4) & 1) * 8) * 2);
                uint32_t ah[4], al[4];
                ldmx4(ah, sbase + off);
                ldmx4(al, sbase + ASZ + off);
#pragma unroll
                for (int nt = 0; nt < 4; ++nt) {
                    mmaf16(acc[mt][nt], ah, bf[nt]);
                    mmaf16(acc[mt][nt], al, bf[nt]);
                }
            }
        }
        __syncthreads();
    }

    const int groupID = lane >> 2;
    const int tid4 = lane & 3;
#pragma unroll
    for (int mt = 0; mt < 4; ++mt) {
#pragma unroll
        for (int half = 0; half < 2; ++half) {
            int gr = bm + wm * 64 + mt * 16 + groupID + half * 8;
            if (gr >= M) continue;
#pragma unroll
            for (int nt = 0; nt < 4; ++nt) {
                int gc = bn + wn * 32 + nt * 8 + tid4 * 2;
                float2 r = make_float2(acc[mt][nt][half * 2], acc[mt][nt][half * 2 + 1]);
                *reinterpret_cast<float2*>(C + (size_t)gr * ldc + gc) = r;
            }
        }
    }
}

// ---------------------------------------------------------------------------
// fp16 2-MMA head GEMM (MODE 0: fp32 A + split B -> fp16-split C;
//                       MODE 1: split A + single B -> fp32 C)
// ---------------------------------------------------------------------------
template<int MODE>
__global__ void __launch_bounds__(256, 2)
hgemm_kernel(const float* __restrict__ A,
             const __half* __restrict__ Ah, const __half* __restrict__ Al,
             int lda,
             const __half* __restrict__ Bh, const __half* __restrict__ Bl,
             int ldb,
             float* __restrict__ C,
             __half* __restrict__ Cbh, __half* __restrict__ Cbl,
             int ldc, int M, int K)
{
    extern __shared__ __align__(16) char sm[];
    const int tid  = threadIdx.x;
    const int wid  = tid >> 5;
    const int lane = tid & 31;
    const int wm = wid & 1;
    const int wn = wid >> 1;
    const int bm = blockIdx.x * 128;
    const int bn = blockIdx.y * 128;
    const uint32_t sbase = smem_u32(sm);

    int arow[4], akc[4];
#pragma unroll
    for (int it = 0; it < 4; ++it) {
        int idx = tid + it * 256;
        arow[it] = idx >> 3;
        akc[it]  = (idx & 7) << 2;
    }
    int brow[2], bc16[2];
#pragma unroll
    for (int it = 0; it < 2; ++it) {
        int idx = tid + it * 256;
        brow[it] = idx >> 2;
        bc16[it] = (idx & 3) << 4;
    }

    float acc[4][4][4];
#pragma unroll
    for (int i = 0; i < 4; i++)
#pragma unroll
        for (int j = 0; j < 4; j++)
#pragma unroll
            for (int l = 0; l < 4; l++) acc[i][j][l] = 0.0f;

    const int nch = K >> 5;
    float4 fr[4];
    uint2  urh[4], url[4];

    const uint32_t sB0 = sbase + ((MODE == 0) ? ASZ : 2 * ASZ);
    const uint32_t bstride = (MODE == 0) ? 2 * ASZ : ASZ;

#pragma unroll
    for (int it = 0; it < 4; ++it) {
        int gr = bm + arow[it];
        if (MODE == 0) {
            fr[it] = make_float4(0.f, 0.f, 0.f, 0.f);
            if (gr < M) fr[it] = *reinterpret_cast<const float4*>(A + (size_t)gr * lda + akc[it]);
        } else {
            urh[it] = make_uint2(0, 0); url[it] = make_uint2(0, 0);
            if (gr < M) {
                urh[it] = *reinterpret_cast<const uint2*>(Ah + (size_t)gr * lda + akc[it]);
                url[it] = *reinterpret_cast<const uint2*>(Al + (size_t)gr * lda + akc[it]);
            }
        }
    }
#pragma unroll
    for (int it = 0; it < 2; ++it) {
        uint32_t so = sB0 + brow[it] * ROWB + bc16[it];
        size_t gb = ((size_t)(bn + brow[it]) * ldb) * 2 + bc16[it];
        cpa16(so, (const char*)Bh + gb);
        if (MODE == 0) cpa16(so + ASZ, (const char*)Bl + gb);
    }
    asm volatile("cp.async.commit_group;" ::: "memory");

    for (int ch = 0; ch < nch; ++ch) {
#pragma unroll
        for (int it = 0; it < 4; ++it) {
            int off = arow[it] * ROWB + akc[it] * 2;
            if (MODE == 0) {
                float4 v = fr[it];
                v.x = fmaxf(v.x, 0.f); v.y = fmaxf(v.y, 0.f);
                v.z = fmaxf(v.z, 0.f); v.w = fmaxf(v.w, 0.f);
                __half2 h01 = __float22half2_rn(make_float2(v.x, v.y));
                __half2 h23 = __float22half2_rn(make_float2(v.z, v.w));
                uint2 u;
                u.x = *reinterpret_cast<uint32_t*>(&h01);
                u.y = *reinterpret_cast<uint32_t*>(&h23);
                *reinterpret_cast<uint2*>(sm + off) = u;
            } else {
                *reinterpret_cast<uint2*>(sm + off)       = urh[it];
                *reinterpret_cast<uint2*>(sm + ASZ + off) = url[it];
            }
        }
        asm volatile("cp.async.wait_group 0;" ::: "memory");
        __syncthreads();

        if (ch + 1 < nch) {
            int k0 = (ch + 1) << 5;
#pragma unroll
            for (int it = 0; it < 4; ++it) {
                int gr = bm + arow[it];
                if (MODE == 0) {
                    fr[it] = make_float4(0.f, 0.f, 0.f, 0.f);
                    if (gr < M)
                        fr[it] = *reinterpret_cast<const float4*>(A + (size_t)gr * lda + k0 + akc[it]);
                } else {
                    urh[it] = make_uint2(0, 0); url[it] = make_uint2(0, 0);
                    if (gr < M) {
                        urh[it] = *reinterpret_cast<const uint2*>(Ah + (size_t)gr * lda + k0 + akc[it]);
                        url[it] = *reinterpret_cast<const uint2*>(Al + (size_t)gr * lda + k0 + akc[it]);
                    }
                }
            }
            uint32_t so0 = sB0 + ((ch + 1) & 1) * bstride;
#pragma unroll
            for (int it = 0; it < 2; ++it) {
                uint32_t so = so0 + brow[it] * ROWB + bc16[it];
                size_t gb = ((size_t)(bn + brow[it]) * ldb + k0) * 2 + bc16[it];
                cpa16(so, (const char*)Bh + gb);
                if (MODE == 0) cpa16(so + ASZ, (const char*)Bl + gb);
            }
            asm volatile("cp.async.commit_group;" ::: "memory");
        }

        const uint32_t sB = sB0 + (ch & 1) * bstride;
#pragma unroll
        for (int ks = 0; ks < 2; ++ks) {
            uint32_t bfh[4][2], bfl[4][2];
#pragma unroll
            for (int nt = 0; nt < 4; ++nt) {
                uint32_t off = (uint32_t)((wn * 32 + nt * 8 + (lane & 7)) * ROWB
                                          + (ks * 16 + ((lane >> 3) & 1) * 8) * 2);
                ldmx2(bfh[nt], sB + off);
                if (MODE == 0) ldmx2(bfl[nt], sB + ASZ + off);
            }
#pragma unroll
            for (int mt = 0; mt < 4; ++mt) {
                uint32_t off = (uint32_t)((wm * 64 + mt * 16 + (lane & 15)) * ROWB
                                          + (ks * 16 + ((lane >> 4) & 1) * 8) * 2);
                uint32_t a0[4], a1[4];
                ldmx4(a0, sbase + off);
                if (MODE == 1) ldmx4(a1, sbase + ASZ + off);
#pragma unroll
                for (int nt = 0; nt < 4; ++nt) {
                    if (MODE == 0) {
                        mmaf16(acc[mt][nt], a0, bfh[nt]);
                        mmaf16(acc[mt][nt], a0, bfl[nt]);
                    } else {
                        mmaf16(acc[mt][nt], a0, bfh[nt]);
                        mmaf16(acc[mt][nt], a1, bfh[nt]);
                    }
                }
            }
        }
        __syncthreads();
    }

    const int groupID = lane >> 2;
    const int tid4 = lane & 3;
#pragma unroll
    for (int mt = 0; mt < 4; ++mt) {
#pragma unroll
        for (int half = 0; half < 2; ++half) {
            int gr = bm + wm * 64 + mt * 16 + groupID + half * 8;
            if (gr >= M) continue;
#pragma unroll
            for (int nt = 0; nt < 4; ++nt) {
                int gc = bn + wn * 32 + nt * 8 + tid4 * 2;
                float2 r = make_float2(acc[mt][nt][half * 2], acc[mt][nt][half * 2 + 1]);
                if (MODE == 0) {
                    r.x = fmaxf(r.x, 0.f); r.y = fmaxf(r.y, 0.f);
                    __half2 hh = __float22half2_rn(r);
                    float2 fh = __half22float2(hh);
                    __half2 hl = __float22half2_rn(make_float2(r.x - fh.x, r.y - fh.y));
                    *reinterpret_cast<__half2*>(Cbh + (size_t)gr * ldc + gc) = hh;
                    *reinterpret_cast<__half2*>(Cbl + (size_t)gr * ldc + gc) = hl;
                } else {
                    *reinterpret_cast<float2*>(C + (size_t)gr * ldc + gc) = r;
                }
            }
        }
    }
}

// ---------------------------------------------------------------------------
// CSR build + graph kernels
// ---------------------------------------------------------------------------
__global__ void zero_degi_kernel(int* __restrict__ degi, int n)
{
    int t = blockIdx.x * blockDim.x + threadIdx.x;
    if (t < n) degi[t] = 0;
}

__global__ void degi_kernel(const int* __restrict__ dst, int* __restrict__ degi, int e)
{
    int t = blockIdx.x * blockDim.x + threadIdx.x;
    if (t < e) atomicAdd(&degi[dst[t]], 1);
}

__global__ void __launch_bounds__(1024)
scandinv_kernel(const int* __restrict__ degi, int* __restrict__ off,
                int* __restrict__ cur, float* __restrict__ dinv,
                float* __restrict__ dinv2, int n)
{
    __shared__ int warpsum[32];
    __shared__ int carry;
    const int tid = threadIdx.x;
    const int lane = tid & 31;
    const int wrp = tid >> 5;
    if (tid == 0) carry = 0;
    __syncthreads();
    for (int base = 0; base < n; base += 1024) {
        int i = base + tid;
        int v = (i < n) ? degi[i] : 0;
        if (i < n) {
            float d  = (float)v + 1.0f;
            float di = 1.0f / sqrtf(d);
            dinv[i]  = di;
            dinv2[i] = di * di;
        }
        int x = v;
#pragma unroll
        for (int o = 1; o < 32; o <<= 1) {
            int y = __shfl_up_sync(0xffffffffu, x, o);
            if (lane >= o) x += y;
        }
        if (lane == 31) warpsum[wrp] = x;
        __syncthreads();
        if (tid < 32) {
            int s = warpsum[tid];
#pragma unroll
            for (int o = 1; o < 32; o <<= 1) {
                int y = __shfl_up_sync(0xffffffffu, s, o);
                if (tid >= o) s += y;
            }
            warpsum[tid] = s;
        }
        __syncthreads();
        int incl = x + (wrp ? warpsum[wrp - 1] : 0);
        int excl = incl - v + carry;
        if (i < n) { off[i] = excl; cur[i] = excl; }
        __syncthreads();
        if (tid == 1023) carry += incl;
        __syncthreads();
    }
}

__global__ void place_kernel(const int* __restrict__ src, const int* __restrict__ dst,
                             const float* __restrict__ dinv,
                             int* __restrict__ cur,
                             int* __restrict__ csrc, float* __restrict__ cw, int e)
{
    int t = blockIdx.x * blockDim.x + threadIdx.x;
    if (t >= e) return;
    int s = src[t], d = dst[t];
    int pos = atomicAdd(&cur[d], 1);
    csrc[pos] = s;
    cw[pos]   = dinv[s] * dinv[d];
}

// gather aggregation: one warp per node, 8/4/1 unroll ladder (MLP up to 8)
__global__ void gather_kernel(const float* __restrict__ h,
                              const int* __restrict__ off, const int* __restrict__ degi,
                              const int* __restrict__ csrc, const float* __restrict__ cw,
                              const float* __restrict__ dinv2, const float* __restrict__ bias,
                              float* __restrict__ slice, int n)
{
    int t = blockIdx.x * blockDim.x + threadIdx.x;
    int w = t >> 5;
    if (w >= n) return;
    int lane = t & 31;
    int c = lane << 2;
    const float4 hv = *reinterpret_cast<const float4*>(h + (size_t)w * DD + c);
    const float4 bb = *reinterpret_cast<const float4*>(bias + c);
    float d2 = dinv2[w];
    float4 acc = make_float4(hv.x * d2 + bb.x, hv.y * d2 + bb.y,
                             hv.z * d2 + bb.z, hv.w * d2 + bb.w);
    int j   = off[w];
    int end = j + degi[w];
    for (; j + 8 <= end; j += 8) {
        int   ii[8];
        float ww[8];
#pragma unroll
        for (int q = 0; q < 8; ++q) { ii[q] = __ldg(csrc + j + q); ww[q] = __ldg(cw + j + q); }
        float4 vv[8];
#pragma unroll
        for (int q = 0; q < 8; ++q)
            vv[q] = *reinterpret_cast<const float4*>(h + (size_t)ii[q] * DD + c);
#pragma unroll
        for (int q = 0; q < 8; ++q) {
            acc.x += ww[q] * vv[q].x; acc.y += ww[q] * vv[q].y;
            acc.z += ww[q] * vv[q].z; acc.w += ww[q] * vv[q].w;
        }
    }
    for (; j + 4 <= end; j += 4) {
        int   i0 = __ldg(csrc + j),     i1 = __ldg(csrc + j + 1);
        int   i2 = __ldg(csrc + j + 2), i3 = __ldg(csrc + j + 3);
        float w0 = __ldg(cw + j),       w1 = __ldg(cw + j + 1);
        float w2 = __ldg(cw + j + 2),   w3 = __ldg(cw + j + 3);
        float4 v0 = *reinterpret_cast<const float4*>(h + (size_t)i0 * DD + c);
        float4 v1 = *reinterpret_cast<const float4*>(h + (size_t)i1 * DD + c);
        float4 v2 = *reinterpret_cast<const float4*>(h + (size_t)i2 * DD + c);
        float4 v3 = *reinterpret_cast<const float4*>(h + (size_t)i3 * DD + c);
        acc.x += w0 * v0.x + w1 * v1.x + w2 * v2.x + w3 * v3.x;
        acc.y += w0 * v0.y + w1 * v1.y + w2 * v2.y + w3 * v3.y;
        acc.z += w0 * v0.z + w1 * v1.z + w2 * v2.z + w3 * v3.z;
        acc.w += w0 * v0.w + w1 * v1.w + w2 * v2.w + w3 * v3.w;
    }
    for (; j < end; ++j) {
        int s    = __ldg(csrc + j);
        float wt = __ldg(cw + j);
        float4 v = *reinterpret_cast<const float4*>(h + (size_t)s * DD + c);
        acc.x += wt * v.x; acc.y += wt * v.y;
        acc.z += wt * v.z; acc.w += wt * v.w;
    }
    *reinterpret_cast<float4*>(slice + (size_t)w * EDIM + c) = acc;
}

__global__ void expmap_proj_kernel(float* __restrict__ p, int rows)
{
    int t = blockIdx.x * blockDim.x + threadIdx.x;
    int w = t >> 5;
    if (w >= rows) return;
    int lane = t & 31;
    float* r = p + (size_t)w * EDIM;
    float4 v0 = *reinterpret_cast<const float4*>(r + lane * 4);
    float4 v1 = *reinterpret_cast<const float4*>(r + lane * 4 + 128);
    float4 v2 = *reinterpret_cast<const float4*>(r + lane * 4 + 256);
    float ss = v0.x*v0.x + v0.y*v0.y + v0.z*v0.z + v0.w*v0.w
             + v1.x*v1.x + v1.y*v1.y + v1.z*v1.z + v1.w*v1.w
             + v2.x*v2.x + v2.y*v2.y + v2.z*v2.z + v2.w*v2.w;
#pragma unroll
    for (int o = 16; o; o >>= 1) ss += __shfl_xor_sync(0xffffffffu, ss, o);
    float nrm = sqrtf(ss);
    float n1  = fmaxf(nrm, 1e-15f);
    float s   = tanhf(n1) / n1;
    float yn  = s * nrm;
    const float maxn = 1.0f - 4e-3f;
    if (yn > maxn) s = s * maxn / yn;
    v0.x*=s; v0.y*=s; v0.z*=s; v0.w*=s;
    v1.x*=s; v1.y*=s; v1.z*=s; v1.w*=s;
    v2.x*=s; v2.y*=s; v2.z*=s; v2.w*=s;
    *reinterpret_cast<float4*>(r + lane * 4      ) = v0;
    *reinterpret_cast<float4*>(r + lane * 4 + 128) = v1;
    *reinterpret_cast<float4*>(r + lane * 4 + 256) = v2;
}

// pool of relu(nf): writes 384 cols at out[g*ldo + t]
__global__ void pool_kernel(const float* __restrict__ nf, const int* __restrict__ batch,
                            float* __restrict__ out, int ldo, int n)
{
    int g = blockIdx.x;
    int t = threadIdx.x;
    int lo = 0, hi = n;
    while (lo < hi) { int m = (lo + hi) >> 1; if (batch[m] < g) lo = m + 1; else hi = m; }
    int s0 = lo;
    hi = n;
    while (lo < hi) { int m = (lo + hi) >> 1; if (batch[m] < g + 1) lo = m + 1; else hi = m; }
    int s1 = lo;
    float acc = 0.0f;
    for (int i = s0; i < s1; i++) acc += fmaxf(nf[(size_t)i * EDIM + t], 0.0f);
    out[(size_t)g * ldo + t] = acc;
}

// ---------------------------------------------------------------------------
// fp32 SGEMM (tiny graph-level GEMMs, M=512). flags: 1=RELU, 2=ACCUM
// ---------------------------------------------------------------------------
__global__ void __launch_bounds__(256)
sgemm_kernel(const float* __restrict__ A, int lda,
             const float* __restrict__ B,
             float* __restrict__ C, int ldc,
             int M, int Nc, int K, int flags)
{
    __shared__ float As[16][132];
    __shared__ float Bs[16][128];
    const int tid = threadIdx.x;
    const int bm = blockIdx.x * 128;
    const int bn = blockIdx.y * 128;
    const int tx = tid & 15;
    const int ty = tid >> 4;

    float acc[8][8];
#pragma unroll
    for (int i = 0; i < 8; i++)
#pragma unroll
        for (int j = 0; j < 8; j++) acc[i][j] = 0.0f;

    for (int k0 = 0; k0 < K; k0 += 16) {
#pragma unroll
        for (int it = 0; it < 2; ++it) {
            int idx = tid + it * 256;
            int row = idx >> 2;
            int kc  = (idx & 3) << 2;
            int gr  = bm + row;
            float4 v = make_float4(0.f, 0.f, 0.f, 0.f);
            if (gr < M) v = *reinterpret_cast<const float4*>(A + (size_t)gr * lda + k0 + kc);
            As[kc + 0][row] = v.x; As[kc + 1][row] = v.y;
            As[kc + 2][row] = v.z; As[kc + 3][row] = v.w;
        }
#pragma unroll
        for (int it = 0; it < 2; ++it) {
            int idx = tid + it * 256;
            int kr  = idx >> 5;
            int nc  = (idx & 31) << 2;
            float4 v = *reinterpret_cast<const float4*>(B + (size_t)(k0 + kr) * Nc + bn + nc);
            *reinterpret_cast<float4*>(&Bs[kr][nc]) = v;
        }
        __syncthreads();
#pragma unroll
        for (int k = 0; k < 16; ++k) {
            float a[8], b[8];
#pragma unroll
            for (int i = 0; i < 8; i++) a[i] = As[k][ty * 8 + i];
#pragma unroll
            for (int j = 0; j < 8; j++) b[j] = Bs[k][tx * 8 + j];
#pragma unroll
            for (int i = 0; i < 8; i++)
#pragma unroll
                for (int j = 0; j < 8; j++) acc[i][j] = fmaf(a[i], b[j], acc[i][j]);
        }
        __syncthreads();
    }

#pragma unroll
    for (int i = 0; i < 8; i++) {
        int gr = bm + ty * 8 + i;
        if (gr >= M) break;
#pragma unroll
        for (int j = 0; j < 8; j += 4) {
            int gc = bn + tx * 8 + j;
            float4 r = make_float4(acc[i][j], acc[i][j+1], acc[i][j+2], acc[i][j+3]);
            if (flags & 2) {
                float4 o = *reinterpret_cast<const float4*>(C + (size_t)gr * ldc + gc);
                r.x += o.x; r.y += o.y; r.z += o.z; r.w += o.w;
            }
            if (flags & 1) {
                r.x = fmaxf(r.x, 0.f); r.y = fmaxf(r.y, 0.f);
                r.z = fmaxf(r.z, 0.f); r.w = fmaxf(r.w, 0.f);
            }
            *reinterpret_cast<float4*>(C + (size_t)gr * ldc + gc) = r;
        }
    }
}

// ---------------------------------------------------------------------------
// Host driver
// ---------------------------------------------------------------------------
static inline int ceil_div(int a, int b) { return (a + b - 1) / b; }

extern "C" void kernel_launch(void* const* d_in, const int* in_sizes, int n_in,
                              void* d_out, int out_size)
{
    (void)out_size;
    const float *x = nullptr, *xs = nullptr;
    const int *src = nullptr, *dst = nullptr, *batch = nullptr;
    const float *W[6] = {}; const float *bv[6] = {};
    const float *p147[3] = {}; const float *G1 = nullptr;
    int xi = 0, ei = 0, wi = 0, bi = 0, pi = 0;
    for (int i = 0; i < n_in; i++) {
        int s = in_sizes[i];
        const void* p = d_in[i];
        if (s == NN * FF)          { if (xi == 0) x = (const float*)p; else xs = (const float*)p; xi++; }
        else if (s == EE)          { if (ei == 0) src = (const int*)p; else dst = (const int*)p; ei++; }
        else if (s == NN)          { batch = (const int*)p; }
        else if (s == FF * DD)     { if (wi < 6) W[wi] = (const float*)p; wi++; }
        else if (s == DD)          { if (bi < 6) bv[bi] = (const float*)p; bi++; }
        else if (s == EDIM * EDIM) { if (pi < 3) p147[pi] = (const float*)p; pi++; }
        else if (s == 2 * EDIM * EDIM) { G1 = (const float*)p; }
    }
    const float* P1 = p147[0];
    const float* P2 = p147[1];
    const float* G2 = p147[2];

    float *h, *h2, *nf, *ns, *lms, *lms2, *dinv, *dinv2, *gfs, *ghid, *cw;
    int *degi, *off, *cur, *csrc;
    __half *wgt, *hidh, *hidl, *hid2h, *hid2l, *p1h, *p1l, *p2h;
    cudaGetSymbolAddress((void**)&h,    g_h);
    cudaGetSymbolAddress((void**)&h2,   g_h2);
    cudaGetSymbolAddress((void**)&nf,   g_nf);
    cudaGetSymbolAddress((void**)&ns,   g_ns);
    cudaGetSymbolAddress((void**)&hidh, g_hidh);
    cudaGetSymbolAddress((void**)&hidl, g_hidl);
    cudaGetSymbolAddress((void**)&hid2h,g_hid2h);
    cudaGetSymbolAddress((void**)&hid2l,g_hid2l);
    cudaGetSymbolAddress((void**)&lms,  g_lms);
    cudaGetSymbolAddress((void**)&lms2, g_lms2);
    cudaGetSymbolAddress((void**)&degi, g_degi);
    cudaGetSymbolAddress((void**)&dinv, g_dinv);
    cudaGetSymbolAddress((void**)&dinv2,g_dinv2);
    cudaGetSymbolAddress((void**)&off,  g_off);
    cudaGetSymbolAddress((void**)&cur,  g_cur);
    cudaGetSymbolAddress((void**)&csrc, g_csrc);
    cudaGetSymbolAddress((void**)&cw,   g_cw);
    cudaGetSymbolAddress((void**)&gfs,  g_gfs);
    cudaGetSymbolAddress((void**)&ghid, g_ghid);
    cudaGetSymbolAddress((void**)&wgt,  g_wgt);
    cudaGetSymbolAddress((void**)&p1h,  g_p1h);
    cudaGetSymbolAddress((void**)&p1l,  g_p1l);
    cudaGetSymbolAddress((void**)&p2h,  g_p2h);

    cudaFuncSetAttribute(hgcn_gemm_kernel, cudaFuncAttributeMaxDynamicSharedMemorySize, GCN_SMEM);
    cudaFuncSetAttribute(hgemm_kernel<0>, cudaFuncAttributeMaxDynamicSharedMemorySize, 5 * ASZ);
    cudaFuncSetAttribute(hgemm_kernel<1>, cudaFuncAttributeMaxDynamicSharedMemorySize, 4 * ASZ);

    float* out = (float*)d_out;
    const int E = EE, N = NN;

    const bool fork = g_hx.ok;
    cudaStream_t s0 = 0;
    cudaStream_t s1 = fork ? g_hx.s1 : (cudaStream_t)0;

    const int gemm_mx = ceil_div(N, 128);
    const int nwarp_threads = N * 32;

    // ---------------- prelude --------------------------------------------
    if (fork) {
        cudaEventRecord(g_hx.eFork, s0);
        cudaStreamWaitEvent(s1, g_hx.eFork, 0);
        zero_degi_kernel<<<ceil_div(N, 256), 256, 0, s1>>>(degi, N);
        degi_kernel<<<ceil_div(E, 256), 256, 0, s1>>>(dst, degi, E);
        scandinv_kernel<<<1, 1024, 0, s1>>>(degi, off, cur, dinv, dinv2, N);
        place_kernel<<<ceil_div(E, 256), 256, 0, s1>>>(src, dst, dinv, cur, csrc, cw, E);
        cudaEventRecord(g_hx.e2, s1);
        prep_kernel<<<14036, 256, 0, s0>>>(W[0], W[1], W[2], W[3], W[4], W[5], P1, P2,
                                           wgt, p1h, p1l, p2h, x, xs, lms, lms2);
        cudaEventRecord(g_hx.e1, s0);
        hgcn_gemm_kernel<<<dim3(gemm_mx, 1), 256, GCN_SMEM, s0>>>(
            x, FF, wgt, DD, h, DD, N, DD, 16, lms);
        cudaStreamWaitEvent(s1, g_hx.e1, 0);
        cudaStreamWaitEvent(s0, g_hx.e2, 0);
    } else {
        zero_degi_kernel<<<ceil_div(N, 256), 256, 0, s0>>>(degi, N);
        degi_kernel<<<ceil_div(E, 256), 256, 0, s0>>>(dst, degi, E);
        scandinv_kernel<<<1, 1024, 0, s0>>>(degi, off, cur, dinv, dinv2, N);
        place_kernel<<<ceil_div(E, 256), 256, 0, s0>>>(src, dst, dinv, cur, csrc, cw, E);
        prep_kernel<<<14036, 256, 0, s0>>>(W[0], W[1], W[2], W[3], W[4], W[5], P1, P2,
                                           wgt, p1h, p1l, p2h, x, xs, lms, lms2);
        hgcn_gemm_kernel<<<dim3(gemm_mx, 1), 256, GCN_SMEM, s0>>>(
            x, FF, wgt, DD, h, DD, N, DD, 16, lms);
    }

    auto run_branch = [&](cudaStream_t st, const float* xin, const float* lmsb, float* hb,
                          int wbase, const float* const* bb, float* nbuf, float* gpool,
                          bool skipFirstGemm) {
        const float* in = xin;
        int lda = FF;
        for (int l = 0; l < 3; l++) {
            float* slice = nbuf + l * DD;
            size_t woff = (size_t)(wbase + l) * 16384;
            if (!(l == 0 && skipFirstGemm)) {
                int fl = (l == 0) ? 16 : 8;
                hgcn_gemm_kernel<<<dim3(gemm_mx, 1), 256, GCN_SMEM, st>>>(
                    in, lda, wgt + woff, DD,
                    hb, DD, N, DD, fl, lmsb);
            }
            gather_kernel<<<ceil_div(nwarp_threads, 256), 256, 0, st>>>(
                hb, off, degi, csrc, cw, dinv2, bb[l], slice, N);
            in = slice;
            lda = EDIM;
        }
        pool_kernel<<<GG, EDIM, 0, st>>>(nbuf, batch, gpool, GFS_LD, N);
    };

    const float* bf[3]  = {bv[0], bv[1], bv[2]};
    const float* bs_[3] = {bv[3], bv[4], bv[5]};

    const size_t off0 = 0;
    const size_t off1 = (size_t)GG * EDIM;
    const size_t off2 = 2 * (size_t)GG * EDIM;
    const size_t off3 = off2 + (size_t)N * EDIM;
    const size_t off4 = off3 + (size_t)GG * EDIM;

    const int ggrid = ceil_div(GG, 128);
    const int gwarp_threads = GG * 32;
    float* ghid0 = ghid;
    float* ghid1 = ghid + (size_t)GG * EDIM;
    float* ghid3 = ghid + 2 * (size_t)GG * EDIM;
    float* gf = gfs;           // cols [0,384) of gfs
    float* gs = gfs + EDIM;    // cols [384,768)

    // ---------------- stream s1: structure branch + out4 + out3 ------------
    run_branch(s1, xs, lms2, h2, 3, bs_, ns, gs, false);
    if (fork) cudaEventRecord(g_hx.eGS, s1);

    // out4: P1 (fp16 MODE0), P2 (fp16 MODE1), expmap
    hgemm_kernel<0><<<dim3(gemm_mx, 3), 256, 5 * ASZ, s1>>>(
        ns, nullptr, nullptr, EDIM, p1h, p1l, EDIM,
        nullptr, hid2h, hid2l, EDIM, N, EDIM);
    hgemm_kernel<1><<<dim3(gemm_mx, 3), 256, 4 * ASZ, s1>>>(
        nullptr, hid2h, hid2l, EDIM, p2h, nullptr, EDIM,
        out + off4, nullptr, nullptr, EDIM, N, EDIM);
    expmap_proj_kernel<<<ceil_div(nwarp_threads, 256), 256, 0, s1>>>(out + off4, N);

    // out3: mlp(gs, P1, P2)   (gs slice of gfs, lda=768)
    sgemm_kernel<<<dim3(ggrid, 3), 256, 0, s1>>>(gs, GFS_LD, P1, ghid3, EDIM, GG, EDIM, EDIM, 1);
    sgemm_kernel<<<dim3(ggrid, 3), 256, 0, s1>>>(ghid3, EDIM, P2, out + off3, EDIM,
                                                 GG, EDIM, EDIM, 0);
    expmap_proj_kernel<<<ceil_div(gwarp_threads, 256), 256, 0, s1>>>(out + off3, GG);
    if (fork) cudaEventRecord(g_hx.eEnd, s1);

    // ---------------- stream 0: feature branch + out2 + out1 + out0 --------
    run_branch(s0, x, lms, h, 0, bf, nf, gf, /*skipFirstGemm=*/true);

    // out2 head
    hgemm_kernel<0><<<dim3(gemm_mx, 3), 256, 5 * ASZ, s0>>>(
        nf, nullptr, nullptr, EDIM, p1h, p1l, EDIM,
        nullptr, hidh, hidl, EDIM, N, EDIM);
    hgemm_kernel<1><<<dim3(gemm_mx, 3), 256, 4 * ASZ, s0>>>(
        nullptr, hidh, hidl, EDIM, p2h, nullptr, EDIM,
        out + off2, nullptr, nullptr, EDIM, N, EDIM);
    expmap_proj_kernel<<<ceil_div(nwarp_threads, 256), 256, 0, s0>>>(out + off2, N);

    // out1: mlp(gf, P1, P2)  (gf slice of gfs, lda=768)
    sgemm_kernel<<<dim3(ggrid, 3), 256, 0, s0>>>(gf, GFS_LD, P1, ghid1, EDIM, GG, EDIM, EDIM, 1);
    sgemm_kernel<<<dim3(ggrid, 3), 256, 0, s0>>>(ghid1, EDIM, P2, out + off1, EDIM,
                                                 GG, EDIM, EDIM, 0);
    expmap_proj_kernel<<<ceil_div(gwarp_threads, 256), 256, 0, s0>>>(out + off1, GG);

    // out0: e( relu(gfs @ G1 [K=768]) @ G2 )  -- needs gs pool from s1
    if (fork) cudaStreamWaitEvent(s0, g_hx.eGS, 0);
    sgemm_kernel<<<dim3(ggrid, 3), 256, 0, s0>>>(gfs, GFS_LD, G1, ghid0, EDIM,
                                                 GG, EDIM, 2 * EDIM, 1);
    sgemm_kernel<<<dim3(ggrid, 3), 256, 0, s0>>>(ghid0, EDIM, G2, out + off0, EDIM,
                                                 GG, EDIM, EDIM, 0);
    expmap_proj_kernel<<<ceil_div(gwarp_threads, 256), 256, 0, s0>>>(out + off0, GG);

    if (fork) cudaStreamWaitEvent(s0, g_hx.eEnd, 0);
}

// round 17
// speedup vs baseline: 1.1876x; 1.1011x over previous
#include <cuda_runtime.h>
#include <cuda_bf16.h>
#include <cuda_fp16.h>
#include <cstdint>
#include <cstddef>

// Problem constants (fixed by the reference)
#define NN 50000
#define EE 600000
#define GG 512
#define FF 128
#define DD 128
#define EDIM 384
#define GFS_LD 768

// ---------------------------------------------------------------------------
// Scratch (device globals -- no allocation allowed in kernel_launch)
// ---------------------------------------------------------------------------
__device__ __align__(16) float g_h   [NN * DD];
__device__ __align__(16) float g_h2  [NN * DD];
__device__ __align__(16) float g_nf  [NN * EDIM];
__device__ __align__(16) float g_ns  [NN * EDIM];
__device__ __align__(16) __half g_hidh [NN * EDIM];
__device__ __align__(16) __half g_hid2h[NN * EDIM];
__device__ float g_lms [NN];
__device__ float g_lms2[NN];
__device__ int   g_degi[NN];
__device__ float g_dinv[NN];
__device__ float g_dinv2[NN];
__device__ int   g_off [NN];
__device__ int   g_cur [NN];
__device__ int   g_csrc[EE];
__device__ float g_cw  [EE];
__device__ __align__(16) float g_gfs [GG * GFS_LD];   // [gf | gs] concat rows
__device__ __align__(16) float g_ghid[3 * GG * EDIM];
// GCN weights: single fp16, transposed [N,K], 6 layers of 16384
__device__ __align__(16) __half g_wgt[98304];
// fp16 head weights, transposed [N,K]: P1, P2 single fp16
__device__ __align__(16) __half g_p1h[147456];
__device__ __align__(16) __half g_p2h[147456];

// ---------------------------------------------------------------------------
// Static-init stream/event resources
// ---------------------------------------------------------------------------
struct HxStreams {
    cudaStream_t s1 = nullptr;
    cudaEvent_t eFork = nullptr, e1 = nullptr, e2 = nullptr;
    cudaEvent_t eGS = nullptr, eEnd = nullptr;
    bool ok = false;
    HxStreams() {
        ok = (cudaStreamCreateWithFlags(&s1, cudaStreamNonBlocking) == cudaSuccess)
          && (cudaEventCreateWithFlags(&eFork, cudaEventDisableTiming) == cudaSuccess)
          && (cudaEventCreateWithFlags(&e1,   cudaEventDisableTiming) == cudaSuccess)
          && (cudaEventCreateWithFlags(&e2,   cudaEventDisableTiming) == cudaSuccess)
          && (cudaEventCreateWithFlags(&eGS,  cudaEventDisableTiming) == cudaSuccess)
          && (cudaEventCreateWithFlags(&eEnd, cudaEventDisableTiming) == cudaSuccess);
    }
};
static HxStreams g_hx;

// ---------------------------------------------------------------------------
// Helpers
// ---------------------------------------------------------------------------
__device__ __forceinline__ void ldmx4(uint32_t* r, uint32_t addr) {
    asm volatile("ldmatrix.sync.aligned.m8n8.x4.shared.b16 {%0,%1,%2,%3}, [%4];"
                 : "=r"(r[0]), "=r"(r[1]), "=r"(r[2]), "=r"(r[3]) : "r"(addr));
}
__device__ __forceinline__ void ldmx2(uint32_t* r, uint32_t addr) {
    asm volatile("ldmatrix.sync.aligned.m8n8.x2.shared.b16 {%0,%1}, [%2];"
                 : "=r"(r[0]), "=r"(r[1]) : "r"(addr));
}
__device__ __forceinline__ void mmaf16(float* d, const uint32_t* a, const uint32_t* b) {
    asm volatile("mma.sync.aligned.m16n8k16.row.col.f32.f16.f16.f32 "
                 "{%0,%1,%2,%3}, {%4,%5,%6,%7}, {%8,%9}, {%0,%1,%2,%3};"
                 : "+f"(d[0]), "+f"(d[1]), "+f"(d[2]), "+f"(d[3])
                 : "r"(a[0]), "r"(a[1]), "r"(a[2]), "r"(a[3]), "r"(b[0]), "r"(b[1]));
}
__device__ __forceinline__ uint32_t smem_u32(const void* p) {
    uint32_t a;
    asm("{ .reg .u64 t; cvta.to.shared.u64 t, %1; cvt.u32.u64 %0, t; }" : "=r"(a) : "l"(p));
    return a;
}
__device__ __forceinline__ void cpa16(uint32_t saddr, const void* gaddr) {
    asm volatile("cp.async.cg.shared.global [%0], [%1], 16;" :: "r"(saddr), "l"(gaddr));
}

// ---------------------------------------------------------------------------
// prep kernel: weight transpose (blocks 0..1535), logmap scales after.
// All weights -> single fp16 transposed [N,K].
// ---------------------------------------------------------------------------
__global__ void prep_kernel(const float* __restrict__ W0, const float* __restrict__ W1,
                            const float* __restrict__ W2, const float* __restrict__ W3,
                            const float* __restrict__ W4, const float* __restrict__ W5,
                            const float* __restrict__ P1, const float* __restrict__ P2,
                            __half* __restrict__ wgt,
                            __half* __restrict__ p1h, __half* __restrict__ p2h,
                            const float* __restrict__ x, const float* __restrict__ xs,
                            float* __restrict__ lms, float* __restrict__ lms2)
{
    int b = blockIdx.x;
    if (b < 1536) {
        int idx = b * 256 + threadIdx.x;
        if (idx < 98304) {
            int m = idx >> 14; int li = idx & 16383;
            const float* ws[6] = {W0, W1, W2, W3, W4, W5};
            int k = li / 128, n = li % 128;
            wgt[(m << 14) + n * 128 + k] = __float2half_rn(ws[m][li]);
        } else if (idx < 245760) {
            int li = idx - 98304;
            int k = li / 384, n = li % 384;
            p1h[n * 384 + k] = __float2half_rn(P1[li]);
        } else {
            int li = idx - 245760;
            int k = li / 384, n = li % 384;
            p2h[n * 384 + k] = __float2half_rn(P2[li]);
        }
    } else {
        int rb = b - 1536;
        const float* xin = x; float* sout = lms;
        if (rb >= 6250) { rb -= 6250; xin = xs; sout = lms2; }
        int w = rb * 8 + (threadIdx.x >> 5);
        if (w >= NN) return;
        int lane = threadIdx.x & 31;
        const float4 v = *reinterpret_cast<const float4*>(xin + (size_t)w * FF + lane * 4);
        float ss = v.x * v.x + v.y * v.y + v.z * v.z + v.w * v.w;
#pragma unroll
        for (int o = 16; o; o >>= 1) ss += __shfl_xor_sync(0xffffffffu, ss, o);
        if (lane == 0) {
            float nrm = sqrtf(ss);
            float n1  = fmaxf(nrm, 1e-15f);
            float arg = fminf(n1, 1.0f - 1e-15f);
            sout[w] = atanhf(arg) / n1;
        }
    }
}

// ---------------------------------------------------------------------------
// fp16 2-MMA GCN GEMM: A fp32 -> fp16 hi/lo split on the fly (A effectively
// exact); B single fp16; C = Ah*B + Al*B.
// flags: 8=RELU on A, 16=scale A rows by ascale[].
// smem: [Ah][Al][B0][B1] = 4*ASZ
// ---------------------------------------------------------------------------
#define ROWB 80
#define ASZ (128 * ROWB)
#define GCN_SMEM (4 * ASZ)
#define HEAD_SMEM (3 * ASZ)

__global__ void __launch_bounds__(256, 2)
hgcn_gemm_kernel(const float* __restrict__ A, int lda,
                 const __half* __restrict__ Bw, int ldb,
                 float* __restrict__ C, int ldc,
                 int M, int K, int flags,
                 const float* __restrict__ ascale)
{
    extern __shared__ __align__(16) char sm[];
    const int tid  = threadIdx.x;
    const int wid  = tid >> 5;
    const int lane = tid & 31;
    const int wm = wid & 1;
    const int wn = wid >> 1;
    const int bm = blockIdx.x * 128;
    const int bn = blockIdx.y * 128;
    const uint32_t sbase = smem_u32(sm);
    const uint32_t sB0 = sbase + 2 * ASZ;

    int arow[4], akc[4];
#pragma unroll
    for (int it = 0; it < 4; ++it) {
        int idx = tid + it * 256;
        arow[it] = idx >> 3;
        akc[it]  = (idx & 7) << 2;
    }
    int brow[2], bc16[2];
#pragma unroll
    for (int it = 0; it < 2; ++it) {
        int idx = tid + it * 256;
        brow[it] = idx >> 2;
        bc16[it] = (idx & 3) << 4;
    }

    float acc[4][4][4];
#pragma unroll
    for (int i = 0; i < 4; i++)
#pragma unroll
        for (int j = 0; j < 4; j++)
#pragma unroll
            for (int l = 0; l < 4; l++) acc[i][j][l] = 0.0f;

    const int nch = K >> 5;
    float4 fr[4];
    float  asc[4];

#pragma unroll
    for (int it = 0; it < 4; ++it) {
        int gr = bm + arow[it];
        fr[it] = make_float4(0.f, 0.f, 0.f, 0.f);
        asc[it] = 1.0f;
        if (gr < M) {
            fr[it] = *reinterpret_cast<const float4*>(A + (size_t)gr * lda + akc[it]);
            if (flags & 16) asc[it] = ascale[gr];
        }
    }
#pragma unroll
    for (int it = 0; it < 2; ++it) {
        uint32_t so = sB0 + brow[it] * ROWB + bc16[it];
        size_t gb = ((size_t)(bn + brow[it]) * ldb) * 2 + bc16[it];
        cpa16(so, (const char*)Bw + gb);
    }
    asm volatile("cp.async.commit_group;" ::: "memory");

    for (int ch = 0; ch < nch; ++ch) {
#pragma unroll
        for (int it = 0; it < 4; ++it) {
            float4 v = fr[it];
            float s = asc[it];
            v.x *= s; v.y *= s; v.z *= s; v.w *= s;
            if (flags & 8) {
                v.x = fmaxf(v.x, 0.f); v.y = fmaxf(v.y, 0.f);
                v.z = fmaxf(v.z, 0.f); v.w = fmaxf(v.w, 0.f);
            }
            __half2 h01 = __float22half2_rn(make_float2(v.x, v.y));
            __half2 h23 = __float22half2_rn(make_float2(v.z, v.w));
            float2 f01 = __half22float2(h01);
            float2 f23 = __half22float2(h23);
            __half2 l01 = __float22half2_rn(make_float2(v.x - f01.x, v.y - f01.y));
            __half2 l23 = __float22half2_rn(make_float2(v.z - f23.x, v.w - f23.y));
            int off = arow[it] * ROWB + akc[it] * 2;
            uint2 uh, ul;
            uh.x = *reinterpret_cast<uint32_t*>(&h01);
            uh.y = *reinterpret_cast<uint32_t*>(&h23);
            ul.x = *reinterpret_cast<uint32_t*>(&l01);
            ul.y = *reinterpret_cast<uint32_t*>(&l23);
            *reinterpret_cast<uint2*>(sm + off)       = uh;
            *reinterpret_cast<uint2*>(sm + ASZ + off) = ul;
        }
        asm volatile("cp.async.wait_group 0;" ::: "memory");
        __syncthreads();

        if (ch + 1 < nch) {
            int k0 = (ch + 1) << 5;
#pragma unroll
            for (int it = 0; it < 4; ++it) {
                int gr = bm + arow[it];
                fr[it] = make_float4(0.f, 0.f, 0.f, 0.f);
                if (gr < M)
                    fr[it] = *reinterpret_cast<const float4*>(A + (size_t)gr * lda + k0 + akc[it]);
            }
            uint32_t so0 = sB0 + ((ch + 1) & 1) * ASZ;
#pragma unroll
            for (int it = 0; it < 2; ++it) {
                uint32_t so = so0 + brow[it] * ROWB + bc16[it];
                size_t gb = ((size_t)(bn + brow[it]) * ldb + k0) * 2 + bc16[it];
                cpa16(so, (const char*)Bw + gb);
            }
            asm volatile("cp.async.commit_group;" ::: "memory");
        }

        const uint32_t sB = sB0 + (ch & 1) * ASZ;
#pragma unroll
        for (int ks = 0; ks < 2; ++ks) {
            uint32_t bf[4][2];
#pragma unroll
            for (int nt = 0; nt < 4; ++nt) {
                uint32_t off = (uint32_t)((wn * 32 + nt * 8 + (lane & 7)) * ROWB
                                          + (ks * 16 + ((lane >> 3) & 1) * 8) * 2);
                ldmx2(bf[nt], sB + off);
            }
#pragma unroll
            for (int mt = 0; mt < 4; ++mt) {
                uint32_t off = (uint32_t)((wm * 64 + mt * 16 + (lane & 15)) * ROWB
                                          + (ks * 16 + ((lane >> 4) & 1) * 8) * 2);
                uint32_t ah[4], al[4];
                ldmx4(ah, sbase + off);
                ldmx4(al, sbase + ASZ + off);
#pragma unroll
                for (int nt = 0; nt < 4; ++nt) {
                    mmaf16(acc[mt][nt], ah, bf[nt]);
                    mmaf16(acc[mt][nt], al, bf[nt]);
                }
            }
        }
        __syncthreads();
    }

    const int groupID = lane >> 2;
    const int tid4 = lane & 3;
#pragma unroll
    for (int mt = 0; mt < 4; ++mt) {
#pragma unroll
        for (int half = 0; half < 2; ++half) {
            int gr = bm + wm * 64 + mt * 16 + groupID + half * 8;
            if (gr >= M) continue;
#pragma unroll
            for (int nt = 0; nt < 4; ++nt) {
                int gc = bn + wn * 32 + nt * 8 + tid4 * 2;
                float2 r = make_float2(acc[mt][nt][half * 2], acc[mt][nt][half * 2 + 1]);
                *reinterpret_cast<float2*>(C + (size_t)gr * ldc + gc) = r;
            }
        }
    }
}

// ---------------------------------------------------------------------------
// Plain fp16 1-MMA head GEMM.
// MODE 0: A fp32 (relu + convert to fp16); epilogue relu + fp16 store (Ch).
// MODE 1: A fp16; epilogue fp32 store (C).
// smem: [A][B0][B1] = 3*ASZ
// ---------------------------------------------------------------------------
template<int MODE>
__global__ void __launch_bounds__(256, 2)
hgemm_kernel(const float* __restrict__ A, const __half* __restrict__ Ah, int lda,
             const __half* __restrict__ Bw, int ldb,
             float* __restrict__ C, __half* __restrict__ Ch,
             int ldc, int M, int K)
{
    extern __shared__ __align__(16) char sm[];
    const int tid  = threadIdx.x;
    const int wid  = tid >> 5;
    const int lane = tid & 31;
    const int wm = wid & 1;
    const int wn = wid >> 1;
    const int bm = blockIdx.x * 128;
    const int bn = blockIdx.y * 128;
    const uint32_t sbase = smem_u32(sm);
    const uint32_t sB0 = sbase + ASZ;

    int arow[4], akc[4];
#pragma unroll
    for (int it = 0; it < 4; ++it) {
        int idx = tid + it * 256;
        arow[it] = idx >> 3;
        akc[it]  = (idx & 7) << 2;
    }
    int brow[2], bc16[2];
#pragma unroll
    for (int it = 0; it < 2; ++it) {
        int idx = tid + it * 256;
        brow[it] = idx >> 2;
        bc16[it] = (idx & 3) << 4;
    }

    float acc[4][4][4];
#pragma unroll
    for (int i = 0; i < 4; i++)
#pragma unroll
        for (int j = 0; j < 4; j++)
#pragma unroll
            for (int l = 0; l < 4; l++) acc[i][j][l] = 0.0f;

    const int nch = K >> 5;
    float4 fr[4];
    uint2  ur[4];

#pragma unroll
    for (int it = 0; it < 4; ++it) {
        int gr = bm + arow[it];
        if (MODE == 0) {
            fr[it] = make_float4(0.f, 0.f, 0.f, 0.f);
            if (gr < M) fr[it] = *reinterpret_cast<const float4*>(A + (size_t)gr * lda + akc[it]);
        } else {
            ur[it] = make_uint2(0, 0);
            if (gr < M) ur[it] = *reinterpret_cast<const uint2*>(Ah + (size_t)gr * lda + akc[it]);
        }
    }
#pragma unroll
    for (int it = 0; it < 2; ++it) {
        uint32_t so = sB0 + brow[it] * ROWB + bc16[it];
        size_t gb = ((size_t)(bn + brow[it]) * ldb) * 2 + bc16[it];
        cpa16(so, (const char*)Bw + gb);
    }
    asm volatile("cp.async.commit_group;" ::: "memory");

    for (int ch = 0; ch < nch; ++ch) {
#pragma unroll
        for (int it = 0; it < 4; ++it) {
            int off = arow[it] * ROWB + akc[it] * 2;
            if (MODE == 0) {
                float4 v = fr[it];
                v.x = fmaxf(v.x, 0.f); v.y = fmaxf(v.y, 0.f);
                v.z = fmaxf(v.z, 0.f); v.w = fmaxf(v.w, 0.f);
                __half2 h01 = __float22half2_rn(make_float2(v.x, v.y));
                __half2 h23 = __float22half2_rn(make_float2(v.z, v.w));
                uint2 u;
                u.x = *reinterpret_cast<uint32_t*>(&h01);
                u.y = *reinterpret_cast<uint32_t*>(&h23);
                *reinterpret_cast<uint2*>(sm + off) = u;
            } else {
                *reinterpret_cast<uint2*>(sm + off) = ur[it];
            }
        }
        asm volatile("cp.async.wait_group 0;" ::: "memory");
        __syncthreads();

        if (ch + 1 < nch) {
            int k0 = (ch + 1) << 5;
#pragma unroll
            for (int it = 0; it < 4; ++it) {
                int gr = bm + arow[it];
                if (MODE == 0) {
                    fr[it] = make_float4(0.f, 0.f, 0.f, 0.f);
                    if (gr < M)
                        fr[it] = *reinterpret_cast<const float4*>(A + (size_t)gr * lda + k0 + akc[it]);
                } else {
                    ur[it] = make_uint2(0, 0);
                    if (gr < M)
                        ur[it] = *reinterpret_cast<const uint2*>(Ah + (size_t)gr * lda + k0 + akc[it]);
                }
            }
            uint32_t so0 = sB0 + ((ch + 1) & 1) * ASZ;
#pragma unroll
            for (int it = 0; it < 2; ++it) {
                uint32_t so = so0 + brow[it] * ROWB + bc16[it];
                size_t gb = ((size_t)(bn + brow[it]) * ldb + k0) * 2 + bc16[it];
                cpa16(so, (const char*)Bw + gb);
            }
            asm volatile("cp.async.commit_group;" ::: "memory");
        }

        const uint32_t sB = sB0 + (ch & 1) * ASZ;
#pragma unroll
        for (int ks = 0; ks < 2; ++ks) {
            uint32_t bf[4][2];
#pragma unroll
            for (int nt = 0; nt < 4; ++nt) {
                uint32_t off = (uint32_t)((wn * 32 + nt * 8 + (lane & 7)) * ROWB
                                          + (ks * 16 + ((lane >> 3) & 1) * 8) * 2);
                ldmx2(bf[nt], sB + off);
            }
#pragma unroll
            for (int mt = 0; mt < 4; ++mt) {
                uint32_t off = (uint32_t)((wm * 64 + mt * 16 + (lane & 15)) * ROWB
                                          + (ks * 16 + ((lane >> 4) & 1) * 8) * 2);
                uint32_t a0[4];
                ldmx4(a0, sbase + off);
#pragma unroll
                for (int nt = 0; nt < 4; ++nt)
                    mmaf16(acc[mt][nt], a0, bf[nt]);
            }
        }
        __syncthreads();
    }

    const int groupID = lane >> 2;
    const int tid4 = lane & 3;
#pragma unroll
    for (int mt = 0; mt < 4; ++mt) {
#pragma unroll
        for (int half = 0; half < 2; ++half) {
            int gr = bm + wm * 64 + mt * 16 + groupID + half * 8;
            if (gr >= M) continue;
#pragma unroll
            for (int nt = 0; nt < 4; ++nt) {
                int gc = bn + wn * 32 + nt * 8 + tid4 * 2;
                float2 r = make_float2(acc[mt][nt][half * 2], acc[mt][nt][half * 2 + 1]);
                if (MODE == 0) {
                    r.x = fmaxf(r.x, 0.f); r.y = fmaxf(r.y, 0.f);
                    __half2 hh = __float22half2_rn(r);
                    *reinterpret_cast<__half2*>(Ch + (size_t)gr * ldc + gc) = hh;
                } else {
                    *reinterpret_cast<float2*>(C + (size_t)gr * ldc + gc) = r;
                }
            }
        }
    }
}

// ---------------------------------------------------------------------------
// CSR build + graph kernels
// ---------------------------------------------------------------------------
__global__ void zero_degi_kernel(int* __restrict__ degi, int n)
{
    int t = blockIdx.x * blockDim.x + threadIdx.x;
    if (t < n) degi[t] = 0;
}

__global__ void degi_kernel(const int* __restrict__ dst, int* __restrict__ degi, int e)
{
    int t = blockIdx.x * blockDim.x + threadIdx.x;
    if (t < e) atomicAdd(&degi[dst[t]], 1);
}

__global__ void __launch_bounds__(1024)
scandinv_kernel(const int* __restrict__ degi, int* __restrict__ off,
                int* __restrict__ cur, float* __restrict__ dinv,
                float* __restrict__ dinv2, int n)
{
    __shared__ int warpsum[32];
    __shared__ int carry;
    const int tid = threadIdx.x;
    const int lane = tid & 31;
    const int wrp = tid >> 5;
    if (tid == 0) carry = 0;
    __syncthreads();
    for (int base = 0; base < n; base += 1024) {
        int i = base + tid;
        int v = (i < n) ? degi[i] : 0;
        if (i < n) {
            float d  = (float)v + 1.0f;
            float di = 1.0f / sqrtf(d);
            dinv[i]  = di;
            dinv2[i] = di * di;
        }
        int x = v;
#pragma unroll
        for (int o = 1; o < 32; o <<= 1) {
            int y = __shfl_up_sync(0xffffffffu, x, o);
            if (lane >= o) x += y;
        }
        if (lane == 31) warpsum[wrp] = x;
        __syncthreads();
        if (tid < 32) {
            int s = warpsum[tid];
#pragma unroll
            for (int o = 1; o < 32; o <<= 1) {
                int y = __shfl_up_sync(0xffffffffu, s, o);
                if (tid >= o) s += y;
            }
            warpsum[tid] = s;
        }
        __syncthreads();
        int incl = x + (wrp ? warpsum[wrp - 1] : 0);
        int excl = incl - v + carry;
        if (i < n) { off[i] = excl; cur[i] = excl; }
        __syncthreads();
        if (tid == 1023) carry += incl;
        __syncthreads();
    }
}

__global__ void place_kernel(const int* __restrict__ src, const int* __restrict__ dst,
                             const float* __restrict__ dinv,
                             int* __restrict__ cur,
                             int* __restrict__ csrc, float* __restrict__ cw, int e)
{
    int t = blockIdx.x * blockDim.x + threadIdx.x;
    if (t >= e) return;
    int s = src[t], d = dst[t];
    int pos = atomicAdd(&cur[d], 1);
    csrc[pos] = s;
    cw[pos]   = dinv[s] * dinv[d];
}

// gather aggregation: one warp per node, 8/4/1 unroll ladder (MLP up to 8)
__global__ void gather_kernel(const float* __restrict__ h,
                              const int* __restrict__ off, const int* __restrict__ degi,
                              const int* __restrict__ csrc, const float* __restrict__ cw,
                              const float* __restrict__ dinv2, const float* __restrict__ bias,
                              float* __restrict__ slice, int n)
{
    int t = blockIdx.x * blockDim.x + threadIdx.x;
    int w = t >> 5;
    if (w >= n) return;
    int lane = t & 31;
    int c = lane << 2;
    const float4 hv = *reinterpret_cast<const float4*>(h + (size_t)w * DD + c);
    const float4 bb = *reinterpret_cast<const float4*>(bias + c);
    float d2 = dinv2[w];
    float4 acc = make_float4(hv.x * d2 + bb.x, hv.y * d2 + bb.y,
                             hv.z * d2 + bb.z, hv.w * d2 + bb.w);
    int j   = off[w];
    int end = j + degi[w];
    for (; j + 8 <= end; j += 8) {
        int   ii[8];
        float ww[8];
#pragma unroll
        for (int q = 0; q < 8; ++q) { ii[q] = __ldg(csrc + j + q); ww[q] = __ldg(cw + j + q); }
        float4 vv[8];
#pragma unroll
        for (int q = 0; q < 8; ++q)
            vv[q] = *reinterpret_cast<const float4*>(h + (size_t)ii[q] * DD + c);
#pragma unroll
        for (int q = 0; q < 8; ++q) {
            acc.x += ww[q] * vv[q].x; acc.y += ww[q] * vv[q].y;
            acc.z += ww[q] * vv[q].z; acc.w += ww[q] * vv[q].w;
        }
    }
    for (; j + 4 <= end; j += 4) {
        int   i0 = __ldg(csrc + j),     i1 = __ldg(csrc + j + 1);
        int   i2 = __ldg(csrc + j + 2), i3 = __ldg(csrc + j + 3);
        float w0 = __ldg(cw + j),       w1 = __ldg(cw + j + 1);
        float w2 = __ldg(cw + j + 2),   w3 = __ldg(cw + j + 3);
        float4 v0 = *reinterpret_cast<const float4*>(h + (size_t)i0 * DD + c);
        float4 v1 = *reinterpret_cast<const float4*>(h + (size_t)i1 * DD + c);
        float4 v2 = *reinterpret_cast<const float4*>(h + (size_t)i2 * DD + c);
        float4 v3 = *reinterpret_cast<const float4*>(h + (size_t)i3 * DD + c);
        acc.x += w0 * v0.x + w1 * v1.x + w2 * v2.x + w3 * v3.x;
        acc.y += w0 * v0.y + w1 * v1.y + w2 * v2.y + w3 * v3.y;
        acc.z += w0 * v0.z + w1 * v1.z + w2 * v2.z + w3 * v3.z;
        acc.w += w0 * v0.w + w1 * v1.w + w2 * v2.w + w3 * v3.w;
    }
    for (; j < end; ++j) {
        int s    = __ldg(csrc + j);
        float wt = __ldg(cw + j);
        float4 v = *reinterpret_cast<const float4*>(h + (size_t)s * DD + c);
        acc.x += wt * v.x; acc.y += wt * v.y;
        acc.z += wt * v.z; acc.w += wt * v.w;
    }
    *reinterpret_cast<float4*>(slice + (size_t)w * EDIM + c) = acc;
}

__global__ void expmap_proj_kernel(float* __restrict__ p, int rows)
{
    int t = blockIdx.x * blockDim.x + threadIdx.x;
    int w = t >> 5;
    if (w >= rows) return;
    int lane = t & 31;
    float* r = p + (size_t)w * EDIM;
    float4 v0 = *reinterpret_cast<const float4*>(r + lane * 4);
    float4 v1 = *reinterpret_cast<const float4*>(r + lane * 4 + 128);
    float4 v2 = *reinterpret_cast<const float4*>(r + lane * 4 + 256);
    float ss = v0.x*v0.x + v0.y*v0.y + v0.z*v0.z + v0.w*v0.w
             + v1.x*v1.x + v1.y*v1.y + v1.z*v1.z + v1.w*v1.w
             + v2.x*v2.x + v2.y*v2.y + v2.z*v2.z + v2.w*v2.w;
#pragma unroll
    for (int o = 16; o; o >>= 1) ss += __shfl_xor_sync(0xffffffffu, ss, o);
    float nrm = sqrtf(ss);
    float n1  = fmaxf(nrm, 1e-15f);
    float s   = tanhf(n1) / n1;
    float yn  = s * nrm;
    const float maxn = 1.0f - 4e-3f;
    if (yn > maxn) s = s * maxn / yn;
    v0.x*=s; v0.y*=s; v0.z*=s; v0.w*=s;
    v1.x*=s; v1.y*=s; v1.z*=s; v1.w*=s;
    v2.x*=s; v2.y*=s; v2.z*=s; v2.w*=s;
    *reinterpret_cast<float4*>(r + lane * 4      ) = v0;
    *reinterpret_cast<float4*>(r + lane * 4 + 128) = v1;
    *reinterpret_cast<float4*>(r + lane * 4 + 256) = v2;
}

// pool of relu(nf): writes 384 cols at out[g*ldo + t]
__global__ void pool_kernel(const float* __restrict__ nf, const int* __restrict__ batch,
                            float* __restrict__ out, int ldo, int n)
{
    int g = blockIdx.x;
    int t = threadIdx.x;
    int lo = 0, hi = n;
    while (lo < hi) { int m = (lo + hi) >> 1; if (batch[m] < g) lo = m + 1; else hi = m; }
    int s0 = lo;
    hi = n;
    while (lo < hi) { int m = (lo + hi) >> 1; if (batch[m] < g + 1) lo = m + 1; else hi = m; }
    int s1 = lo;
    float acc = 0.0f;
    for (int i = s0; i < s1; i++) acc += fmaxf(nf[(size_t)i * EDIM + t], 0.0f);
    out[(size_t)g * ldo + t] = acc;
}

// ---------------------------------------------------------------------------
// fp32 SGEMM (tiny graph-level GEMMs, M=512). flags: 1=RELU, 2=ACCUM
// ---------------------------------------------------------------------------
__global__ void __launch_bounds__(256)
sgemm_kernel(const float* __restrict__ A, int lda,
             const float* __restrict__ B,
             float* __restrict__ C, int ldc,
             int M, int Nc, int K, int flags)
{
    __shared__ float As[16][132];
    __shared__ float Bs[16][128];
    const int tid = threadIdx.x;
    const int bm = blockIdx.x * 128;
    const int bn = blockIdx.y * 128;
    const int tx = tid & 15;
    const int ty = tid >> 4;

    float acc[8][8];
#pragma unroll
    for (int i = 0; i < 8; i++)
#pragma unroll
        for (int j = 0; j < 8; j++) acc[i][j] = 0.0f;

    for (int k0 = 0; k0 < K; k0 += 16) {
#pragma unroll
        for (int it = 0; it < 2; ++it) {
            int idx = tid + it * 256;
            int row = idx >> 2;
            int kc  = (idx & 3) << 2;
            int gr  = bm + row;
            float4 v = make_float4(0.f, 0.f, 0.f, 0.f);
            if (gr < M) v = *reinterpret_cast<const float4*>(A + (size_t)gr * lda + k0 + kc);
            As[kc + 0][row] = v.x; As[kc + 1][row] = v.y;
            As[kc + 2][row] = v.z; As[kc + 3][row] = v.w;
        }
#pragma unroll
        for (int it = 0; it < 2; ++it) {
            int idx = tid + it * 256;
            int kr  = idx >> 5;
            int nc  = (idx & 31) << 2;
            float4 v = *reinterpret_cast<const float4*>(B + (size_t)(k0 + kr) * Nc + bn + nc);
            *reinterpret_cast<float4*>(&Bs[kr][nc]) = v;
        }
        __syncthreads();
#pragma unroll
        for (int k = 0; k < 16; ++k) {
            float a[8], b[8];
#pragma unroll
            for (int i = 0; i < 8; i++) a[i] = As[k][ty * 8 + i];
#pragma unroll
            for (int j = 0; j < 8; j++) b[j] = Bs[k][tx * 8 + j];
#pragma unroll
            for (int i = 0; i < 8; i++)
#pragma unroll
                for (int j = 0; j < 8; j++) acc[i][j] = fmaf(a[i], b[j], acc[i][j]);
        }
        __syncthreads();
    }

#pragma unroll
    for (int i = 0; i < 8; i++) {
        int gr = bm + ty * 8 + i;
        if (gr >= M) break;
#pragma unroll
        for (int j = 0; j < 8; j += 4) {
            int gc = bn + tx * 8 + j;
            float4 r = make_float4(acc[i][j], acc[i][j+1], acc[i][j+2], acc[i][j+3]);
            if (flags & 2) {
                float4 o = *reinterpret_cast<const float4*>(C + (size_t)gr * ldc + gc);
                r.x += o.x; r.y += o.y; r.z += o.z; r.w += o.w;
            }
            if (flags & 1) {
                r.x = fmaxf(r.x, 0.f); r.y = fmaxf(r.y, 0.f);
                r.z = fmaxf(r.z, 0.f); r.w = fmaxf(r.w, 0.f);
            }
            *reinterpret_cast<float4*>(C + (size_t)gr * ldc + gc) = r;
        }
    }
}

// ---------------------------------------------------------------------------
// Host driver
// ---------------------------------------------------------------------------
static inline int ceil_div(int a, int b) { return (a + b - 1) / b; }

extern "C" void kernel_launch(void* const* d_in, const int* in_sizes, int n_in,
                              void* d_out, int out_size)
{
    (void)out_size;
    const float *x = nullptr, *xs = nullptr;
    const int *src = nullptr, *dst = nullptr, *batch = nullptr;
    const float *W[6] = {}; const float *bv[6] = {};
    const float *p147[3] = {}; const float *G1 = nullptr;
    int xi = 0, ei = 0, wi = 0, bi = 0, pi = 0;
    for (int i = 0; i < n_in; i++) {
        int s = in_sizes[i];
        const void* p = d_in[i];
        if (s == NN * FF)          { if (xi == 0) x = (const float*)p; else xs = (const float*)p; xi++; }
        else if (s == EE)          { if (ei == 0) src = (const int*)p; else dst = (const int*)p; ei++; }
        else if (s == NN)          { batch = (const int*)p; }
        else if (s == FF * DD)     { if (wi < 6) W[wi] = (const float*)p; wi++; }
        else if (s == DD)          { if (bi < 6) bv[bi] = (const float*)p; bi++; }
        else if (s == EDIM * EDIM) { if (pi < 3) p147[pi] = (const float*)p; pi++; }
        else if (s == 2 * EDIM * EDIM) { G1 = (const float*)p; }
    }
    const float* P1 = p147[0];
    const float* P2 = p147[1];
    const float* G2 = p147[2];

    float *h, *h2, *nf, *ns, *lms, *lms2, *dinv, *dinv2, *gfs, *ghid, *cw;
    int *degi, *off, *cur, *csrc;
    __half *wgt, *hidh, *hid2h, *p1h, *p2h;
    cudaGetSymbolAddress((void**)&h,    g_h);
    cudaGetSymbolAddress((void**)&h2,   g_h2);
    cudaGetSymbolAddress((void**)&nf,   g_nf);
    cudaGetSymbolAddress((void**)&ns,   g_ns);
    cudaGetSymbolAddress((void**)&hidh, g_hidh);
    cudaGetSymbolAddress((void**)&hid2h,g_hid2h);
    cudaGetSymbolAddress((void**)&lms,  g_lms);
    cudaGetSymbolAddress((void**)&lms2, g_lms2);
    cudaGetSymbolAddress((void**)&degi, g_degi);
    cudaGetSymbolAddress((void**)&dinv, g_dinv);
    cudaGetSymbolAddress((void**)&dinv2,g_dinv2);
    cudaGetSymbolAddress((void**)&off,  g_off);
    cudaGetSymbolAddress((void**)&cur,  g_cur);
    cudaGetSymbolAddress((void**)&csrc, g_csrc);
    cudaGetSymbolAddress((void**)&cw,   g_cw);
    cudaGetSymbolAddress((void**)&gfs,  g_gfs);
    cudaGetSymbolAddress((void**)&ghid, g_ghid);
    cudaGetSymbolAddress((void**)&wgt,  g_wgt);
    cudaGetSymbolAddress((void**)&p1h,  g_p1h);
    cudaGetSymbolAddress((void**)&p2h,  g_p2h);

    cudaFuncSetAttribute(hgcn_gemm_kernel, cudaFuncAttributeMaxDynamicSharedMemorySize, GCN_SMEM);
    cudaFuncSetAttribute(hgemm_kernel<0>, cudaFuncAttributeMaxDynamicSharedMemorySize, HEAD_SMEM);
    cudaFuncSetAttribute(hgemm_kernel<1>, cudaFuncAttributeMaxDynamicSharedMemorySize, HEAD_SMEM);

    float* out = (float*)d_out;
    const int E = EE, N = NN;

    const bool fork = g_hx.ok;
    cudaStream_t s0 = 0;
    cudaStream_t s1 = fork ? g_hx.s1 : (cudaStream_t)0;

    const int gemm_mx = ceil_div(N, 128);
    const int nwarp_threads = N * 32;

    // ---------------- prelude --------------------------------------------
    if (fork) {
        cudaEventRecord(g_hx.eFork, s0);
        cudaStreamWaitEvent(s1, g_hx.eFork, 0);
        zero_degi_kernel<<<ceil_div(N, 256), 256, 0, s1>>>(degi, N);
        degi_kernel<<<ceil_div(E, 256), 256, 0, s1>>>(dst, degi, E);
        scandinv_kernel<<<1, 1024, 0, s1>>>(degi, off, cur, dinv, dinv2, N);
        place_kernel<<<ceil_div(E, 256), 256, 0, s1>>>(src, dst, dinv, cur, csrc, cw, E);
        cudaEventRecord(g_hx.e2, s1);
        prep_kernel<<<14036, 256, 0, s0>>>(W[0], W[1], W[2], W[3], W[4], W[5], P1, P2,
                                           wgt, p1h, p2h, x, xs, lms, lms2);
        cudaEventRecord(g_hx.e1, s0);
        hgcn_gemm_kernel<<<dim3(gemm_mx, 1), 256, GCN_SMEM, s0>>>(
            x, FF, wgt, DD, h, DD, N, DD, 16, lms);
        cudaStreamWaitEvent(s1, g_hx.e1, 0);
        cudaStreamWaitEvent(s0, g_hx.e2, 0);
    } else {
        zero_degi_kernel<<<ceil_div(N, 256), 256, 0, s0>>>(degi, N);
        degi_kernel<<<ceil_div(E, 256), 256, 0, s0>>>(dst, degi, E);
        scandinv_kernel<<<1, 1024, 0, s0>>>(degi, off, cur, dinv, dinv2, N);
        place_kernel<<<ceil_div(E, 256), 256, 0, s0>>>(src, dst, dinv, cur, csrc, cw, E);
        prep_kernel<<<14036, 256, 0, s0>>>(W[0], W[1], W[2], W[3], W[4], W[5], P1, P2,
                                           wgt, p1h, p2h, x, xs, lms, lms2);
        hgcn_gemm_kernel<<<dim3(gemm_mx, 1), 256, GCN_SMEM, s0>>>(
            x, FF, wgt, DD, h, DD, N, DD, 16, lms);
    }

    auto run_branch = [&](cudaStream_t st, const float* xin, const float* lmsb, float* hb,
                          int wbase, const float* const* bb, float* nbuf, float* gpool,
                          bool skipFirstGemm) {
        const float* in = xin;
        int lda = FF;
        for (int l = 0; l < 3; l++) {
            float* slice = nbuf + l * DD;
            size_t woff = (size_t)(wbase + l) * 16384;
            if (!(l == 0 && skipFirstGemm)) {
                int fl = (l == 0) ? 16 : 8;
                hgcn_gemm_kernel<<<dim3(gemm_mx, 1), 256, GCN_SMEM, st>>>(
                    in, lda, wgt + woff, DD,
                    hb, DD, N, DD, fl, lmsb);
            }
            gather_kernel<<<ceil_div(nwarp_threads, 256), 256, 0, st>>>(
                hb, off, degi, csrc, cw, dinv2, bb[l], slice, N);
            in = slice;
            lda = EDIM;
        }
        pool_kernel<<<GG, EDIM, 0, st>>>(nbuf, batch, gpool, GFS_LD, N);
    };

    const float* bf[3]  = {bv[0], bv[1], bv[2]};
    const float* bs_[3] = {bv[3], bv[4], bv[5]};

    const size_t off0 = 0;
    const size_t off1 = (size_t)GG * EDIM;
    const size_t off2 = 2 * (size_t)GG * EDIM;
    const size_t off3 = off2 + (size_t)N * EDIM;
    const size_t off4 = off3 + (size_t)GG * EDIM;

    const int ggrid = ceil_div(GG, 128);
    const int gwarp_threads = GG * 32;
    float* ghid0 = ghid;
    float* ghid1 = ghid + (size_t)GG * EDIM;
    float* ghid3 = ghid + 2 * (size_t)GG * EDIM;
    float* gf = gfs;           // cols [0,384) of gfs
    float* gs = gfs + EDIM;    // cols [384,768)

    // ---------------- stream s1: structure branch + out4 + out3 ------------
    run_branch(s1, xs, lms2, h2, 3, bs_, ns, gs, false);
    if (fork) cudaEventRecord(g_hx.eGS, s1);

    // out4: P1 (fp16 MODE0), P2 (fp16 MODE1), expmap
    hgemm_kernel<0><<<dim3(gemm_mx, 3), 256, HEAD_SMEM, s1>>>(
        ns, nullptr, EDIM, p1h, EDIM, nullptr, hid2h, EDIM, N, EDIM);
    hgemm_kernel<1><<<dim3(gemm_mx, 3), 256, HEAD_SMEM, s1>>>(
        nullptr, hid2h, EDIM, p2h, EDIM, out + off4, nullptr, EDIM, N, EDIM);
    expmap_proj_kernel<<<ceil_div(nwarp_threads, 256), 256, 0, s1>>>(out + off4, N);

    // out3: mlp(gs, P1, P2)   (gs slice of gfs, lda=768)
    sgemm_kernel<<<dim3(ggrid, 3), 256, 0, s1>>>(gs, GFS_LD, P1, ghid3, EDIM, GG, EDIM, EDIM, 1);
    sgemm_kernel<<<dim3(ggrid, 3), 256, 0, s1>>>(ghid3, EDIM, P2, out + off3, EDIM,
                                                 GG, EDIM, EDIM, 0);
    expmap_proj_kernel<<<ceil_div(gwarp_threads, 256), 256, 0, s1>>>(out + off3, GG);
    if (fork) cudaEventRecord(g_hx.eEnd, s1);

    // ---------------- stream 0: feature branch + out2 + out1 + out0 --------
    run_branch(s0, x, lms, h, 0, bf, nf, gf, /*skipFirstGemm=*/true);

    // out2 head
    hgemm_kernel<0><<<dim3(gemm_mx, 3), 256, HEAD_SMEM, s0>>>(
        nf, nullptr, EDIM, p1h, EDIM, nullptr, hidh, EDIM, N, EDIM);
    hgemm_kernel<1><<<dim3(gemm_mx, 3), 256, HEAD_SMEM, s0>>>(
        nullptr, hidh, EDIM, p2h, EDIM, out + off2, nullptr, EDIM, N, EDIM);
    expmap_proj_kernel<<<ceil_div(nwarp_threads, 256), 256, 0, s0>>>(out + off2, N);

    // out1: mlp(gf, P1, P2)  (gf slice of gfs, lda=768)
    sgemm_kernel<<<dim3(ggrid, 3), 256, 0, s0>>>(gf, GFS_LD, P1, ghid1, EDIM, GG, EDIM, EDIM, 1);
    sgemm_kernel<<<dim3(ggrid, 3), 256, 0, s0>>>(ghid1, EDIM, P2, out + off1, EDIM,
                                                 GG, EDIM, EDIM, 0);
    expmap_proj_kernel<<<ceil_div(gwarp_threads, 256), 256, 0, s0>>>(out + off1, GG);

    // out0: e( relu(gfs @ G1 [K=768]) @ G2 )  -- needs gs pool from s1
    if (fork) cudaStreamWaitEvent(s0, g_hx.eGS, 0);
    sgemm_kernel<<<dim3(ggrid, 3), 256, 0, s0>>>(gfs, GFS_LD, G1, ghid0, EDIM,
                                                 GG, EDIM, 2 * EDIM, 1);
    sgemm_kernel<<<dim3(ggrid, 3), 256, 0, s0>>>(ghid0, EDIM, G2, out + off0, EDIM,
                                                 GG, EDIM, EDIM, 0);
    expmap_proj_kernel<<<ceil_div(gwarp_threads, 256), 256, 0, s0>>>(out + off0, GG);

    if (fork) cudaStreamWaitEvent(s0, g_hx.eEnd, 0);
}